// round 2
// baseline (speedup 1.0000x reference)
#include <cuda_runtime.h>

// Problem constants (fixed by the dataset)
constexpr int Dd      = 64;      // feature dim
constexpr int Hh      = 128;     // hidden dim
constexpr int N_NODES = 50000;
constexpr int N_EDGES = 800000;

constexpr int BM        = 128;   // rows (edges/nodes) per block tile
constexpr int KC        = 32;    // K chunk
constexpr int AS_STRIDE = 36;    // padded smem stride for A chunk (floats)
constexpr int HS        = 132;   // padded smem stride for h (floats)

// Scratch for segment_sum (no cudaMalloc allowed)
__device__ float g_agg[N_NODES * Dd];

__global__ void zero_agg_kernel() {
    int i = blockIdx.x * blockDim.x + threadIdx.x;
    int stride = gridDim.x * blockDim.x;
    for (; i < N_NODES * Dd; i += stride) g_agg[i] = 0.0f;
}

// Fused 2-layer MLP over BM-row tiles.
// EDGE=true : rows are edges, A = [edge_feats | nf[send] | nf[recv]] (K1=192),
//             writes e and atomicAdds into g_agg[receiver].
// EDGE=false: rows are nodes, A = [g_agg[n] | nf[n]] (K1=128), writes n.
template<int K1, bool EDGE>
__global__ __launch_bounds__(256, 2)
void mlp_block_kernel(const float* __restrict__ feats0,
                      const float* __restrict__ node_feats,
                      const float* __restrict__ W1,
                      const float* __restrict__ bias1,
                      const float* __restrict__ W2,
                      const float* __restrict__ bias2,
                      const int*   __restrict__ senders,
                      const int*   __restrict__ receivers,
                      float*       __restrict__ out,
                      int M)
{
    extern __shared__ float smem[];
    // Region layout (floats):
    //   [0, BM*HS)            : phase1 = A chunk [128][36] + W1 chunk [32][128]
    //                           phase2 = h [128][132]   (reused, sync-separated)
    //   [BM*HS, +Hh*Dd)       : W2 [128][64]
    //   then 2*BM ints        : sender / receiver indices
    float* sA  = smem;                         // [BM][AS_STRIDE]
    float* sW1 = smem + BM * AS_STRIDE;        // [KC][Hh]
    float* sH  = smem;                         // [BM][HS]
    float* sW2 = smem + BM * HS;               // [Hh][Dd]
    int*   sSend = (int*)(sW2 + Hh * Dd);
    int*   sRecv = sSend + BM;

    const int tid  = threadIdx.x;
    const int row0 = blockIdx.x * BM;

    const float* f0 = EDGE ? feats0 : (const float*)g_agg;

    // Preload W2 (float4, coalesced)
    {
        const float4* src = (const float4*)W2;
        float4* dst = (float4*)sW2;
        #pragma unroll
        for (int i = tid; i < Hh * Dd / 4; i += 256) dst[i] = src[i];
    }
    if (EDGE) {
        for (int i = tid; i < BM; i += 256) {
            sSend[i] = senders[row0 + i];
            sRecv[i] = receivers[row0 + i];
        }
    }
    __syncthreads();

    // ------------------- Phase 1: h = relu(A @ W1 + b1) -------------------
    const int tx = tid % 16;   // output-col group (8 cols each)
    const int ty = tid / 16;   // output-row group (8 rows each)

    float acc[64];
    #pragma unroll
    for (int i = 0; i < 64; i++) acc[i] = 0.0f;

    for (int kc = 0; kc < K1; kc += KC) {
        // Load A chunk: 128 rows x 32 cols (float4 per thread x4)
        #pragma unroll
        for (int it = 0; it < 4; it++) {
            int idx = it * 256 + tid;
            int r  = idx >> 3;
            int c  = (idx & 7) * 4;   // local col within chunk
            int gc = kc + c;          // global K col (chunk never straddles a 64-col segment)
            float4 v;
            if (EDGE) {
                const float* src;
                if (gc < Dd)          src = f0 + (size_t)(row0 + r) * Dd + gc;
                else if (gc < 2 * Dd) src = node_feats + (size_t)sSend[r] * Dd + (gc - Dd);
                else                  src = node_feats + (size_t)sRecv[r] * Dd + (gc - 2 * Dd);
                v = *(const float4*)src;
            } else {
                int n = row0 + r;
                if (n < M) {
                    const float* src = (gc < Dd) ? f0 + (size_t)n * Dd + gc
                                                 : node_feats + (size_t)n * Dd + (gc - Dd);
                    v = *(const float4*)src;
                } else {
                    v = make_float4(0.f, 0.f, 0.f, 0.f);
                }
            }
            *(float4*)&sA[r * AS_STRIDE + c] = v;
        }
        // Load W1 chunk: 32 rows x 128 cols
        #pragma unroll
        for (int it = 0; it < 4; it++) {
            int idx = it * 256 + tid;
            int kk = idx >> 5;
            int cc = (idx & 31) * 4;
            *(float4*)&sW1[kk * Hh + cc] =
                *(const float4*)&W1[(size_t)(kc + kk) * Hh + cc];
        }
        __syncthreads();

        #pragma unroll 4
        for (int k = 0; k < KC; k++) {
            float b[8], a[8];
            float4 bv0 = *(float4*)&sW1[k * Hh + tx * 8];
            float4 bv1 = *(float4*)&sW1[k * Hh + tx * 8 + 4];
            b[0] = bv0.x; b[1] = bv0.y; b[2] = bv0.z; b[3] = bv0.w;
            b[4] = bv1.x; b[5] = bv1.y; b[6] = bv1.z; b[7] = bv1.w;
            #pragma unroll
            for (int j = 0; j < 8; j++) a[j] = sA[(ty * 8 + j) * AS_STRIDE + k];
            #pragma unroll
            for (int j = 0; j < 8; j++)
                #pragma unroll
                for (int i = 0; i < 8; i++)
                    acc[j * 8 + i] += a[j] * b[i];
        }
        __syncthreads();
    }

    // relu + bias1, store h into smem (overwrites A/W1 region; sync'd above)
    #pragma unroll
    for (int j = 0; j < 8; j++) {
        int row = ty * 8 + j;
        float4 v0, v1;
        v0.x = fmaxf(acc[j * 8 + 0] + bias1[tx * 8 + 0], 0.f);
        v0.y = fmaxf(acc[j * 8 + 1] + bias1[tx * 8 + 1], 0.f);
        v0.z = fmaxf(acc[j * 8 + 2] + bias1[tx * 8 + 2], 0.f);
        v0.w = fmaxf(acc[j * 8 + 3] + bias1[tx * 8 + 3], 0.f);
        v1.x = fmaxf(acc[j * 8 + 4] + bias1[tx * 8 + 4], 0.f);
        v1.y = fmaxf(acc[j * 8 + 5] + bias1[tx * 8 + 5], 0.f);
        v1.z = fmaxf(acc[j * 8 + 6] + bias1[tx * 8 + 6], 0.f);
        v1.w = fmaxf(acc[j * 8 + 7] + bias1[tx * 8 + 7], 0.f);
        *(float4*)&sH[row * HS + tx * 8]     = v0;
        *(float4*)&sH[row * HS + tx * 8 + 4] = v1;
    }
    __syncthreads();

    // ------------------- Phase 2: out = h @ W2 + b2 -------------------
    const int tx2 = tid & 7;    // col group (8 cols)
    const int ty2 = tid >> 3;   // row group (4 rows)

    float acc2[32];
    #pragma unroll
    for (int i = 0; i < 32; i++) acc2[i] = 0.0f;

    #pragma unroll 4
    for (int k = 0; k < Hh; k++) {
        float b[8], a[4];
        float4 bv0 = *(float4*)&sW2[k * Dd + tx2 * 8];
        float4 bv1 = *(float4*)&sW2[k * Dd + tx2 * 8 + 4];
        b[0] = bv0.x; b[1] = bv0.y; b[2] = bv0.z; b[3] = bv0.w;
        b[4] = bv1.x; b[5] = bv1.y; b[6] = bv1.z; b[7] = bv1.w;
        #pragma unroll
        for (int j = 0; j < 4; j++) a[j] = sH[(ty2 * 4 + j) * HS + k];
        #pragma unroll
        for (int j = 0; j < 4; j++)
            #pragma unroll
            for (int i = 0; i < 8; i++)
                acc2[j * 8 + i] += a[j] * b[i];
    }

    // Epilogue: bias2, write out, scatter-add into g_agg (edge pass)
    #pragma unroll
    for (int j = 0; j < 4; j++) {
        int r = ty2 * 4 + j;
        int grow = row0 + r;
        if (!EDGE && grow >= M) continue;
        float v[8];
        #pragma unroll
        for (int i = 0; i < 8; i++) v[i] = acc2[j * 8 + i] + bias2[tx2 * 8 + i];
        float4* dst = (float4*)&out[(size_t)grow * Dd + tx2 * 8];
        dst[0] = make_float4(v[0], v[1], v[2], v[3]);
        dst[1] = make_float4(v[4], v[5], v[6], v[7]);
        if (EDGE) {
            int rv = sRecv[r];
            float* aggp = &g_agg[(size_t)rv * Dd + tx2 * 8];
            #pragma unroll
            for (int i = 0; i < 8; i++) atomicAdd(&aggp[i], v[i]);
        }
    }
}

constexpr int SMEM_BYTES = (BM * HS + Hh * Dd) * 4 + 2 * BM * 4;

extern "C" void kernel_launch(void* const* d_in, const int* in_sizes, int n_in,
                              void* d_out, int out_size)
{
    const float* node_feats = (const float*)d_in[0];
    const float* edge_feats = (const float*)d_in[1];
    const float* We1 = (const float*)d_in[2];
    const float* be1 = (const float*)d_in[3];
    const float* We2 = (const float*)d_in[4];
    const float* be2 = (const float*)d_in[5];
    const float* Wn1 = (const float*)d_in[6];
    const float* bn1 = (const float*)d_in[7];
    const float* Wn2 = (const float*)d_in[8];
    const float* bn2 = (const float*)d_in[9];
    const int* senders   = (const int*)d_in[10];
    const int* receivers = (const int*)d_in[11];

    float* e_out = (float*)d_out;                       // [E, 64]
    float* n_out = e_out + (size_t)N_EDGES * Dd;        // [N, 64]

    cudaFuncSetAttribute(mlp_block_kernel<3 * Dd, true>,
                         cudaFuncAttributeMaxDynamicSharedMemorySize, SMEM_BYTES);
    cudaFuncSetAttribute(mlp_block_kernel<2 * Dd, false>,
                         cudaFuncAttributeMaxDynamicSharedMemorySize, SMEM_BYTES);

    // 1) zero aggregation scratch
    zero_agg_kernel<<<256, 256>>>();

    // 2) edge MLP: writes e, scatter-adds into g_agg
    mlp_block_kernel<3 * Dd, true><<<N_EDGES / BM, 256, SMEM_BYTES>>>(
        edge_feats, node_feats, We1, be1, We2, be2,
        senders, receivers, e_out, N_EDGES);

    // 3) node MLP: reads g_agg + node_feats, writes n
    mlp_block_kernel<2 * Dd, false><<<(N_NODES + BM - 1) / BM, 256, SMEM_BYTES>>>(
        nullptr, node_feats, Wn1, bn1, Wn2, bn2,
        nullptr, nullptr, n_out, N_NODES);
}

// round 4
// speedup vs baseline: 1.5927x; 1.5927x over previous
#include <cuda_runtime.h>
#include <cuda_fp16.h>
#include <cstdint>

// ---------------- problem constants ----------------
constexpr int Dd = 64, Hh = 128, N_NODES = 50000, N_EDGES = 800000, BM = 128;

// ---------------- device scratch (no cudaMalloc allowed) ----------------
__device__ float g_agg[(size_t)N_NODES * Dd];

// ---------------- helpers ----------------
__device__ __forceinline__ uint32_t smem_u32(const void* p) {
    uint32_t a;
    asm("{ .reg .u64 t; cvta.to.shared.u64 t, %1; cvt.u32.u64 %0, t; }" : "=r"(a) : "l"(p));
    return a;
}
__device__ __forceinline__ void ldsm4(uint32_t* r, uint32_t addr) {
    asm volatile("ldmatrix.sync.aligned.m8n8.x4.shared.b16 {%0,%1,%2,%3}, [%4];"
                 : "=r"(r[0]), "=r"(r[1]), "=r"(r[2]), "=r"(r[3]) : "r"(addr));
}
__device__ __forceinline__ void mma16816(float* c, const uint32_t* a, const uint32_t* b) {
    asm volatile("mma.sync.aligned.m16n8k16.row.col.f32.f16.f16.f32 "
                 "{%0,%1,%2,%3}, {%4,%5,%6,%7}, {%8,%9}, {%0,%1,%2,%3};"
                 : "+f"(c[0]), "+f"(c[1]), "+f"(c[2]), "+f"(c[3])
                 : "r"(a[0]), "r"(a[1]), "r"(a[2]), "r"(a[3]), "r"(b[0]), "r"(b[1]));
}
__device__ __forceinline__ void split2(float x, float y, uint32_t& hi, uint32_t& lo) {
    __half h0 = __float2half_rn(x), h1 = __float2half_rn(y);
    __half l0 = __float2half_rn(x - __half2float(h0));
    __half l1 = __float2half_rn(y - __half2float(h1));
    __half2 hp = __halves2half2(h0, h1), lp = __halves2half2(l0, l1);
    hi = *(uint32_t*)&hp; lo = *(uint32_t*)&lp;
}

__global__ void zero_agg_kernel() {
    int i = blockIdx.x * blockDim.x + threadIdx.x;
    int stride = gridDim.x * blockDim.x;
    float4* p = (float4*)g_agg;
    for (; i < N_NODES * Dd / 4; i += stride) p[i] = make_float4(0.f, 0.f, 0.f, 0.f);
}

// ---------------- fused 2-layer MLP, HMMA (mma.sync) path ----------------
// Persistent: 148 CTAs x 256 threads (8 warps, 2(m) x 4(n) warp grid), BM=128 rows/tile.
// 3-term fp16 hi/lo split for fp32-grade accuracy: AhBh + AlBh + AhBl.
template<int K1, bool EDGE>
__global__ void __launch_bounds__(256, 1)
gnn_mlp(const float* __restrict__ f0, const float* __restrict__ node_feats,
        const float* __restrict__ W1g, const float* __restrict__ b1g,
        const float* __restrict__ W2g, const float* __restrict__ b2g,
        const int* __restrict__ senders, const int* __restrict__ receivers,
        float* __restrict__ out, int M, int num_tiles)
{
    constexpr int S1 = K1 + 8;    // W1 image stride (halves), conflict-free for ldmatrix
    constexpr int S2 = Hh + 8;    // W2 image stride
    constexpr int SA = 40;        // A / h chunk stride
    // byte offsets in dynamic smem
    constexpr uint32_t O_SEND = 0, O_RECV = 512, O_B1V = 1024, O_B2V = 1536;
    constexpr uint32_t B1H = 2048;
    constexpr uint32_t B1L = B1H + (uint32_t)Hh * S1 * 2;
    constexpr uint32_t B2H = B1L + (uint32_t)Hh * S1 * 2;
    constexpr uint32_t B2L = B2H + (uint32_t)Dd * S2 * 2;
    constexpr uint32_t AH  = B2L + (uint32_t)Dd * S2 * 2;
    constexpr uint32_t AL  = AH + (uint32_t)BM * SA * 2;
    constexpr uint32_t HHo = AL + (uint32_t)BM * SA * 2;
    constexpr uint32_t HLo = HHo + (uint32_t)BM * SA * 2;

    extern __shared__ unsigned char smem[];
    const uint32_t sb = smem_u32(smem);
    const int tid = threadIdx.x, lane = tid & 31, wid = tid >> 5;
    const int mw = wid >> 2;          // m warp group: 0/1 (64 rows each)
    const int nw = wid & 3;           // n warp group: 0..3
    const int lr = lane >> 2;         // frag row within 8
    const int lc = (lane & 3) * 2;    // frag col pair base

    int*   sSend = (int*)(smem + O_SEND);
    int*   sRecv = (int*)(smem + O_RECV);
    float* sB1v  = (float*)(smem + O_B1V);
    float* sB2v  = (float*)(smem + O_B2V);
    __half* b1h = (__half*)(smem + B1H); __half* b1l = (__half*)(smem + B1L);
    __half* b2h = (__half*)(smem + B2H); __half* b2l = (__half*)(smem + B2L);

    // ---- one-time: convert weights to fp16 hi/lo images in smem ----
    for (int i = tid; i < Hh * K1; i += 256) {
        int n = i / K1, k = i - n * K1;
        float v = W1g[(size_t)k * Hh + n];
        __half h = __float2half_rn(v);
        b1h[n * S1 + k] = h;
        b1l[n * S1 + k] = __float2half_rn(v - __half2float(h));
    }
    for (int i = tid; i < Dd * Hh; i += 256) {
        int n = i / Hh, k = i - n * Hh;
        float v = W2g[(size_t)k * Dd + n];
        __half h = __float2half_rn(v);
        b2h[n * S2 + k] = h;
        b2l[n * S2 + k] = __float2half_rn(v - __half2float(h));
    }
    if (tid < Hh) sB1v[tid] = b1g[tid];
    if (tid < Dd) sB2v[tid] = b2g[tid];
    __syncthreads();

    for (int tile = blockIdx.x; tile < num_tiles; tile += gridDim.x) {
        const int row0 = tile * BM;
        __syncthreads();  // protect sSend/sRecv (read by prev epilogue)
        if (EDGE && tid < BM) {
            sSend[tid] = senders[row0 + tid];
            sRecv[tid] = receivers[row0 + tid];
        }
        __syncthreads();

        // ================= layer 1: C1[128x128] = A[128xK1] @ W1 =================
        float acc1[4][16];
        #pragma unroll
        for (int a = 0; a < 4; a++)
            #pragma unroll
            for (int b = 0; b < 16; b++) acc1[a][b] = 0.f;

        for (int kc = 0; kc < K1; kc += 32) {
            __syncthreads();  // prev chunk's frag reads done
            // gather 128x32 f32, split, store to sA hi/lo
            const int seg = kc >> 6, so = kc & 63;
            #pragma unroll
            for (int it = 0; it < 4; it++) {
                int idx = it * 256 + tid;
                int r = idx >> 3, c4 = idx & 7;
                float4 v;
                if (EDGE) {
                    const float* src = (seg == 0) ? f0 + (size_t)(row0 + r) * Dd + so + c4 * 4
                                     : (seg == 1) ? node_feats + (size_t)sSend[r] * Dd + so + c4 * 4
                                                  : node_feats + (size_t)sRecv[r] * Dd + so + c4 * 4;
                    v = *(const float4*)src;
                } else {
                    if (row0 + r < M) {
                        const float* src = (seg == 0) ? g_agg + (size_t)(row0 + r) * Dd + so + c4 * 4
                                                      : node_feats + (size_t)(row0 + r) * Dd + so + c4 * 4;
                        v = *(const float4*)src;
                    } else v = make_float4(0.f, 0.f, 0.f, 0.f);
                }
                uint2 hv, lv;
                split2(v.x, v.y, hv.x, lv.x);
                split2(v.z, v.w, hv.y, lv.y);
                uint32_t off = 2u * (r * SA + c4 * 4);
                *(uint2*)(smem + AH + off) = hv;
                *(uint2*)(smem + AL + off) = lv;
            }
            __syncthreads();

            #pragma unroll
            for (int ks = 0; ks < 32; ks += 16) {
                uint32_t ah[4][4], al[4][4], bh[4][2], bl[4][2];
                #pragma unroll
                for (int mi = 0; mi < 4; mi++) {
                    uint32_t ao = 2u * ((mw * 64 + mi * 16 + (lane & 15)) * SA + ks + (lane >> 4) * 8);
                    ldsm4(ah[mi], sb + AH + ao);
                    ldsm4(al[mi], sb + AL + ao);
                }
                #pragma unroll
                for (int p = 0; p < 2; p++) {
                    uint32_t t[4], u[4];
                    uint32_t bo = 2u * ((nw * 32 + p * 16 + (lane & 15)) * S1 + kc + ks + (lane >> 4) * 8);
                    ldsm4(t, sb + B1H + bo);
                    ldsm4(u, sb + B1L + bo);
                    bh[2*p][0] = t[0]; bh[2*p+1][0] = t[1]; bh[2*p][1] = t[2]; bh[2*p+1][1] = t[3];
                    bl[2*p][0] = u[0]; bl[2*p+1][0] = u[1]; bl[2*p][1] = u[2]; bl[2*p+1][1] = u[3];
                }
                #pragma unroll
                for (int mi = 0; mi < 4; mi++)
                    #pragma unroll
                    for (int ni = 0; ni < 4; ni++) {
                        mma16816(&acc1[mi][ni*4], ah[mi], bh[ni]);
                        mma16816(&acc1[mi][ni*4], al[mi], bh[ni]);
                        mma16816(&acc1[mi][ni*4], ah[mi], bl[ni]);
                    }
            }
        }

        // ================= layer 2: C2[128x64] = relu(C1+b1) @ W2 =================
        float acc2[4][8];
        #pragma unroll
        for (int a = 0; a < 4; a++)
            #pragma unroll
            for (int b = 0; b < 8; b++) acc2[a][b] = 0.f;

        for (int c = 0; c < 4; c++) {            // h column chunks of 32
            __syncthreads();                     // prev chunk reads done
            if (nw == c) {                       // owners write this chunk (bias+relu+split)
                #pragma unroll
                for (int mi = 0; mi < 4; mi++) {
                    int rbase = mw * 64 + mi * 16 + lr;
                    #pragma unroll
                    for (int ni = 0; ni < 4; ni++) {
                        int cl = ni * 8 + lc;
                        float bb0 = sB1v[c * 32 + cl], bb1 = sB1v[c * 32 + cl + 1];
                        float v0 = fmaxf(acc1[mi][ni*4+0] + bb0, 0.f);
                        float v1 = fmaxf(acc1[mi][ni*4+1] + bb1, 0.f);
                        float v2 = fmaxf(acc1[mi][ni*4+2] + bb0, 0.f);
                        float v3 = fmaxf(acc1[mi][ni*4+3] + bb1, 0.f);
                        uint32_t h01, l01, h23, l23;
                        split2(v0, v1, h01, l01);
                        split2(v2, v3, h23, l23);
                        uint32_t o0 = 2u * (rbase * SA + cl);
                        uint32_t o1 = 2u * ((rbase + 8) * SA + cl);
                        *(uint32_t*)(smem + HHo + o0) = h01;
                        *(uint32_t*)(smem + HLo + o0) = l01;
                        *(uint32_t*)(smem + HHo + o1) = h23;
                        *(uint32_t*)(smem + HLo + o1) = l23;
                    }
                }
            }
            __syncthreads();

            #pragma unroll
            for (int ks = 0; ks < 32; ks += 16) {
                uint32_t ah[4][4], al[4][4], bh[2][2], bl[2][2];
                #pragma unroll
                for (int mi = 0; mi < 4; mi++) {
                    uint32_t ao = 2u * ((mw * 64 + mi * 16 + (lane & 15)) * SA + ks + (lane >> 4) * 8);
                    ldsm4(ah[mi], sb + HHo + ao);
                    ldsm4(al[mi], sb + HLo + ao);
                }
                {
                    uint32_t t[4], u[4];
                    uint32_t bo = 2u * ((nw * 16 + (lane & 15)) * S2 + c * 32 + ks + (lane >> 4) * 8);
                    ldsm4(t, sb + B2H + bo);
                    ldsm4(u, sb + B2L + bo);
                    bh[0][0] = t[0]; bh[1][0] = t[1]; bh[0][1] = t[2]; bh[1][1] = t[3];
                    bl[0][0] = u[0]; bl[1][0] = u[1]; bl[0][1] = u[2]; bl[1][1] = u[3];
                }
                #pragma unroll
                for (int mi = 0; mi < 4; mi++)
                    #pragma unroll
                    for (int ni = 0; ni < 2; ni++) {
                        mma16816(&acc2[mi][ni*4], ah[mi], bh[ni]);
                        mma16816(&acc2[mi][ni*4], al[mi], bh[ni]);
                        mma16816(&acc2[mi][ni*4], ah[mi], bl[ni]);
                    }
            }
        }

        // ================= epilogue: bias2, store out, scatter-add =================
        #pragma unroll
        for (int mi = 0; mi < 4; mi++) {
            int r0 = mw * 64 + mi * 16 + lr;
            #pragma unroll
            for (int ni = 0; ni < 2; ni++) {
                int c0 = nw * 16 + ni * 8 + lc;
                float bb0 = sB2v[c0], bb1 = sB2v[c0 + 1];
                float v0 = acc2[mi][ni*4+0] + bb0, v1 = acc2[mi][ni*4+1] + bb1;
                float v2 = acc2[mi][ni*4+2] + bb0, v3 = acc2[mi][ni*4+3] + bb1;
                if (EDGE || row0 + r0 < M)
                    *(float2*)(out + (size_t)(row0 + r0) * Dd + c0) = make_float2(v0, v1);
                if (EDGE || row0 + r0 + 8 < M)
                    *(float2*)(out + (size_t)(row0 + r0 + 8) * Dd + c0) = make_float2(v2, v3);
                if (EDGE) {
                    float* a0 = g_agg + (size_t)sRecv[r0] * Dd + c0;
                    float* a1 = g_agg + (size_t)sRecv[r0 + 8] * Dd + c0;
                    atomicAdd(a0, v0); atomicAdd(a0 + 1, v1);
                    atomicAdd(a1, v2); atomicAdd(a1 + 1, v3);
                }
            }
        }
    }
}

// ---------------- launch ----------------
template<int K1> constexpr int smem_bytes() {
    return 2048 + Hh * (K1 + 8) * 2 * 2 + Dd * (Hh + 8) * 2 * 2 + 4 * BM * 40 * 2;
}
constexpr int SMEM_EDGE = smem_bytes<3 * Dd>();  // 180224
constexpr int SMEM_NODE = smem_bytes<2 * Dd>();  // 147456

extern "C" void kernel_launch(void* const* d_in, const int* in_sizes, int n_in,
                              void* d_out, int out_size)
{
    const float* node_feats = (const float*)d_in[0];
    const float* edge_feats = (const float*)d_in[1];
    const float* We1 = (const float*)d_in[2];
    const float* be1 = (const float*)d_in[3];
    const float* We2 = (const float*)d_in[4];
    const float* be2 = (const float*)d_in[5];
    const float* Wn1 = (const float*)d_in[6];
    const float* bn1 = (const float*)d_in[7];
    const float* Wn2 = (const float*)d_in[8];
    const float* bn2 = (const float*)d_in[9];
    const int* senders   = (const int*)d_in[10];
    const int* receivers = (const int*)d_in[11];

    float* e_out = (float*)d_out;
    float* n_out = e_out + (size_t)N_EDGES * Dd;

    cudaFuncSetAttribute(gnn_mlp<3 * Dd, true>,
                         cudaFuncAttributeMaxDynamicSharedMemorySize, SMEM_EDGE);
    cudaFuncSetAttribute(gnn_mlp<2 * Dd, false>,
                         cudaFuncAttributeMaxDynamicSharedMemorySize, SMEM_NODE);

    zero_agg_kernel<<<256, 256>>>();

    gnn_mlp<3 * Dd, true><<<148, 256, SMEM_EDGE>>>(
        edge_feats, node_feats, We1, be1, We2, be2,
        senders, receivers, e_out, N_EDGES, N_EDGES / BM);

    gnn_mlp<2 * Dd, false><<<148, 256, SMEM_NODE>>>(
        nullptr, node_feats, Wn1, bn1, Wn2, bn2,
        nullptr, nullptr, n_out, N_NODES, (N_NODES + BM - 1) / BM);
}

// round 5
// speedup vs baseline: 2.5304x; 1.5887x over previous
#include <cuda_runtime.h>
#include <cuda_fp16.h>
#include <cstdint>

// ---------------- problem constants ----------------
constexpr int Dd = 64, Hh = 128, N_NODES = 50000, N_EDGES = 800000, BM = 128;

// ---------------- device scratch (no cudaMalloc allowed) ----------------
__device__ float g_agg[(size_t)N_NODES * Dd];
__device__ float g_P[(size_t)N_NODES * 256];   // [n, 0:128)=nf@W1b (sender), [128:256)=nf@W1c (receiver)

// ---------------- helpers ----------------
__device__ __forceinline__ uint32_t smem_u32(const void* p) {
    uint32_t a;
    asm("{ .reg .u64 t; cvta.to.shared.u64 t, %1; cvt.u32.u64 %0, t; }" : "=r"(a) : "l"(p));
    return a;
}
__device__ __forceinline__ void ldsm4(uint32_t* r, uint32_t addr) {
    asm volatile("ldmatrix.sync.aligned.m8n8.x4.shared.b16 {%0,%1,%2,%3}, [%4];"
                 : "=r"(r[0]), "=r"(r[1]), "=r"(r[2]), "=r"(r[3]) : "r"(addr));
}
__device__ __forceinline__ void mma16816(float* c, const uint32_t* a, const uint32_t* b) {
    asm volatile("mma.sync.aligned.m16n8k16.row.col.f32.f16.f16.f32 "
                 "{%0,%1,%2,%3}, {%4,%5,%6,%7}, {%8,%9}, {%0,%1,%2,%3};"
                 : "+f"(c[0]), "+f"(c[1]), "+f"(c[2]), "+f"(c[3])
                 : "r"(a[0]), "r"(a[1]), "r"(a[2]), "r"(a[3]), "r"(b[0]), "r"(b[1]));
}
__device__ __forceinline__ void split2(float x, float y, uint32_t& hi, uint32_t& lo) {
    __half h0 = __float2half_rn(x), h1 = __float2half_rn(y);
    __half l0 = __float2half_rn(x - __half2float(h0));
    __half l1 = __float2half_rn(y - __half2float(h1));
    __half2 hp = __halves2half2(h0, h1), lp = __halves2half2(l0, l1);
    hi = *(uint32_t*)&hp; lo = *(uint32_t*)&lp;
}
// XOR-swizzled byte offset inside an image whose rows are RB bytes (RB multiple of 128)
template<int RB>
__device__ __forceinline__ uint32_t ioff(int r, int cb) {
    return (uint32_t)(r * RB + ((((cb >> 4) ^ (r & 7)) << 4) | (cb & 15)));
}

// ---------------- precompute kernel: P = nf @ [W1b|W1c], plus zero g_agg ----------------
__global__ void __launch_bounds__(256, 1)
pre_kernel(const float* __restrict__ nf, const float* __restrict__ We1)
{
    constexpr uint32_t BH = 0, BL = 32768, AH = 65536, AL = 81920; // total 98304
    extern __shared__ unsigned char smem[];
    const uint32_t sb = smem_u32(smem);
    const int tid = threadIdx.x, lane = tid & 31, wid = tid >> 5;
    const int mw = wid >> 2, nw = wid & 3;
    const int lr = lane >> 2, lc = (lane & 3) * 2;

    // zero g_agg (before edge kernel's atomics; cross-launch ordering guarantees visibility)
    {
        float4* p = (float4*)g_agg;
        for (int i = blockIdx.x * 256 + tid; i < N_NODES * Dd / 4; i += gridDim.x * 256)
            p[i] = make_float4(0.f, 0.f, 0.f, 0.f);
    }

    // B image: 256 n-rows x 64 k (hi/lo), n<128 -> We1[64+k][n], else We1[128+k][n-128]
    for (int i = tid; i < 256 * 64; i += 256) {
        int n = i >> 6, k = i & 63;
        int srow = (n < 128) ? (64 + k) : (128 + k);
        float v = We1[(size_t)srow * Hh + (n & 127)];
        __half h = __float2half_rn(v);
        uint32_t o = ioff<128>(n, k * 2);
        *(__half*)(smem + BH + o) = h;
        *(__half*)(smem + BL + o) = __float2half_rn(v - __half2float(h));
    }

    // A image: 128 node rows x 64 k
    const int row0 = blockIdx.x * BM;
    #pragma unroll
    for (int it = 0; it < 8; it++) {
        int idx = it * 256 + tid, r = idx >> 4, c4 = idx & 15;
        int grow = row0 + r;
        float4 v = (grow < N_NODES) ? *(const float4*)(nf + (size_t)grow * Dd + c4 * 4)
                                    : make_float4(0.f, 0.f, 0.f, 0.f);
        uint2 hv, lv;
        split2(v.x, v.y, hv.x, lv.x);
        split2(v.z, v.w, hv.y, lv.y);
        uint32_t o = ioff<128>(r, c4 * 8);
        *(uint2*)(smem + AH + o) = hv;
        *(uint2*)(smem + AL + o) = lv;
    }
    __syncthreads();

    float acc[4][32];
    #pragma unroll
    for (int a = 0; a < 4; a++)
        #pragma unroll
        for (int b = 0; b < 32; b++) acc[a][b] = 0.f;

    #pragma unroll
    for (int ks = 0; ks < 64; ks += 16) {
        uint32_t ah[4][4], al[4][4], bh[8][2], bl[8][2];
        #pragma unroll
        for (int mi = 0; mi < 4; mi++) {
            uint32_t ao = ioff<128>(mw * 64 + mi * 16 + (lane & 15), ks * 2 + (lane >> 4) * 16);
            ldsm4(ah[mi], sb + AH + ao);
            ldsm4(al[mi], sb + AL + ao);
        }
        #pragma unroll
        for (int p = 0; p < 4; p++) {
            uint32_t t[4], u[4];
            uint32_t bo = ioff<128>(nw * 64 + p * 16 + (lane & 15), ks * 2 + (lane >> 4) * 16);
            ldsm4(t, sb + BH + bo);
            ldsm4(u, sb + BL + bo);
            bh[2*p][0] = t[0]; bh[2*p+1][0] = t[1]; bh[2*p][1] = t[2]; bh[2*p+1][1] = t[3];
            bl[2*p][0] = u[0]; bl[2*p+1][0] = u[1]; bl[2*p][1] = u[2]; bl[2*p+1][1] = u[3];
        }
        #pragma unroll
        for (int mi = 0; mi < 4; mi++)
            #pragma unroll
            for (int ni = 0; ni < 8; ni++) {
                mma16816(&acc[mi][ni*4], ah[mi], bh[ni]);
                mma16816(&acc[mi][ni*4], al[mi], bh[ni]);
                mma16816(&acc[mi][ni*4], ah[mi], bl[ni]);
            }
    }

    #pragma unroll
    for (int mi = 0; mi < 4; mi++) {
        int r0 = row0 + mw * 64 + mi * 16 + lr;
        #pragma unroll
        for (int ni = 0; ni < 8; ni++) {
            int c = nw * 64 + ni * 8 + lc;
            if (r0 < N_NODES)
                *(float2*)(g_P + (size_t)r0 * 256 + c) = make_float2(acc[mi][ni*4+0], acc[mi][ni*4+1]);
            if (r0 + 8 < N_NODES)
                *(float2*)(g_P + (size_t)(r0 + 8) * 256 + c) = make_float2(acc[mi][ni*4+2], acc[mi][ni*4+3]);
        }
    }
}

// ---------------- fused 2-layer MLP (persistent, HMMA, full-h) ----------------
// EDGE: A = edge_feats (K=64); layer1 result += P_s + P_r gathered from g_P. atomics into g_agg.
// NODE: A = [g_agg | nf] (K=128).
template<bool EDGE>
__global__ void __launch_bounds__(256, 1)
gnn_mlp(const float* __restrict__ f0, const float* __restrict__ node_feats,
        const float* __restrict__ W1g, const float* __restrict__ b1g,
        const float* __restrict__ W2g, const float* __restrict__ b2g,
        const int* __restrict__ senders, const int* __restrict__ receivers,
        float* __restrict__ out, int M, int num_tiles)
{
    constexpr int AK  = EDGE ? 64 : 128;    // layer-1 K
    constexpr int ARB = AK * 2;             // A / B1 image row bytes
    constexpr uint32_t B1H = 1024;
    constexpr uint32_t B1SZ = 128u * ARB;
    constexpr uint32_t B1L = B1H + B1SZ;
    constexpr uint32_t B2H = B1L + B1SZ;
    constexpr uint32_t B2L = B2H + 16384;
    constexpr uint32_t AH  = B2L + 16384;
    constexpr uint32_t AL  = AH + B1SZ;
    constexpr uint32_t HHo = AL + B1SZ;
    constexpr uint32_t HLo = HHo + 32768;

    extern __shared__ unsigned char smem[];
    const uint32_t sb = smem_u32(smem);
    const int tid = threadIdx.x, lane = tid & 31, wid = tid >> 5;
    const int mw = wid >> 2, nw = wid & 3;
    const int lr = lane >> 2, lc = (lane & 3) * 2;
    int* sSend = (int*)(smem + 0);
    int* sRecv = (int*)(smem + 512);

    // one-time weight images (hi/lo, [n][k], swizzled)
    for (int i = tid; i < 128 * AK; i += 256) {
        int n = i / AK, k = i - n * AK;
        float v = W1g[(size_t)k * Hh + n];
        __half h = __float2half_rn(v);
        uint32_t o = ioff<ARB>(n, k * 2);
        *(__half*)(smem + B1H + o) = h;
        *(__half*)(smem + B1L + o) = __float2half_rn(v - __half2float(h));
    }
    for (int i = tid; i < 64 * 128; i += 256) {
        int n = i >> 7, k = i & 127;
        float v = W2g[(size_t)k * Dd + n];
        __half h = __float2half_rn(v);
        uint32_t o = ioff<256>(n, k * 2);
        *(__half*)(smem + B2H + o) = h;
        *(__half*)(smem + B2L + o) = __float2half_rn(v - __half2float(h));
    }
    __syncthreads();

    for (int tile = blockIdx.x; tile < num_tiles; tile += gridDim.x) {
        const int row0 = tile * BM;
        __syncthreads();   // protect staging + images vs previous tile's readers
        if (EDGE && tid < BM) {
            sSend[tid] = senders[row0 + tid];
            sRecv[tid] = receivers[row0 + tid];
        }
        // ---- build A image ----
        if (EDGE) {
            #pragma unroll
            for (int it = 0; it < 8; it++) {
                int idx = it * 256 + tid, r = idx >> 4, c4 = idx & 15;
                float4 v = *(const float4*)(f0 + (size_t)(row0 + r) * Dd + c4 * 4);
                uint2 hv, lv;
                split2(v.x, v.y, hv.x, lv.x);
                split2(v.z, v.w, hv.y, lv.y);
                uint32_t o = ioff<ARB>(r, c4 * 8);
                *(uint2*)(smem + AH + o) = hv;
                *(uint2*)(smem + AL + o) = lv;
            }
        } else {
            #pragma unroll
            for (int it = 0; it < 16; it++) {
                int idx = it * 256 + tid, r = idx >> 5, c8 = idx & 31;
                int col = c8 * 4, grow = row0 + r;
                float4 v = make_float4(0.f, 0.f, 0.f, 0.f);
                if (grow < M)
                    v = (col < Dd) ? *(const float4*)(g_agg + (size_t)grow * Dd + col)
                                   : *(const float4*)(node_feats + (size_t)grow * Dd + col - Dd);
                uint2 hv, lv;
                split2(v.x, v.y, hv.x, lv.x);
                split2(v.z, v.w, hv.y, lv.y);
                uint32_t o = ioff<ARB>(r, c8 * 8);
                *(uint2*)(smem + AH + o) = hv;
                *(uint2*)(smem + AL + o) = lv;
            }
        }
        __syncthreads();

        // ---- layer 1: C1[128x128] = A @ W1part ----
        float acc1[4][16];
        #pragma unroll
        for (int a = 0; a < 4; a++)
            #pragma unroll
            for (int b = 0; b < 16; b++) acc1[a][b] = 0.f;

        #pragma unroll
        for (int ks = 0; ks < AK; ks += 16) {
            uint32_t ah[4][4], al[4][4], bh[4][2], bl[4][2];
            #pragma unroll
            for (int mi = 0; mi < 4; mi++) {
                uint32_t ao = ioff<ARB>(mw * 64 + mi * 16 + (lane & 15), ks * 2 + (lane >> 4) * 16);
                ldsm4(ah[mi], sb + AH + ao);
                ldsm4(al[mi], sb + AL + ao);
            }
            #pragma unroll
            for (int p = 0; p < 2; p++) {
                uint32_t t[4], u[4];
                uint32_t bo = ioff<ARB>(nw * 32 + p * 16 + (lane & 15), ks * 2 + (lane >> 4) * 16);
                ldsm4(t, sb + B1H + bo);
                ldsm4(u, sb + B1L + bo);
                bh[2*p][0] = t[0]; bh[2*p+1][0] = t[1]; bh[2*p][1] = t[2]; bh[2*p+1][1] = t[3];
                bl[2*p][0] = u[0]; bl[2*p+1][0] = u[1]; bl[2*p][1] = u[2]; bl[2*p+1][1] = u[3];
            }
            #pragma unroll
            for (int mi = 0; mi < 4; mi++)
                #pragma unroll
                for (int ni = 0; ni < 4; ni++) {
                    mma16816(&acc1[mi][ni*4], ah[mi], bh[ni]);
                    mma16816(&acc1[mi][ni*4], al[mi], bh[ni]);
                    mma16816(&acc1[mi][ni*4], ah[mi], bl[ni]);
                }
        }

        // ---- epilogue 1: (+P_s+P_r) + bias1, relu, split, write full h ----
        #pragma unroll
        for (int mi = 0; mi < 4; mi++) {
            int r0 = mw * 64 + mi * 16 + lr;
            int s0 = 0, s1 = 0, rv0 = 0, rv1 = 0;
            if (EDGE) { s0 = sSend[r0]; rv0 = sRecv[r0]; s1 = sSend[r0 + 8]; rv1 = sRecv[r0 + 8]; }
            #pragma unroll
            for (int ni = 0; ni < 4; ni++) {
                int c0 = nw * 32 + ni * 8 + lc;
                float bb0 = __ldg(b1g + c0), bb1 = __ldg(b1g + c0 + 1);
                float v0 = acc1[mi][ni*4+0] + bb0, v1 = acc1[mi][ni*4+1] + bb1;
                float v2 = acc1[mi][ni*4+2] + bb0, v3 = acc1[mi][ni*4+3] + bb1;
                if (EDGE) {
                    float2 ps = *(const float2*)(g_P + (size_t)s0 * 256 + c0);
                    float2 pr = *(const float2*)(g_P + (size_t)rv0 * 256 + 128 + c0);
                    v0 += ps.x + pr.x; v1 += ps.y + pr.y;
                    float2 qs = *(const float2*)(g_P + (size_t)s1 * 256 + c0);
                    float2 qr = *(const float2*)(g_P + (size_t)rv1 * 256 + 128 + c0);
                    v2 += qs.x + qr.x; v3 += qs.y + qr.y;
                }
                v0 = fmaxf(v0, 0.f); v1 = fmaxf(v1, 0.f);
                v2 = fmaxf(v2, 0.f); v3 = fmaxf(v3, 0.f);
                uint32_t h01, l01, h23, l23;
                split2(v0, v1, h01, l01);
                split2(v2, v3, h23, l23);
                uint32_t o0 = ioff<256>(r0, c0 * 2), o1 = ioff<256>(r0 + 8, c0 * 2);
                *(uint32_t*)(smem + HHo + o0) = h01;
                *(uint32_t*)(smem + HLo + o0) = l01;
                *(uint32_t*)(smem + HHo + o1) = h23;
                *(uint32_t*)(smem + HLo + o1) = l23;
            }
        }
        __syncthreads();

        // ---- layer 2: C2[128x64] = h @ W2 ----
        float acc2[4][8];
        #pragma unroll
        for (int a = 0; a < 4; a++)
            #pragma unroll
            for (int b = 0; b < 8; b++) acc2[a][b] = 0.f;

        #pragma unroll
        for (int ks = 0; ks < 128; ks += 16) {
            uint32_t ah[4][4], al[4][4], bh[2][2], bl[2][2];
            #pragma unroll
            for (int mi = 0; mi < 4; mi++) {
                uint32_t ao = ioff<256>(mw * 64 + mi * 16 + (lane & 15), ks * 2 + (lane >> 4) * 16);
                ldsm4(ah[mi], sb + HHo + ao);
                ldsm4(al[mi], sb + HLo + ao);
            }
            {
                uint32_t t[4], u[4];
                uint32_t bo = ioff<256>(nw * 16 + (lane & 15), ks * 2 + (lane >> 4) * 16);
                ldsm4(t, sb + B2H + bo);
                ldsm4(u, sb + B2L + bo);
                bh[0][0] = t[0]; bh[1][0] = t[1]; bh[0][1] = t[2]; bh[1][1] = t[3];
                bl[0][0] = u[0]; bl[1][0] = u[1]; bl[0][1] = u[2]; bl[1][1] = u[3];
            }
            #pragma unroll
            for (int mi = 0; mi < 4; mi++)
                #pragma unroll
                for (int ni = 0; ni < 2; ni++) {
                    mma16816(&acc2[mi][ni*4], ah[mi], bh[ni]);
                    mma16816(&acc2[mi][ni*4], al[mi], bh[ni]);
                    mma16816(&acc2[mi][ni*4], ah[mi], bl[ni]);
                }
        }

        // ---- epilogue 2: bias2, store out, scatter-add ----
        #pragma unroll
        for (int mi = 0; mi < 4; mi++) {
            int r0 = mw * 64 + mi * 16 + lr;
            int rv0 = 0, rv1 = 0;
            if (EDGE) { rv0 = sRecv[r0]; rv1 = sRecv[r0 + 8]; }
            #pragma unroll
            for (int ni = 0; ni < 2; ni++) {
                int c = nw * 16 + ni * 8 + lc;
                float bb0 = __ldg(b2g + c), bb1 = __ldg(b2g + c + 1);
                float v0 = acc2[mi][ni*4+0] + bb0, v1 = acc2[mi][ni*4+1] + bb1;
                float v2 = acc2[mi][ni*4+2] + bb0, v3 = acc2[mi][ni*4+3] + bb1;
                if (EDGE || row0 + r0 < M)
                    *(float2*)(out + (size_t)(row0 + r0) * Dd + c) = make_float2(v0, v1);
                if (EDGE || row0 + r0 + 8 < M)
                    *(float2*)(out + (size_t)(row0 + r0 + 8) * Dd + c) = make_float2(v2, v3);
                if (EDGE) {
                    float* a0 = g_agg + (size_t)rv0 * Dd + c;
                    float* a1 = g_agg + (size_t)rv1 * Dd + c;
                    atomicAdd(a0, v0); atomicAdd(a0 + 1, v1);
                    atomicAdd(a1, v2); atomicAdd(a1 + 1, v3);
                }
            }
        }
    }
}

// ---------------- launch ----------------
constexpr int SMEM_PRE  = 98304;
constexpr int SMEM_EDGE = 1024 + 2 * 16384 + 2 * 16384 + 2 * 16384 + 2 * 32768; // 164864
constexpr int SMEM_NODE = 1024 + 2 * 32768 + 2 * 16384 + 2 * 32768 + 2 * 32768; // 230400

extern "C" void kernel_launch(void* const* d_in, const int* in_sizes, int n_in,
                              void* d_out, int out_size)
{
    const float* node_feats = (const float*)d_in[0];
    const float* edge_feats = (const float*)d_in[1];
    const float* We1 = (const float*)d_in[2];
    const float* be1 = (const float*)d_in[3];
    const float* We2 = (const float*)d_in[4];
    const float* be2 = (const float*)d_in[5];
    const float* Wn1 = (const float*)d_in[6];
    const float* bn1 = (const float*)d_in[7];
    const float* Wn2 = (const float*)d_in[8];
    const float* bn2 = (const float*)d_in[9];
    const int* senders   = (const int*)d_in[10];
    const int* receivers = (const int*)d_in[11];

    float* e_out = (float*)d_out;
    float* n_out = e_out + (size_t)N_EDGES * Dd;

    cudaFuncSetAttribute(pre_kernel, cudaFuncAttributeMaxDynamicSharedMemorySize, SMEM_PRE);
    cudaFuncSetAttribute(gnn_mlp<true>,  cudaFuncAttributeMaxDynamicSharedMemorySize, SMEM_EDGE);
    cudaFuncSetAttribute(gnn_mlp<false>, cudaFuncAttributeMaxDynamicSharedMemorySize, SMEM_NODE);

    const int n_tiles = (N_NODES + BM - 1) / BM;   // 391

    // 1) P tables + zero g_agg
    pre_kernel<<<n_tiles, 256, SMEM_PRE>>>(node_feats, We1);

    // 2) edge pass (persistent)
    gnn_mlp<true><<<148, 256, SMEM_EDGE>>>(
        edge_feats, node_feats, We1, be1, We2, be2,
        senders, receivers, e_out, N_EDGES, N_EDGES / BM);

    // 3) node pass (persistent)
    gnn_mlp<false><<<148, 256, SMEM_NODE>>>(
        nullptr, node_feats, Wn1, bn1, Wn2, bn2,
        nullptr, nullptr, n_out, N_NODES, n_tiles);
}

// round 6
// speedup vs baseline: 2.8999x; 1.1460x over previous
#include <cuda_runtime.h>
#include <cuda_fp16.h>
#include <cstdint>

// ---------------- problem constants ----------------
constexpr int Dd = 64, Hh = 128, N_NODES = 50000, N_EDGES = 800000, BM = 128;

// ---------------- device scratch (no cudaMalloc allowed) ----------------
__device__ float g_agg[(size_t)N_NODES * Dd];
__device__ float g_P[(size_t)N_NODES * 256];   // [n, 0:128)=nf@W1b (sender), [128:256)=nf@W1c (receiver)

// ---------------- helpers ----------------
__device__ __forceinline__ uint32_t smem_u32(const void* p) {
    uint32_t a;
    asm("{ .reg .u64 t; cvta.to.shared.u64 t, %1; cvt.u32.u64 %0, t; }" : "=r"(a) : "l"(p));
    return a;
}
__device__ __forceinline__ void ldsm4(uint32_t* r, uint32_t addr) {
    asm volatile("ldmatrix.sync.aligned.m8n8.x4.shared.b16 {%0,%1,%2,%3}, [%4];"
                 : "=r"(r[0]), "=r"(r[1]), "=r"(r[2]), "=r"(r[3]) : "r"(addr));
}
__device__ __forceinline__ void mma16816(float* c, const uint32_t* a, const uint32_t* b) {
    asm volatile("mma.sync.aligned.m16n8k16.row.col.f32.f16.f16.f32 "
                 "{%0,%1,%2,%3}, {%4,%5,%6,%7}, {%8,%9}, {%0,%1,%2,%3};"
                 : "+f"(c[0]), "+f"(c[1]), "+f"(c[2]), "+f"(c[3])
                 : "r"(a[0]), "r"(a[1]), "r"(a[2]), "r"(a[3]), "r"(b[0]), "r"(b[1]));
}
__device__ __forceinline__ void split2(float x, float y, uint32_t& hi, uint32_t& lo) {
    __half2 hp = __float22half2_rn(make_float2(x, y));
    float2 hb = __half22float2(hp);
    __half2 lp = __float22half2_rn(make_float2(x - hb.x, y - hb.y));
    hi = *(uint32_t*)&hp; lo = *(uint32_t*)&lp;
}
__device__ __forceinline__ uint32_t pack_hi(float x, float y) {
    __half2 hp = __float22half2_rn(make_float2(x, y));
    return *(uint32_t*)&hp;
}
__device__ __forceinline__ void red_add_v2(float* p, float v0, float v1) {
    asm volatile("red.global.add.v2.f32 [%0], {%1,%2};" :: "l"(p), "f"(v0), "f"(v1) : "memory");
}
// XOR-swizzled byte offset inside an image whose rows are RB bytes (RB multiple of 128)
template<int RB>
__device__ __forceinline__ uint32_t ioff(int r, int cb) {
    return (uint32_t)(r * RB + ((((cb >> 4) ^ (r & 7)) << 4) | (cb & 15)));
}

// ---------------- precompute kernel: P = nf @ [W1b|W1c], plus zero g_agg ----------------
// Persistent (148 blocks); B weight image built ONCE per block with coalesced reads.
__global__ void __launch_bounds__(256, 1)
pre_kernel(const float* __restrict__ nf, const float* __restrict__ We1)
{
    constexpr uint32_t BH = 0, BL = 32768, AH = 65536, AL = 81920; // total 98304
    constexpr int NT = (N_NODES + BM - 1) / BM;
    extern __shared__ unsigned char smem[];
    const uint32_t sb = smem_u32(smem);
    const int tid = threadIdx.x, lane = tid & 31, wid = tid >> 5;
    const int mw = wid >> 2, nw = wid & 3;
    const int lr = lane >> 2, lc = (lane & 3) * 2;

    // zero g_agg
    {
        float4* p = (float4*)g_agg;
        for (int i = blockIdx.x * 256 + tid; i < N_NODES * Dd / 4; i += gridDim.x * 256)
            p[i] = make_float4(0.f, 0.f, 0.f, 0.f);
    }

    // B image (coalesced: consecutive tid -> consecutive n)
    for (int i = tid; i < 64 * 256; i += 256) {
        int k = i >> 8, n = i & 255;
        int srow = (n < 128) ? (64 + k) : (128 + k);
        float v = We1[(size_t)srow * Hh + (n & 127)];
        __half h = __float2half_rn(v);
        uint32_t o = ioff<128>(n, k * 2);
        *(__half*)(smem + BH + o) = h;
        *(__half*)(smem + BL + o) = __float2half_rn(v - __half2float(h));
    }
    __syncthreads();

    for (int tile = blockIdx.x; tile < NT; tile += gridDim.x) {
        const int row0 = tile * BM;
        __syncthreads();   // prev tile's A readers done
        #pragma unroll
        for (int it = 0; it < 8; it++) {
            int idx = it * 256 + tid, r = idx >> 4, c4 = idx & 15;
            int grow = row0 + r;
            float4 v = (grow < N_NODES) ? *(const float4*)(nf + (size_t)grow * Dd + c4 * 4)
                                        : make_float4(0.f, 0.f, 0.f, 0.f);
            uint2 hv, lv;
            split2(v.x, v.y, hv.x, lv.x);
            split2(v.z, v.w, hv.y, lv.y);
            uint32_t o = ioff<128>(r, c4 * 8);
            *(uint2*)(smem + AH + o) = hv;
            *(uint2*)(smem + AL + o) = lv;
        }
        __syncthreads();

        float acc[4][32];
        #pragma unroll
        for (int a = 0; a < 4; a++)
            #pragma unroll
            for (int b = 0; b < 32; b++) acc[a][b] = 0.f;

        #pragma unroll
        for (int ks = 0; ks < 64; ks += 16) {
            uint32_t ah[4][4], al[4][4], bh[8][2], bl[8][2];
            #pragma unroll
            for (int mi = 0; mi < 4; mi++) {
                uint32_t ao = ioff<128>(mw * 64 + mi * 16 + (lane & 15), ks * 2 + (lane >> 4) * 16);
                ldsm4(ah[mi], sb + AH + ao);
                ldsm4(al[mi], sb + AL + ao);
            }
            #pragma unroll
            for (int p = 0; p < 4; p++) {
                uint32_t t[4], u[4];
                uint32_t bo = ioff<128>(nw * 64 + p * 16 + (lane & 15), ks * 2 + (lane >> 4) * 16);
                ldsm4(t, sb + BH + bo);
                ldsm4(u, sb + BL + bo);
                bh[2*p][0] = t[0]; bh[2*p+1][0] = t[1]; bh[2*p][1] = t[2]; bh[2*p+1][1] = t[3];
                bl[2*p][0] = u[0]; bl[2*p+1][0] = u[1]; bl[2*p][1] = u[2]; bl[2*p+1][1] = u[3];
            }
            #pragma unroll
            for (int mi = 0; mi < 4; mi++)
                #pragma unroll
                for (int ni = 0; ni < 8; ni++) {
                    mma16816(&acc[mi][ni*4], ah[mi], bh[ni]);
                    mma16816(&acc[mi][ni*4], al[mi], bh[ni]);
                    mma16816(&acc[mi][ni*4], ah[mi], bl[ni]);
                }
        }

        #pragma unroll
        for (int mi = 0; mi < 4; mi++) {
            int r0 = row0 + mw * 64 + mi * 16 + lr;
            #pragma unroll
            for (int ni = 0; ni < 8; ni++) {
                int c = nw * 64 + ni * 8 + lc;
                if (r0 < N_NODES)
                    *(float2*)(g_P + (size_t)r0 * 256 + c) = make_float2(acc[mi][ni*4+0], acc[mi][ni*4+1]);
                if (r0 + 8 < N_NODES)
                    *(float2*)(g_P + (size_t)(r0 + 8) * 256 + c) = make_float2(acc[mi][ni*4+2], acc[mi][ni*4+3]);
            }
        }
    }
}

// ---------------- fused 2-layer MLP (persistent, HMMA, full-h, hi-only h) ----------------
template<bool EDGE>
__global__ void __launch_bounds__(256, 1)
gnn_mlp(const float* __restrict__ f0, const float* __restrict__ node_feats,
        const float* __restrict__ W1g, const float* __restrict__ b1g,
        const float* __restrict__ W2g, const float* __restrict__ b2g,
        const int* __restrict__ senders, const int* __restrict__ receivers,
        float* __restrict__ out, int M, int num_tiles)
{
    constexpr int AK  = EDGE ? 64 : 128;    // layer-1 K
    constexpr int ARB = AK * 2;             // A / B1 image row bytes
    constexpr uint32_t B1H = 1024;
    constexpr uint32_t B1SZ = 128u * ARB;
    constexpr uint32_t B1L = B1H + B1SZ;
    constexpr uint32_t B2H = B1L + B1SZ;
    constexpr uint32_t B2L = B2H + 16384;
    constexpr uint32_t AH  = B2L + 16384;
    constexpr uint32_t AL  = AH + B1SZ;
    constexpr uint32_t HHo = AL + B1SZ;     // h hi image only (32 KB)

    extern __shared__ unsigned char smem[];
    const uint32_t sb = smem_u32(smem);
    const int tid = threadIdx.x, lane = tid & 31, wid = tid >> 5;
    const int mw = wid >> 2, nw = wid & 3;
    const int lr = lane >> 2, lc = (lane & 3) * 2;
    int* sSend = (int*)(smem + 0);
    int* sRecv = (int*)(smem + 512);

    // one-time weight images (coalesced reads: consecutive tid -> consecutive n)
    for (int i = tid; i < 128 * AK; i += 256) {
        int k = i >> 7, n = i & 127;
        float v = W1g[(size_t)k * Hh + n];
        __half h = __float2half_rn(v);
        uint32_t o = ioff<ARB>(n, k * 2);
        *(__half*)(smem + B1H + o) = h;
        *(__half*)(smem + B1L + o) = __float2half_rn(v - __half2float(h));
    }
    for (int i = tid; i < 64 * 128; i += 256) {
        int k = i >> 6, n = i & 63;
        float v = W2g[(size_t)k * Dd + n];
        __half h = __float2half_rn(v);
        uint32_t o = ioff<256>(n, k * 2);
        *(__half*)(smem + B2H + o) = h;
        *(__half*)(smem + B2L + o) = __float2half_rn(v - __half2float(h));
    }
    __syncthreads();

    for (int tile = blockIdx.x; tile < num_tiles; tile += gridDim.x) {
        const int row0 = tile * BM;
        __syncthreads();   // prev tile epilogue readers done
        if (EDGE && tid < BM) {
            sSend[tid] = senders[row0 + tid];
            sRecv[tid] = receivers[row0 + tid];
        }
        // ---- build A image ----
        if (EDGE) {
            #pragma unroll
            for (int it = 0; it < 8; it++) {
                int idx = it * 256 + tid, r = idx >> 4, c4 = idx & 15;
                float4 v = *(const float4*)(f0 + (size_t)(row0 + r) * Dd + c4 * 4);
                uint2 hv, lv;
                split2(v.x, v.y, hv.x, lv.x);
                split2(v.z, v.w, hv.y, lv.y);
                uint32_t o = ioff<ARB>(r, c4 * 8);
                *(uint2*)(smem + AH + o) = hv;
                *(uint2*)(smem + AL + o) = lv;
            }
        } else {
            #pragma unroll
            for (int it = 0; it < 16; it++) {
                int idx = it * 256 + tid, r = idx >> 5, c8 = idx & 31;
                int col = c8 * 4, grow = row0 + r;
                float4 v = make_float4(0.f, 0.f, 0.f, 0.f);
                if (grow < M)
                    v = (col < Dd) ? *(const float4*)(g_agg + (size_t)grow * Dd + col)
                                   : *(const float4*)(node_feats + (size_t)grow * Dd + col - Dd);
                uint2 hv, lv;
                split2(v.x, v.y, hv.x, lv.x);
                split2(v.z, v.w, hv.y, lv.y);
                uint32_t o = ioff<ARB>(r, c8 * 8);
                *(uint2*)(smem + AH + o) = hv;
                *(uint2*)(smem + AL + o) = lv;
            }
        }
        __syncthreads();

        // ---- layer 1: C1[128x128] = A @ W1part (3-term) ----
        float acc1[4][16];
        #pragma unroll
        for (int a = 0; a < 4; a++)
            #pragma unroll
            for (int b = 0; b < 16; b++) acc1[a][b] = 0.f;

        #pragma unroll
        for (int ks = 0; ks < AK; ks += 16) {
            uint32_t ah[4][4], al[4][4], bh[4][2], bl[4][2];
            #pragma unroll
            for (int mi = 0; mi < 4; mi++) {
                uint32_t ao = ioff<ARB>(mw * 64 + mi * 16 + (lane & 15), ks * 2 + (lane >> 4) * 16);
                ldsm4(ah[mi], sb + AH + ao);
                ldsm4(al[mi], sb + AL + ao);
            }
            #pragma unroll
            for (int p = 0; p < 2; p++) {
                uint32_t t[4], u[4];
                uint32_t bo = ioff<ARB>(nw * 32 + p * 16 + (lane & 15), ks * 2 + (lane >> 4) * 16);
                ldsm4(t, sb + B1H + bo);
                ldsm4(u, sb + B1L + bo);
                bh[2*p][0] = t[0]; bh[2*p+1][0] = t[1]; bh[2*p][1] = t[2]; bh[2*p+1][1] = t[3];
                bl[2*p][0] = u[0]; bl[2*p+1][0] = u[1]; bl[2*p][1] = u[2]; bl[2*p+1][1] = u[3];
            }
            #pragma unroll
            for (int mi = 0; mi < 4; mi++)
                #pragma unroll
                for (int ni = 0; ni < 4; ni++) {
                    mma16816(&acc1[mi][ni*4], ah[mi], bh[ni]);
                    mma16816(&acc1[mi][ni*4], al[mi], bh[ni]);
                    mma16816(&acc1[mi][ni*4], ah[mi], bl[ni]);
                }
        }

        // ---- epilogue 1: (+P_s+P_r) + bias1, relu, pack fp16-hi, write h ----
        #pragma unroll
        for (int mi = 0; mi < 4; mi++) {
            int r0 = mw * 64 + mi * 16 + lr;
            float2 P0s[4], P0r[4], P1s[4], P1r[4];
            if (EDGE) {
                int s0 = sSend[r0], rv0 = sRecv[r0], s1 = sSend[r0 + 8], rv1 = sRecv[r0 + 8];
                #pragma unroll
                for (int ni = 0; ni < 4; ni++) {
                    int c0 = nw * 32 + ni * 8 + lc;
                    P0s[ni] = *(const float2*)(g_P + (size_t)s0  * 256 + c0);
                    P0r[ni] = *(const float2*)(g_P + (size_t)rv0 * 256 + 128 + c0);
                    P1s[ni] = *(const float2*)(g_P + (size_t)s1  * 256 + c0);
                    P1r[ni] = *(const float2*)(g_P + (size_t)rv1 * 256 + 128 + c0);
                }
            }
            #pragma unroll
            for (int ni = 0; ni < 4; ni++) {
                int c0 = nw * 32 + ni * 8 + lc;
                float bb0 = __ldg(b1g + c0), bb1 = __ldg(b1g + c0 + 1);
                float v0 = acc1[mi][ni*4+0] + bb0, v1 = acc1[mi][ni*4+1] + bb1;
                float v2 = acc1[mi][ni*4+2] + bb0, v3 = acc1[mi][ni*4+3] + bb1;
                if (EDGE) {
                    v0 += P0s[ni].x + P0r[ni].x; v1 += P0s[ni].y + P0r[ni].y;
                    v2 += P1s[ni].x + P1r[ni].x; v3 += P1s[ni].y + P1r[ni].y;
                }
                uint32_t h01 = pack_hi(fmaxf(v0, 0.f), fmaxf(v1, 0.f));
                uint32_t h23 = pack_hi(fmaxf(v2, 0.f), fmaxf(v3, 0.f));
                *(uint32_t*)(smem + HHo + ioff<256>(r0,     c0 * 2)) = h01;
                *(uint32_t*)(smem + HHo + ioff<256>(r0 + 8, c0 * 2)) = h23;
            }
        }
        __syncthreads();

        // ---- layer 2: C2[128x64] = h @ W2 (2-term: h_hi * (W2h + W2l)) ----
        float acc2[4][8];
        #pragma unroll
        for (int a = 0; a < 4; a++)
            #pragma unroll
            for (int b = 0; b < 8; b++) acc2[a][b] = 0.f;

        #pragma unroll
        for (int ks = 0; ks < 128; ks += 16) {
            uint32_t ah[4][4], bh[2][2], bl[2][2];
            #pragma unroll
            for (int mi = 0; mi < 4; mi++) {
                uint32_t ao = ioff<256>(mw * 64 + mi * 16 + (lane & 15), ks * 2 + (lane >> 4) * 16);
                ldsm4(ah[mi], sb + HHo + ao);
            }
            {
                uint32_t t[4], u[4];
                uint32_t bo = ioff<256>(nw * 16 + (lane & 15), ks * 2 + (lane >> 4) * 16);
                ldsm4(t, sb + B2H + bo);
                ldsm4(u, sb + B2L + bo);
                bh[0][0] = t[0]; bh[1][0] = t[1]; bh[0][1] = t[2]; bh[1][1] = t[3];
                bl[0][0] = u[0]; bl[1][0] = u[1]; bl[0][1] = u[2]; bl[1][1] = u[3];
            }
            #pragma unroll
            for (int mi = 0; mi < 4; mi++)
                #pragma unroll
                for (int ni = 0; ni < 2; ni++) {
                    mma16816(&acc2[mi][ni*4], ah[mi], bh[ni]);
                    mma16816(&acc2[mi][ni*4], ah[mi], bl[ni]);
                }
        }

        // ---- epilogue 2: bias2, store out, vector scatter-add ----
        #pragma unroll
        for (int mi = 0; mi < 4; mi++) {
            int r0 = mw * 64 + mi * 16 + lr;
            int rv0 = 0, rv1 = 0;
            if (EDGE) { rv0 = sRecv[r0]; rv1 = sRecv[r0 + 8]; }
            #pragma unroll
            for (int ni = 0; ni < 2; ni++) {
                int c = nw * 16 + ni * 8 + lc;
                float bb0 = __ldg(b2g + c), bb1 = __ldg(b2g + c + 1);
                float v0 = acc2[mi][ni*4+0] + bb0, v1 = acc2[mi][ni*4+1] + bb1;
                float v2 = acc2[mi][ni*4+2] + bb0, v3 = acc2[mi][ni*4+3] + bb1;
                if (EDGE || row0 + r0 < M)
                    *(float2*)(out + (size_t)(row0 + r0) * Dd + c) = make_float2(v0, v1);
                if (EDGE || row0 + r0 + 8 < M)
                    *(float2*)(out + (size_t)(row0 + r0 + 8) * Dd + c) = make_float2(v2, v3);
                if (EDGE) {
                    red_add_v2(g_agg + (size_t)rv0 * Dd + c, v0, v1);
                    red_add_v2(g_agg + (size_t)rv1 * Dd + c, v2, v3);
                }
            }
        }
    }
}

// ---------------- launch ----------------
constexpr int SMEM_PRE  = 98304;
constexpr int SMEM_EDGE = 1024 + 2 * 16384 + 2 * 16384 + 2 * 16384 + 32768;  // 132096
constexpr int SMEM_NODE = 1024 + 2 * 32768 + 2 * 16384 + 2 * 32768 + 32768;  // 197632

extern "C" void kernel_launch(void* const* d_in, const int* in_sizes, int n_in,
                              void* d_out, int out_size)
{
    const float* node_feats = (const float*)d_in[0];
    const float* edge_feats = (const float*)d_in[1];
    const float* We1 = (const float*)d_in[2];
    const float* be1 = (const float*)d_in[3];
    const float* We2 = (const float*)d_in[4];
    const float* be2 = (const float*)d_in[5];
    const float* Wn1 = (const float*)d_in[6];
    const float* bn1 = (const float*)d_in[7];
    const float* Wn2 = (const float*)d_in[8];
    const float* bn2 = (const float*)d_in[9];
    const int* senders   = (const int*)d_in[10];
    const int* receivers = (const int*)d_in[11];

    float* e_out = (float*)d_out;
    float* n_out = e_out + (size_t)N_EDGES * Dd;

    cudaFuncSetAttribute(pre_kernel, cudaFuncAttributeMaxDynamicSharedMemorySize, SMEM_PRE);
    cudaFuncSetAttribute(gnn_mlp<true>,  cudaFuncAttributeMaxDynamicSharedMemorySize, SMEM_EDGE);
    cudaFuncSetAttribute(gnn_mlp<false>, cudaFuncAttributeMaxDynamicSharedMemorySize, SMEM_NODE);

    const int n_tiles = (N_NODES + BM - 1) / BM;   // 391

    pre_kernel<<<148, 256, SMEM_PRE>>>(node_feats, We1);

    gnn_mlp<true><<<148, 256, SMEM_EDGE>>>(
        edge_feats, node_feats, We1, be1, We2, be2,
        senders, receivers, e_out, N_EDGES, N_EDGES / BM);

    gnn_mlp<false><<<148, 256, SMEM_NODE>>>(
        nullptr, node_feats, Wn1, bn1, Wn2, bn2,
        nullptr, nullptr, n_out, N_NODES, n_tiles);
}

// round 7
// speedup vs baseline: 2.9746x; 1.0257x over previous
#include <cuda_runtime.h>
#include <cuda_fp16.h>
#include <cstdint>

// ---------------- problem constants ----------------
constexpr int Dd = 64, Hh = 128, N_NODES = 50000, N_EDGES = 800000, BM = 128;

// ---------------- device scratch (no cudaMalloc allowed) ----------------
__device__ float g_agg[(size_t)N_NODES * Dd];
__device__ float g_P[(size_t)N_NODES * 256];   // [n, 0:128)=nf@W1b (sender), [128:256)=nf@W1c (receiver)

// ---------------- helpers ----------------
__device__ __forceinline__ uint32_t smem_u32(const void* p) {
    uint32_t a;
    asm("{ .reg .u64 t; cvta.to.shared.u64 t, %1; cvt.u32.u64 %0, t; }" : "=r"(a) : "l"(p));
    return a;
}
__device__ __forceinline__ void ldsm4(uint32_t* r, uint32_t addr) {
    asm volatile("ldmatrix.sync.aligned.m8n8.x4.shared.b16 {%0,%1,%2,%3}, [%4];"
                 : "=r"(r[0]), "=r"(r[1]), "=r"(r[2]), "=r"(r[3]) : "r"(addr));
}
__device__ __forceinline__ void ldsm2(uint32_t* r, uint32_t addr) {
    asm volatile("ldmatrix.sync.aligned.m8n8.x2.shared.b16 {%0,%1}, [%2];"
                 : "=r"(r[0]), "=r"(r[1]) : "r"(addr));
}
__device__ __forceinline__ void mma16816(float* c, const uint32_t* a, const uint32_t* b) {
    asm volatile("mma.sync.aligned.m16n8k16.row.col.f32.f16.f16.f32 "
                 "{%0,%1,%2,%3}, {%4,%5,%6,%7}, {%8,%9}, {%0,%1,%2,%3};"
                 : "+f"(c[0]), "+f"(c[1]), "+f"(c[2]), "+f"(c[3])
                 : "r"(a[0]), "r"(a[1]), "r"(a[2]), "r"(a[3]), "r"(b[0]), "r"(b[1]));
}
__device__ __forceinline__ void split2(float x, float y, uint32_t& hi, uint32_t& lo) {
    __half2 hp = __float22half2_rn(make_float2(x, y));
    float2 hb = __half22float2(hp);
    __half2 lp = __float22half2_rn(make_float2(x - hb.x, y - hb.y));
    hi = *(uint32_t*)&hp; lo = *(uint32_t*)&lp;
}
__device__ __forceinline__ uint32_t pack_hi(float x, float y) {
    __half2 hp = __float22half2_rn(make_float2(x, y));
    return *(uint32_t*)&hp;
}
__device__ __forceinline__ void red_add_v2(float* p, float v0, float v1) {
    asm volatile("red.global.add.v2.f32 [%0], {%1,%2};" :: "l"(p), "f"(v0), "f"(v1) : "memory");
}
// XOR-swizzled byte offset inside an image whose rows are RB bytes (RB multiple of 128)
template<int RB>
__device__ __forceinline__ uint32_t ioff(int r, int cb) {
    return (uint32_t)(r * RB + ((((cb >> 4) ^ (r & 7)) << 4) | (cb & 15)));
}

// ---------------- precompute kernel: P = nf @ [W1b|W1c], plus zero g_agg ----------------
// 512 threads, warp grid 2m x 8n (64 rows x 32 P-cols per warp).
__global__ void __launch_bounds__(512, 1)
pre_kernel(const float* __restrict__ nf, const float* __restrict__ We1)
{
    constexpr uint32_t BH = 0, BL = 32768, AH = 65536, AL = 81920; // total 98304
    constexpr int NT = (N_NODES + BM - 1) / BM;
    extern __shared__ unsigned char smem[];
    const uint32_t sb = smem_u32(smem);
    const int tid = threadIdx.x, lane = tid & 31, wid = tid >> 5;
    const int mw = wid >> 3, nw = wid & 7;
    const int lr = lane >> 2, lc = (lane & 3) * 2;

    // zero g_agg
    {
        float4* p = (float4*)g_agg;
        for (int i = blockIdx.x * 512 + tid; i < N_NODES * Dd / 4; i += gridDim.x * 512)
            p[i] = make_float4(0.f, 0.f, 0.f, 0.f);
    }

    // B image: 256 P-cols x 64 k (hi/lo), coalesced reads
    for (int i = tid; i < 64 * 256; i += 512) {
        int k = i >> 8, n = i & 255;
        int srow = (n < 128) ? (64 + k) : (128 + k);
        float v = We1[(size_t)srow * Hh + (n & 127)];
        __half h = __float2half_rn(v);
        uint32_t o = ioff<128>(n, k * 2);
        *(__half*)(smem + BH + o) = h;
        *(__half*)(smem + BL + o) = __float2half_rn(v - __half2float(h));
    }
    __syncthreads();

    for (int tile = blockIdx.x; tile < NT; tile += gridDim.x) {
        const int row0 = tile * BM;
        __syncthreads();
        #pragma unroll
        for (int it = 0; it < 4; it++) {
            int idx = it * 512 + tid, r = idx >> 4, c4 = idx & 15;
            int grow = row0 + r;
            float4 v = (grow < N_NODES) ? *(const float4*)(nf + (size_t)grow * Dd + c4 * 4)
                                        : make_float4(0.f, 0.f, 0.f, 0.f);
            uint2 hv, lv;
            split2(v.x, v.y, hv.x, lv.x);
            split2(v.z, v.w, hv.y, lv.y);
            uint32_t o = ioff<128>(r, c4 * 8);
            *(uint2*)(smem + AH + o) = hv;
            *(uint2*)(smem + AL + o) = lv;
        }
        __syncthreads();

        float acc[4][16];
        #pragma unroll
        for (int a = 0; a < 4; a++)
            #pragma unroll
            for (int b = 0; b < 16; b++) acc[a][b] = 0.f;

        #pragma unroll
        for (int ks = 0; ks < 64; ks += 16) {
            uint32_t ah[4][4], al[4][4], bh[4][2], bl[4][2];
            #pragma unroll
            for (int mi = 0; mi < 4; mi++) {
                uint32_t ao = ioff<128>(mw * 64 + mi * 16 + (lane & 15), ks * 2 + (lane >> 4) * 16);
                ldsm4(ah[mi], sb + AH + ao);
                ldsm4(al[mi], sb + AL + ao);
            }
            #pragma unroll
            for (int p = 0; p < 2; p++) {
                uint32_t t[4], u[4];
                uint32_t bo = ioff<128>(nw * 32 + p * 16 + (lane & 15), ks * 2 + (lane >> 4) * 16);
                ldsm4(t, sb + BH + bo);
                ldsm4(u, sb + BL + bo);
                bh[2*p][0] = t[0]; bh[2*p+1][0] = t[1]; bh[2*p][1] = t[2]; bh[2*p+1][1] = t[3];
                bl[2*p][0] = u[0]; bl[2*p+1][0] = u[1]; bl[2*p][1] = u[2]; bl[2*p+1][1] = u[3];
            }
            #pragma unroll
            for (int mi = 0; mi < 4; mi++)
                #pragma unroll
                for (int ni = 0; ni < 4; ni++) {
                    mma16816(&acc[mi][ni*4], ah[mi], bh[ni]);
                    mma16816(&acc[mi][ni*4], al[mi], bh[ni]);
                    mma16816(&acc[mi][ni*4], ah[mi], bl[ni]);
                }
        }

        #pragma unroll
        for (int mi = 0; mi < 4; mi++) {
            int r0 = row0 + mw * 64 + mi * 16 + lr;
            #pragma unroll
            for (int ni = 0; ni < 4; ni++) {
                int c = nw * 32 + ni * 8 + lc;
                if (r0 < N_NODES)
                    *(float2*)(g_P + (size_t)r0 * 256 + c) = make_float2(acc[mi][ni*4+0], acc[mi][ni*4+1]);
                if (r0 + 8 < N_NODES)
                    *(float2*)(g_P + (size_t)(r0 + 8) * 256 + c) = make_float2(acc[mi][ni*4+2], acc[mi][ni*4+3]);
            }
        }
    }
}

// ---------------- fused 2-layer MLP (512 threads, warp grid 2m x 8n) ----------------
template<bool EDGE>
__global__ void __launch_bounds__(512, 1)
gnn_mlp(const float* __restrict__ f0, const float* __restrict__ node_feats,
        const float* __restrict__ W1g, const float* __restrict__ b1g,
        const float* __restrict__ W2g, const float* __restrict__ b2g,
        const int* __restrict__ senders, const int* __restrict__ receivers,
        float* __restrict__ out, int M, int num_tiles)
{
    constexpr int AK  = EDGE ? 64 : 128;    // layer-1 K
    constexpr int ARB = AK * 2;             // A / B1 image row bytes
    constexpr uint32_t B1H = 1024;
    constexpr uint32_t B1SZ = 128u * ARB;
    constexpr uint32_t B1L = B1H + B1SZ;
    constexpr uint32_t B2H = B1L + B1SZ;
    constexpr uint32_t B2L = B2H + 16384;
    constexpr uint32_t AH  = B2L + 16384;
    constexpr uint32_t AL  = AH + B1SZ;
    constexpr uint32_t HHo = AL + B1SZ;     // h hi image only (32 KB)

    extern __shared__ unsigned char smem[];
    const uint32_t sb = smem_u32(smem);
    const int tid = threadIdx.x, lane = tid & 31, wid = tid >> 5;
    const int mw = wid >> 3;          // 0..1 : 64 rows
    const int nw = wid & 7;           // 0..7 : 16 layer1-cols / 8 layer2-cols
    const int lr = lane >> 2, lc = (lane & 3) * 2;
    int* sSend = (int*)(smem + 0);
    int* sRecv = (int*)(smem + 512);

    // one-time weight images
    for (int i = tid; i < 128 * AK; i += 512) {
        int k = i >> 7, n = i & 127;
        float v = W1g[(size_t)k * Hh + n];
        __half h = __float2half_rn(v);
        uint32_t o = ioff<ARB>(n, k * 2);
        *(__half*)(smem + B1H + o) = h;
        *(__half*)(smem + B1L + o) = __float2half_rn(v - __half2float(h));
    }
    for (int i = tid; i < 64 * 128; i += 512) {
        int k = i >> 6, n = i & 63;
        float v = W2g[(size_t)k * Dd + n];
        __half h = __float2half_rn(v);
        uint32_t o = ioff<256>(n, k * 2);
        *(__half*)(smem + B2H + o) = h;
        *(__half*)(smem + B2L + o) = __float2half_rn(v - __half2float(h));
    }
    // hoisted per-thread biases
    const int cb1 = nw * 16 + lc;
    const float b1r0 = __ldg(b1g + cb1),     b1r1 = __ldg(b1g + cb1 + 1);
    const float b1r2 = __ldg(b1g + cb1 + 8), b1r3 = __ldg(b1g + cb1 + 9);
    const int cb2 = nw * 8 + lc;
    const float b2r0 = __ldg(b2g + cb2), b2r1 = __ldg(b2g + cb2 + 1);
    __syncthreads();

    for (int tile = blockIdx.x; tile < num_tiles; tile += gridDim.x) {
        const int row0 = tile * BM;
        __syncthreads();
        if (EDGE && tid < BM) {
            sSend[tid] = senders[row0 + tid];
            sRecv[tid] = receivers[row0 + tid];
        }
        // ---- build A image ----
        if (EDGE) {
            #pragma unroll
            for (int it = 0; it < 4; it++) {
                int idx = it * 512 + tid, r = idx >> 4, c4 = idx & 15;
                float4 v = *(const float4*)(f0 + (size_t)(row0 + r) * Dd + c4 * 4);
                uint2 hv, lv;
                split2(v.x, v.y, hv.x, lv.x);
                split2(v.z, v.w, hv.y, lv.y);
                uint32_t o = ioff<ARB>(r, c4 * 8);
                *(uint2*)(smem + AH + o) = hv;
                *(uint2*)(smem + AL + o) = lv;
            }
        } else {
            #pragma unroll
            for (int it = 0; it < 8; it++) {
                int idx = it * 512 + tid, r = idx >> 5, c8 = idx & 31;
                int col = c8 * 4, grow = row0 + r;
                float4 v = make_float4(0.f, 0.f, 0.f, 0.f);
                if (grow < M)
                    v = (col < Dd) ? *(const float4*)(g_agg + (size_t)grow * Dd + col)
                                   : *(const float4*)(node_feats + (size_t)grow * Dd + col - Dd);
                uint2 hv, lv;
                split2(v.x, v.y, hv.x, lv.x);
                split2(v.z, v.w, hv.y, lv.y);
                uint32_t o = ioff<ARB>(r, c8 * 8);
                *(uint2*)(smem + AH + o) = hv;
                *(uint2*)(smem + AL + o) = lv;
            }
        }
        __syncthreads();

        // ---- layer 1: C1[128x128] = A @ W1part (3-term), warp covers 64r x 16c ----
        float acc1[4][8];
        #pragma unroll
        for (int a = 0; a < 4; a++)
            #pragma unroll
            for (int b = 0; b < 8; b++) acc1[a][b] = 0.f;

        #pragma unroll
        for (int ks = 0; ks < AK; ks += 16) {
            uint32_t ah[4][4], al[4][4], bh[2][2], bl[2][2];
            #pragma unroll
            for (int mi = 0; mi < 4; mi++) {
                uint32_t ao = ioff<ARB>(mw * 64 + mi * 16 + (lane & 15), ks * 2 + (lane >> 4) * 16);
                ldsm4(ah[mi], sb + AH + ao);
                ldsm4(al[mi], sb + AL + ao);
            }
            {
                uint32_t t[4], u[4];
                uint32_t bo = ioff<ARB>(nw * 16 + (lane & 15), ks * 2 + (lane >> 4) * 16);
                ldsm4(t, sb + B1H + bo);
                ldsm4(u, sb + B1L + bo);
                bh[0][0] = t[0]; bh[1][0] = t[1]; bh[0][1] = t[2]; bh[1][1] = t[3];
                bl[0][0] = u[0]; bl[1][0] = u[1]; bl[0][1] = u[2]; bl[1][1] = u[3];
            }
            #pragma unroll
            for (int mi = 0; mi < 4; mi++)
                #pragma unroll
                for (int ni = 0; ni < 2; ni++) {
                    mma16816(&acc1[mi][ni*4], ah[mi], bh[ni]);
                    mma16816(&acc1[mi][ni*4], al[mi], bh[ni]);
                    mma16816(&acc1[mi][ni*4], ah[mi], bl[ni]);
                }
        }

        // ---- epilogue 1: (+P_s+P_r) + bias1, relu, pack fp16-hi, write h ----
        #pragma unroll
        for (int mi = 0; mi < 4; mi++) {
            int r0 = mw * 64 + mi * 16 + lr;
            float2 P0s[2], P0r[2], P1s[2], P1r[2];
            if (EDGE) {
                int s0 = sSend[r0], rv0 = sRecv[r0], s1 = sSend[r0 + 8], rv1 = sRecv[r0 + 8];
                #pragma unroll
                for (int ni = 0; ni < 2; ni++) {
                    int c0 = nw * 16 + ni * 8 + lc;
                    P0s[ni] = *(const float2*)(g_P + (size_t)s0  * 256 + c0);
                    P0r[ni] = *(const float2*)(g_P + (size_t)rv0 * 256 + 128 + c0);
                    P1s[ni] = *(const float2*)(g_P + (size_t)s1  * 256 + c0);
                    P1r[ni] = *(const float2*)(g_P + (size_t)rv1 * 256 + 128 + c0);
                }
            }
            #pragma unroll
            for (int ni = 0; ni < 2; ni++) {
                int c0 = nw * 16 + ni * 8 + lc;
                float bb0 = ni ? b1r2 : b1r0, bb1 = ni ? b1r3 : b1r1;
                float v0 = acc1[mi][ni*4+0] + bb0, v1 = acc1[mi][ni*4+1] + bb1;
                float v2 = acc1[mi][ni*4+2] + bb0, v3 = acc1[mi][ni*4+3] + bb1;
                if (EDGE) {
                    v0 += P0s[ni].x + P0r[ni].x; v1 += P0s[ni].y + P0r[ni].y;
                    v2 += P1s[ni].x + P1r[ni].x; v3 += P1s[ni].y + P1r[ni].y;
                }
                uint32_t h01 = pack_hi(fmaxf(v0, 0.f), fmaxf(v1, 0.f));
                uint32_t h23 = pack_hi(fmaxf(v2, 0.f), fmaxf(v3, 0.f));
                *(uint32_t*)(smem + HHo + ioff<256>(r0,     c0 * 2)) = h01;
                *(uint32_t*)(smem + HHo + ioff<256>(r0 + 8, c0 * 2)) = h23;
            }
        }
        __syncthreads();

        // ---- layer 2: C2[128x64] = h @ W2 (2-term), warp covers 64r x 8c ----
        float acc2[4][4];
        #pragma unroll
        for (int a = 0; a < 4; a++)
            #pragma unroll
            for (int b = 0; b < 4; b++) acc2[a][b] = 0.f;

        #pragma unroll
        for (int ks = 0; ks < 128; ks += 16) {
            uint32_t ah[4][4], bh[2], bl[2];
            #pragma unroll
            for (int mi = 0; mi < 4; mi++) {
                uint32_t ao = ioff<256>(mw * 64 + mi * 16 + (lane & 15), ks * 2 + (lane >> 4) * 16);
                ldsm4(ah[mi], sb + HHo + ao);
            }
            {
                uint32_t bo = ioff<256>(nw * 8 + (lane & 7), ks * 2 + ((lane >> 3) & 1) * 16);
                ldsm2(bh, sb + B2H + bo);
                ldsm2(bl, sb + B2L + bo);
            }
            #pragma unroll
            for (int mi = 0; mi < 4; mi++) {
                mma16816(acc2[mi], ah[mi], bh);
                mma16816(acc2[mi], ah[mi], bl);
            }
        }

        // ---- epilogue 2: bias2, store out, vector scatter-add ----
        #pragma unroll
        for (int mi = 0; mi < 4; mi++) {
            int r0 = mw * 64 + mi * 16 + lr;
            int rv0 = 0, rv1 = 0;
            if (EDGE) { rv0 = sRecv[r0]; rv1 = sRecv[r0 + 8]; }
            int c = nw * 8 + lc;
            float v0 = acc2[mi][0] + b2r0, v1 = acc2[mi][1] + b2r1;
            float v2 = acc2[mi][2] + b2r0, v3 = acc2[mi][3] + b2r1;
            if (EDGE || row0 + r0 < M)
                *(float2*)(out + (size_t)(row0 + r0) * Dd + c) = make_float2(v0, v1);
            if (EDGE || row0 + r0 + 8 < M)
                *(float2*)(out + (size_t)(row0 + r0 + 8) * Dd + c) = make_float2(v2, v3);
            if (EDGE) {
                red_add_v2(g_agg + (size_t)rv0 * Dd + c, v0, v1);
                red_add_v2(g_agg + (size_t)rv1 * Dd + c, v2, v3);
            }
        }
    }
}

// ---------------- launch ----------------
constexpr int SMEM_PRE  = 98304;
constexpr int SMEM_EDGE = 1024 + 2 * 16384 + 2 * 16384 + 2 * 16384 + 32768;  // 132096
constexpr int SMEM_NODE = 1024 + 2 * 32768 + 2 * 16384 + 2 * 32768 + 32768;  // 197632

extern "C" void kernel_launch(void* const* d_in, const int* in_sizes, int n_in,
                              void* d_out, int out_size)
{
    const float* node_feats = (const float*)d_in[0];
    const float* edge_feats = (const float*)d_in[1];
    const float* We1 = (const float*)d_in[2];
    const float* be1 = (const float*)d_in[3];
    const float* We2 = (const float*)d_in[4];
    const float* be2 = (const float*)d_in[5];
    const float* Wn1 = (const float*)d_in[6];
    const float* bn1 = (const float*)d_in[7];
    const float* Wn2 = (const float*)d_in[8];
    const float* bn2 = (const float*)d_in[9];
    const int* senders   = (const int*)d_in[10];
    const int* receivers = (const int*)d_in[11];

    float* e_out = (float*)d_out;
    float* n_out = e_out + (size_t)N_EDGES * Dd;

    cudaFuncSetAttribute(pre_kernel, cudaFuncAttributeMaxDynamicSharedMemorySize, SMEM_PRE);
    cudaFuncSetAttribute(gnn_mlp<true>,  cudaFuncAttributeMaxDynamicSharedMemorySize, SMEM_EDGE);
    cudaFuncSetAttribute(gnn_mlp<false>, cudaFuncAttributeMaxDynamicSharedMemorySize, SMEM_NODE);

    const int n_tiles = (N_NODES + BM - 1) / BM;   // 391

    pre_kernel<<<148, 512, SMEM_PRE>>>(node_feats, We1);

    gnn_mlp<true><<<148, 512, SMEM_EDGE>>>(
        edge_feats, node_feats, We1, be1, We2, be2,
        senders, receivers, e_out, N_EDGES, N_EDGES / BM);

    gnn_mlp<false><<<148, 512, SMEM_NODE>>>(
        nullptr, node_feats, Wn1, bn1, Wn2, bn2,
        nullptr, nullptr, n_out, N_NODES, n_tiles);
}

// round 8
// speedup vs baseline: 3.3248x; 1.1177x over previous
#include <cuda_runtime.h>
#include <cuda_fp16.h>
#include <cstdint>

// ---------------- problem constants ----------------
constexpr int Dd = 64, Hh = 128, N_NODES = 50000, N_EDGES = 800000;
constexpr int TM = 64;   // rows per half-tile

// ---------------- device scratch (no cudaMalloc allowed) ----------------
__device__ float g_agg[(size_t)N_NODES * Dd];
__device__ float g_P[(size_t)N_NODES * 256];   // [n, 0:128)=nf@W1b (sender), [128:256)=nf@W1c (receiver)

// ---------------- helpers ----------------
__device__ __forceinline__ uint32_t smem_u32(const void* p) {
    uint32_t a;
    asm("{ .reg .u64 t; cvta.to.shared.u64 t, %1; cvt.u32.u64 %0, t; }" : "=r"(a) : "l"(p));
    return a;
}
__device__ __forceinline__ void ldsm4(uint32_t* r, uint32_t addr) {
    asm volatile("ldmatrix.sync.aligned.m8n8.x4.shared.b16 {%0,%1,%2,%3}, [%4];"
                 : "=r"(r[0]), "=r"(r[1]), "=r"(r[2]), "=r"(r[3]) : "r"(addr));
}
__device__ __forceinline__ void ldsm2(uint32_t* r, uint32_t addr) {
    asm volatile("ldmatrix.sync.aligned.m8n8.x2.shared.b16 {%0,%1}, [%2];"
                 : "=r"(r[0]), "=r"(r[1]) : "r"(addr));
}
__device__ __forceinline__ void mma16816(float* c, const uint32_t* a, const uint32_t* b) {
    asm volatile("mma.sync.aligned.m16n8k16.row.col.f32.f16.f16.f32 "
                 "{%0,%1,%2,%3}, {%4,%5,%6,%7}, {%8,%9}, {%0,%1,%2,%3};"
                 : "+f"(c[0]), "+f"(c[1]), "+f"(c[2]), "+f"(c[3])
                 : "r"(a[0]), "r"(a[1]), "r"(a[2]), "r"(a[3]), "r"(b[0]), "r"(b[1]));
}
__device__ __forceinline__ void split2(float x, float y, uint32_t& hi, uint32_t& lo) {
    __half2 hp = __float22half2_rn(make_float2(x, y));
    float2 hb = __half22float2(hp);
    __half2 lp = __float22half2_rn(make_float2(x - hb.x, y - hb.y));
    hi = *(uint32_t*)&hp; lo = *(uint32_t*)&lp;
}
__device__ __forceinline__ uint32_t pack_hi(float x, float y) {
    __half2 hp = __float22half2_rn(make_float2(x, y));
    return *(uint32_t*)&hp;
}
__device__ __forceinline__ void red_add_v2(float* p, float v0, float v1) {
    asm volatile("red.global.add.v2.f32 [%0], {%1,%2};" :: "l"(p), "f"(v0), "f"(v1) : "memory");
}
// XOR-swizzled byte offset; image rows are RB bytes (RB multiple of 128)
template<int RB>
__device__ __forceinline__ uint32_t ioff(int r, int cb) {
    return (uint32_t)(r * RB + ((((cb >> 4) ^ (r & 7)) << 4) | (cb & 15)));
}

// ---------------- precompute kernel: P = nf @ [W1b|W1c], plus zero g_agg ----------------
__global__ void __launch_bounds__(512, 1)
pre_kernel(const float* __restrict__ nf, const float* __restrict__ We1)
{
    constexpr uint32_t BH = 0, BL = 32768, AH = 65536, AL = 81920; // total 98304
    constexpr int NT = (N_NODES + 127) / 128;
    extern __shared__ unsigned char smem[];
    const uint32_t sb = smem_u32(smem);
    const int tid = threadIdx.x, lane = tid & 31, wid = tid >> 5;
    const int mw = wid >> 3, nw = wid & 7;
    const int lr = lane >> 2, lc = (lane & 3) * 2;

    {   // zero g_agg
        float4* p = (float4*)g_agg;
        for (int i = blockIdx.x * 512 + tid; i < N_NODES * Dd / 4; i += gridDim.x * 512)
            p[i] = make_float4(0.f, 0.f, 0.f, 0.f);
    }
    // B image: 256 P-cols x 64 k (hi/lo)
    for (int i = tid; i < 64 * 256; i += 512) {
        int k = i >> 8, n = i & 255;
        int srow = (n < 128) ? (64 + k) : (128 + k);
        float v = We1[(size_t)srow * Hh + (n & 127)];
        __half h = __float2half_rn(v);
        uint32_t o = ioff<128>(n, k * 2);
        *(__half*)(smem + BH + o) = h;
        *(__half*)(smem + BL + o) = __float2half_rn(v - __half2float(h));
    }
    __syncthreads();

    for (int tile = blockIdx.x; tile < NT; tile += gridDim.x) {
        const int row0 = tile * 128;
        __syncthreads();
        #pragma unroll
        for (int it = 0; it < 4; it++) {
            int idx = it * 512 + tid, r = idx >> 4, c4 = idx & 15;
            int grow = row0 + r;
            float4 v = (grow < N_NODES) ? *(const float4*)(nf + (size_t)grow * Dd + c4 * 4)
                                        : make_float4(0.f, 0.f, 0.f, 0.f);
            uint2 hv, lv;
            split2(v.x, v.y, hv.x, lv.x);
            split2(v.z, v.w, hv.y, lv.y);
            uint32_t o = ioff<128>(r, c4 * 8);
            *(uint2*)(smem + AH + o) = hv;
            *(uint2*)(smem + AL + o) = lv;
        }
        __syncthreads();

        float acc[4][16];
        #pragma unroll
        for (int a = 0; a < 4; a++)
            #pragma unroll
            for (int b = 0; b < 16; b++) acc[a][b] = 0.f;

        #pragma unroll
        for (int ks = 0; ks < 64; ks += 16) {
            uint32_t ah[4][4], al[4][4], bh[4][2], bl[4][2];
            #pragma unroll
            for (int mi = 0; mi < 4; mi++) {
                uint32_t ao = ioff<128>(mw * 64 + mi * 16 + (lane & 15), ks * 2 + (lane >> 4) * 16);
                ldsm4(ah[mi], sb + AH + ao);
                ldsm4(al[mi], sb + AL + ao);
            }
            #pragma unroll
            for (int p = 0; p < 2; p++) {
                uint32_t t[4], u[4];
                uint32_t bo = ioff<128>(nw * 32 + p * 16 + (lane & 15), ks * 2 + (lane >> 4) * 16);
                ldsm4(t, sb + BH + bo);
                ldsm4(u, sb + BL + bo);
                bh[2*p][0] = t[0]; bh[2*p+1][0] = t[1]; bh[2*p][1] = t[2]; bh[2*p+1][1] = t[3];
                bl[2*p][0] = u[0]; bl[2*p+1][0] = u[1]; bl[2*p][1] = u[2]; bl[2*p+1][1] = u[3];
            }
            #pragma unroll
            for (int mi = 0; mi < 4; mi++)
                #pragma unroll
                for (int ni = 0; ni < 4; ni++) {
                    mma16816(&acc[mi][ni*4], ah[mi], bh[ni]);
                    mma16816(&acc[mi][ni*4], al[mi], bh[ni]);
                    mma16816(&acc[mi][ni*4], ah[mi], bl[ni]);
                }
        }

        #pragma unroll
        for (int mi = 0; mi < 4; mi++) {
            int r0 = row0 + mw * 64 + mi * 16 + lr;
            #pragma unroll
            for (int ni = 0; ni < 4; ni++) {
                int c = nw * 32 + ni * 8 + lc;
                if (r0 < N_NODES)
                    *(float2*)(g_P + (size_t)r0 * 256 + c) = make_float2(acc[mi][ni*4+0], acc[mi][ni*4+1]);
                if (r0 + 8 < N_NODES)
                    *(float2*)(g_P + (size_t)(r0 + 8) * 256 + c) = make_float2(acc[mi][ni*4+2], acc[mi][ni*4+3]);
            }
        }
    }
}

// ---------------- fused 2-layer MLP: dual-wavefront (two 256-thread halves) ----------------
// Each half processes its own 64-row tile stream; halves share read-only weight images
// and sync ONLY via named barriers -> phases of the two halves interleave on the SM.
template<bool EDGE>
__global__ void __launch_bounds__(512, 1)
gnn_mlp(const float* __restrict__ f0, const float* __restrict__ node_feats,
        const float* __restrict__ W1g, const float* __restrict__ b1g,
        const float* __restrict__ W2g, const float* __restrict__ b2g,
        const int* __restrict__ senders, const int* __restrict__ receivers,
        float* __restrict__ out, int M, int num_tiles)
{
    constexpr int AK  = EDGE ? 64 : 128;       // layer-1 K
    constexpr int ARB = AK * 2;                // A / B1 image row bytes
    constexpr uint32_t B1H = 1024;
    constexpr uint32_t B1SZ = 128u * ARB;      // 128 hidden-cols
    constexpr uint32_t B1L = B1H + B1SZ;
    constexpr uint32_t B2H = B1L + B1SZ;
    constexpr uint32_t B2L = B2H + 16384;
    constexpr uint32_t HALF0 = B2L + 16384;
    constexpr uint32_t ASZ   = (uint32_t)TM * ARB;          // per-half A image size (hi or lo)
    constexpr uint32_t HALF_SZ = 2 * ASZ + (uint32_t)TM * 256; // Ahi+Alo+h

    extern __shared__ unsigned char smem[];
    const uint32_t sb = smem_u32(smem);
    const int tid = threadIdx.x;
    const int half = tid >> 8;                 // 0 / 1
    const int ltid = tid & 255;                // thread within half
    const int lane = ltid & 31, nw = ltid >> 5; // 8 warps per half, nw = 0..7
    const int lr = lane >> 2, lc = (lane & 3) * 2;

    const uint32_t AHo = HALF0 + half * HALF_SZ;
    const uint32_t ALo = AHo + ASZ;
    const uint32_t HHo = ALo + ASZ;
    int* sSend = (int*)(smem + half * 512);
    int* sRecv = (int*)(smem + half * 512 + 256);

    // one-time weight images (all 512 threads)
    for (int i = tid; i < 128 * AK; i += 512) {
        int k = i >> 7, n = i & 127;
        float v = W1g[(size_t)k * Hh + n];
        __half h = __float2half_rn(v);
        uint32_t o = ioff<ARB>(n, k * 2);
        *(__half*)(smem + B1H + o) = h;
        *(__half*)(smem + B1L + o) = __float2half_rn(v - __half2float(h));
    }
    for (int i = tid; i < 64 * 128; i += 512) {
        int k = i >> 6, n = i & 63;
        float v = W2g[(size_t)k * Dd + n];
        __half h = __float2half_rn(v);
        uint32_t o = ioff<256>(n, k * 2);
        *(__half*)(smem + B2H + o) = h;
        *(__half*)(smem + B2L + o) = __float2half_rn(v - __half2float(h));
    }
    // hoisted per-thread biases
    const int cb1 = nw * 16 + lc;
    const float b1r0 = __ldg(b1g + cb1),     b1r1 = __ldg(b1g + cb1 + 1);
    const float b1r2 = __ldg(b1g + cb1 + 8), b1r3 = __ldg(b1g + cb1 + 9);
    const int cb2 = nw * 8 + lc;
    const float b2r0 = __ldg(b2g + cb2), b2r1 = __ldg(b2g + cb2 + 1);
    __syncthreads();

    #define HBAR() asm volatile("bar.sync %0, 256;" :: "r"(half + 1) : "memory")

    for (int tile = blockIdx.x * 2 + half; tile < num_tiles; tile += gridDim.x * 2) {
        const int row0 = tile * TM;
        HBAR();                                  // prev tile readers done (this half only)
        if (EDGE && ltid < TM) {
            sSend[ltid] = senders[row0 + ltid];
            sRecv[ltid] = receivers[row0 + ltid];
        }
        // ---- build A image (64 rows) ----
        if (EDGE) {
            #pragma unroll
            for (int it = 0; it < 4; it++) {
                int idx = it * 256 + ltid, r = idx >> 4, c4 = idx & 15;
                float4 v = *(const float4*)(f0 + (size_t)(row0 + r) * Dd + c4 * 4);
                uint2 hv, lv;
                split2(v.x, v.y, hv.x, lv.x);
                split2(v.z, v.w, hv.y, lv.y);
                uint32_t o = ioff<ARB>(r, c4 * 8);
                *(uint2*)(smem + AHo + o) = hv;
                *(uint2*)(smem + ALo + o) = lv;
            }
        } else {
            #pragma unroll
            for (int it = 0; it < 8; it++) {
                int idx = it * 256 + ltid, r = idx >> 5, c8 = idx & 31;
                int col = c8 * 4, grow = row0 + r;
                float4 v = make_float4(0.f, 0.f, 0.f, 0.f);
                if (grow < M)
                    v = (col < Dd) ? *(const float4*)(g_agg + (size_t)grow * Dd + col)
                                   : *(const float4*)(node_feats + (size_t)grow * Dd + col - Dd);
                uint2 hv, lv;
                split2(v.x, v.y, hv.x, lv.x);
                split2(v.z, v.w, hv.y, lv.y);
                uint32_t o = ioff<ARB>(r, c8 * 8);
                *(uint2*)(smem + AHo + o) = hv;
                *(uint2*)(smem + ALo + o) = lv;
            }
        }
        HBAR();

        // ---- layer 1: C1[64x128] = A @ W1part (3-term); warp: 64r x 16c ----
        float acc1[4][8];
        #pragma unroll
        for (int a = 0; a < 4; a++)
            #pragma unroll
            for (int b = 0; b < 8; b++) acc1[a][b] = 0.f;

        #pragma unroll
        for (int ks = 0; ks < AK; ks += 16) {
            uint32_t ah[4][4], al[4][4], bh[2][2], bl[2][2];
            #pragma unroll
            for (int mi = 0; mi < 4; mi++) {
                uint32_t ao = ioff<ARB>(mi * 16 + (lane & 15), ks * 2 + (lane >> 4) * 16);
                ldsm4(ah[mi], sb + AHo + ao);
                ldsm4(al[mi], sb + ALo + ao);
            }
            {
                uint32_t t[4], u[4];
                uint32_t bo = ioff<ARB>(nw * 16 + (lane & 15), ks * 2 + (lane >> 4) * 16);
                ldsm4(t, sb + B1H + bo);
                ldsm4(u, sb + B1L + bo);
                bh[0][0] = t[0]; bh[1][0] = t[1]; bh[0][1] = t[2]; bh[1][1] = t[3];
                bl[0][0] = u[0]; bl[1][0] = u[1]; bl[0][1] = u[2]; bl[1][1] = u[3];
            }
            #pragma unroll
            for (int mi = 0; mi < 4; mi++)
                #pragma unroll
                for (int ni = 0; ni < 2; ni++) {
                    mma16816(&acc1[mi][ni*4], ah[mi], bh[ni]);
                    mma16816(&acc1[mi][ni*4], al[mi], bh[ni]);
                    mma16816(&acc1[mi][ni*4], ah[mi], bl[ni]);
                }
        }

        // ---- epilogue 1: (+P_s+P_r) + bias1, relu, pack fp16-hi, write h ----
        #pragma unroll
        for (int mi = 0; mi < 4; mi++) {
            int r0 = mi * 16 + lr;
            float2 P0s[2], P0r[2], P1s[2], P1r[2];
            if (EDGE) {
                int s0 = sSend[r0], rv0 = sRecv[r0], s1 = sSend[r0 + 8], rv1 = sRecv[r0 + 8];
                #pragma unroll
                for (int ni = 0; ni < 2; ni++) {
                    int c0 = nw * 16 + ni * 8 + lc;
                    P0s[ni] = *(const float2*)(g_P + (size_t)s0  * 256 + c0);
                    P0r[ni] = *(const float2*)(g_P + (size_t)rv0 * 256 + 128 + c0);
                    P1s[ni] = *(const float2*)(g_P + (size_t)s1  * 256 + c0);
                    P1r[ni] = *(const float2*)(g_P + (size_t)rv1 * 256 + 128 + c0);
                }
            }
            #pragma unroll
            for (int ni = 0; ni < 2; ni++) {
                int c0 = nw * 16 + ni * 8 + lc;
                float bb0 = ni ? b1r2 : b1r0, bb1 = ni ? b1r3 : b1r1;
                float v0 = acc1[mi][ni*4+0] + bb0, v1 = acc1[mi][ni*4+1] + bb1;
                float v2 = acc1[mi][ni*4+2] + bb0, v3 = acc1[mi][ni*4+3] + bb1;
                if (EDGE) {
                    v0 += P0s[ni].x + P0r[ni].x; v1 += P0s[ni].y + P0r[ni].y;
                    v2 += P1s[ni].x + P1r[ni].x; v3 += P1s[ni].y + P1r[ni].y;
                }
                uint32_t h01 = pack_hi(fmaxf(v0, 0.f), fmaxf(v1, 0.f));
                uint32_t h23 = pack_hi(fmaxf(v2, 0.f), fmaxf(v3, 0.f));
                *(uint32_t*)(smem + HHo + ioff<256>(r0,     c0 * 2)) = h01;
                *(uint32_t*)(smem + HHo + ioff<256>(r0 + 8, c0 * 2)) = h23;
            }
        }
        HBAR();

        // ---- layer 2: C2[64x64] = h @ W2 (2-term); warp: 64r x 8c ----
        float acc2[4][4];
        #pragma unroll
        for (int a = 0; a < 4; a++)
            #pragma unroll
            for (int b = 0; b < 4; b++) acc2[a][b] = 0.f;

        #pragma unroll
        for (int ks = 0; ks < 128; ks += 16) {
            uint32_t ah[4][4], bh[2], bl[2];
            #pragma unroll
            for (int mi = 0; mi < 4; mi++) {
                uint32_t ao = ioff<256>(mi * 16 + (lane & 15), ks * 2 + (lane >> 4) * 16);
                ldsm4(ah[mi], sb + HHo + ao);
            }
            {
                uint32_t bo = ioff<256>(nw * 8 + (lane & 7), ks * 2 + ((lane >> 3) & 1) * 16);
                ldsm2(bh, sb + B2H + bo);
                ldsm2(bl, sb + B2L + bo);
            }
            #pragma unroll
            for (int mi = 0; mi < 4; mi++) {
                mma16816(acc2[mi], ah[mi], bh);
                mma16816(acc2[mi], ah[mi], bl);
            }
        }

        // ---- epilogue 2: bias2, store out, vector scatter-add ----
        #pragma unroll
        for (int mi = 0; mi < 4; mi++) {
            int r0 = mi * 16 + lr;
            int rv0 = 0, rv1 = 0;
            if (EDGE) { rv0 = sRecv[r0]; rv1 = sRecv[r0 + 8]; }
            int c = nw * 8 + lc;
            float v0 = acc2[mi][0] + b2r0, v1 = acc2[mi][1] + b2r1;
            float v2 = acc2[mi][2] + b2r0, v3 = acc2[mi][3] + b2r1;
            if (EDGE || row0 + r0 < M)
                *(float2*)(out + (size_t)(row0 + r0) * Dd + c) = make_float2(v0, v1);
            if (EDGE || row0 + r0 + 8 < M)
                *(float2*)(out + (size_t)(row0 + r0 + 8) * Dd + c) = make_float2(v2, v3);
            if (EDGE) {
                red_add_v2(g_agg + (size_t)rv0 * Dd + c, v0, v1);
                red_add_v2(g_agg + (size_t)rv1 * Dd + c, v2, v3);
            }
        }
    }
    #undef HBAR
}

// ---------------- launch ----------------
constexpr int SMEM_PRE  = 98304;
// edge: 1024 + B1 2*16384 + B2 2*16384 + 2 halves * (2*8192 + 16384)       = 132 KB
constexpr int SMEM_EDGE = 1024 + 2 * 16384 + 2 * 16384 + 2 * (2 * 8192  + 16384);
// node: 1024 + B1 2*32768 + B2 2*16384 + 2 halves * (2*16384 + 16384)      = 197 KB
constexpr int SMEM_NODE = 1024 + 2 * 32768 + 2 * 16384 + 2 * (2 * 16384 + 16384);

extern "C" void kernel_launch(void* const* d_in, const int* in_sizes, int n_in,
                              void* d_out, int out_size)
{
    const float* node_feats = (const float*)d_in[0];
    const float* edge_feats = (const float*)d_in[1];
    const float* We1 = (const float*)d_in[2];
    const float* be1 = (const float*)d_in[3];
    const float* We2 = (const float*)d_in[4];
    const float* be2 = (const float*)d_in[5];
    const float* Wn1 = (const float*)d_in[6];
    const float* bn1 = (const float*)d_in[7];
    const float* Wn2 = (const float*)d_in[8];
    const float* bn2 = (const float*)d_in[9];
    const int* senders   = (const int*)d_in[10];
    const int* receivers = (const int*)d_in[11];

    float* e_out = (float*)d_out;
    float* n_out = e_out + (size_t)N_EDGES * Dd;

    cudaFuncSetAttribute(pre_kernel, cudaFuncAttributeMaxDynamicSharedMemorySize, SMEM_PRE);
    cudaFuncSetAttribute(gnn_mlp<true>,  cudaFuncAttributeMaxDynamicSharedMemorySize, SMEM_EDGE);
    cudaFuncSetAttribute(gnn_mlp<false>, cudaFuncAttributeMaxDynamicSharedMemorySize, SMEM_NODE);

    pre_kernel<<<148, 512, SMEM_PRE>>>(node_feats, We1);

    gnn_mlp<true><<<148, 512, SMEM_EDGE>>>(
        edge_feats, node_feats, We1, be1, We2, be2,
        senders, receivers, e_out, N_EDGES, N_EDGES / TM);

    gnn_mlp<false><<<148, 512, SMEM_NODE>>>(
        nullptr, node_feats, Wn1, bn1, Wn2, bn2,
        nullptr, nullptr, n_out, N_NODES, (N_NODES + TM - 1) / TM);
}

// round 9
// speedup vs baseline: 3.8991x; 1.1727x over previous
#include <cuda_runtime.h>
#include <cuda_fp16.h>
#include <cstdint>

// ---------------- problem constants ----------------
constexpr int Dd = 64, Hh = 128, N_NODES = 50000, N_EDGES = 800000;
constexpr int TM = 64;   // rows per half-tile

// ---------------- device scratch (no cudaMalloc allowed) ----------------
__device__ float  g_agg[(size_t)N_NODES * Dd];
__device__ __half g_P[(size_t)N_NODES * 256];  // fp16: [n,0:128)=nf@W1b (sender), [128:256)=nf@W1c (recv)

// ---------------- helpers ----------------
__device__ __forceinline__ uint32_t smem_u32(const void* p) {
    uint32_t a;
    asm("{ .reg .u64 t; cvta.to.shared.u64 t, %1; cvt.u32.u64 %0, t; }" : "=r"(a) : "l"(p));
    return a;
}
__device__ __forceinline__ void ldsm4(uint32_t* r, uint32_t addr) {
    asm volatile("ldmatrix.sync.aligned.m8n8.x4.shared.b16 {%0,%1,%2,%3}, [%4];"
                 : "=r"(r[0]), "=r"(r[1]), "=r"(r[2]), "=r"(r[3]) : "r"(addr));
}
__device__ __forceinline__ void mma16816(float* c, const uint32_t* a, const uint32_t* b) {
    asm volatile("mma.sync.aligned.m16n8k16.row.col.f32.f16.f16.f32 "
                 "{%0,%1,%2,%3}, {%4,%5,%6,%7}, {%8,%9}, {%0,%1,%2,%3};"
                 : "+f"(c[0]), "+f"(c[1]), "+f"(c[2]), "+f"(c[3])
                 : "r"(a[0]), "r"(a[1]), "r"(a[2]), "r"(a[3]), "r"(b[0]), "r"(b[1]));
}
__device__ __forceinline__ void split2(float x, float y, uint32_t& hi, uint32_t& lo) {
    __half2 hp = __float22half2_rn(make_float2(x, y));
    float2 hb = __half22float2(hp);
    __half2 lp = __float22half2_rn(make_float2(x - hb.x, y - hb.y));
    hi = *(uint32_t*)&hp; lo = *(uint32_t*)&lp;
}
__device__ __forceinline__ uint32_t pack_hi(float x, float y) {
    __half2 hp = __float22half2_rn(make_float2(x, y));
    return *(uint32_t*)&hp;
}
__device__ __forceinline__ void red_add_v2(float* p, float v0, float v1) {
    asm volatile("red.global.add.v2.f32 [%0], {%1,%2};" :: "l"(p), "f"(v0), "f"(v1) : "memory");
}
template<int RB>
__device__ __forceinline__ uint32_t ioff(int r, int cb) {
    return (uint32_t)(r * RB + ((((cb >> 4) ^ (r & 7)) << 4) | (cb & 15)));
}

// ---------------- precompute kernel: P = nf @ [W1b|W1c] (fp16 out), zero g_agg ----------------
__global__ void __launch_bounds__(512, 1)
pre_kernel(const float* __restrict__ nf, const float* __restrict__ We1)
{
    constexpr uint32_t BH = 0, BL = 32768, AH = 65536, AL = 81920; // total 98304
    constexpr int NT = (N_NODES + 127) / 128;
    extern __shared__ unsigned char smem[];
    const uint32_t sb = smem_u32(smem);
    const int tid = threadIdx.x, lane = tid & 31, wid = tid >> 5;
    const int mw = wid >> 3, nw = wid & 7;
    const int lr = lane >> 2, lc = (lane & 3) * 2;

    {   // zero g_agg
        float4* p = (float4*)g_agg;
        for (int i = blockIdx.x * 512 + tid; i < N_NODES * Dd / 4; i += gridDim.x * 512)
            p[i] = make_float4(0.f, 0.f, 0.f, 0.f);
    }
    // B image: 256 P-cols x 64 k (hi/lo)
    for (int i = tid; i < 64 * 256; i += 512) {
        int k = i >> 8, n = i & 255;
        int srow = (n < 128) ? (64 + k) : (128 + k);
        float v = We1[(size_t)srow * Hh + (n & 127)];
        __half h = __float2half_rn(v);
        uint32_t o = ioff<128>(n, k * 2);
        *(__half*)(smem + BH + o) = h;
        *(__half*)(smem + BL + o) = __float2half_rn(v - __half2float(h));
    }
    __syncthreads();

    for (int tile = blockIdx.x; tile < NT; tile += gridDim.x) {
        const int row0 = tile * 128;
        __syncthreads();
        #pragma unroll
        for (int it = 0; it < 4; it++) {
            int idx = it * 512 + tid, r = idx >> 4, c4 = idx & 15;
            int grow = row0 + r;
            float4 v = (grow < N_NODES) ? *(const float4*)(nf + (size_t)grow * Dd + c4 * 4)
                                        : make_float4(0.f, 0.f, 0.f, 0.f);
            uint2 hv, lv;
            split2(v.x, v.y, hv.x, lv.x);
            split2(v.z, v.w, hv.y, lv.y);
            uint32_t o = ioff<128>(r, c4 * 8);
            *(uint2*)(smem + AH + o) = hv;
            *(uint2*)(smem + AL + o) = lv;
        }
        __syncthreads();

        float acc[4][16];
        #pragma unroll
        for (int a = 0; a < 4; a++)
            #pragma unroll
            for (int b = 0; b < 16; b++) acc[a][b] = 0.f;

        #pragma unroll
        for (int ks = 0; ks < 64; ks += 16) {
            uint32_t ah[4][4], al[4][4], bh[4][2], bl[4][2];
            #pragma unroll
            for (int mi = 0; mi < 4; mi++) {
                uint32_t ao = ioff<128>(mw * 64 + mi * 16 + (lane & 15), ks * 2 + (lane >> 4) * 16);
                ldsm4(ah[mi], sb + AH + ao);
                ldsm4(al[mi], sb + AL + ao);
            }
            #pragma unroll
            for (int p = 0; p < 2; p++) {
                uint32_t t[4], u[4];
                uint32_t bo = ioff<128>(nw * 32 + p * 16 + (lane & 15), ks * 2 + (lane >> 4) * 16);
                ldsm4(t, sb + BH + bo);
                ldsm4(u, sb + BL + bo);
                bh[2*p][0] = t[0]; bh[2*p+1][0] = t[1]; bh[2*p][1] = t[2]; bh[2*p+1][1] = t[3];
                bl[2*p][0] = u[0]; bl[2*p+1][0] = u[1]; bl[2*p][1] = u[2]; bl[2*p+1][1] = u[3];
            }
            #pragma unroll
            for (int mi = 0; mi < 4; mi++)
                #pragma unroll
                for (int ni = 0; ni < 4; ni++) {
                    mma16816(&acc[mi][ni*4], ah[mi], bh[ni]);
                    mma16816(&acc[mi][ni*4], al[mi], bh[ni]);
                    mma16816(&acc[mi][ni*4], ah[mi], bl[ni]);
                }
        }

        #pragma unroll
        for (int mi = 0; mi < 4; mi++) {
            int r0 = row0 + mw * 64 + mi * 16 + lr;
            #pragma unroll
            for (int ni = 0; ni < 4; ni++) {
                int c = nw * 32 + ni * 8 + lc;
                if (r0 < N_NODES)
                    *(uint32_t*)(g_P + (size_t)r0 * 256 + c) = pack_hi(acc[mi][ni*4+0], acc[mi][ni*4+1]);
                if (r0 + 8 < N_NODES)
                    *(uint32_t*)(g_P + (size_t)(r0 + 8) * 256 + c) = pack_hi(acc[mi][ni*4+2], acc[mi][ni*4+3]);
            }
        }
    }
}

// ---------------- fused 2-layer MLP: dual-wavefront, warp grid 2m x 4n per half ----------------
template<bool EDGE>
__global__ void __launch_bounds__(512, 1)
gnn_mlp(const float* __restrict__ f0, const float* __restrict__ node_feats,
        const float* __restrict__ W1g, const float* __restrict__ b1g,
        const float* __restrict__ W2g, const float* __restrict__ b2g,
        const int* __restrict__ senders, const int* __restrict__ receivers,
        float* __restrict__ out, int M, int num_tiles)
{
    constexpr int AK  = EDGE ? 64 : 128;       // layer-1 K
    constexpr int ARB = AK * 2;                // A / B1 image row bytes
    constexpr uint32_t B1H = 1024;
    constexpr uint32_t B1SZ = 128u * ARB;
    constexpr uint32_t B1L = B1H + B1SZ;
    constexpr uint32_t B2H = B1L + B1SZ;
    constexpr uint32_t B2L = B2H + 16384;
    constexpr uint32_t HALF0 = B2L + 16384;
    constexpr uint32_t ASZ   = (uint32_t)TM * ARB;
    constexpr uint32_t HALF_SZ = 2 * ASZ + (uint32_t)TM * 256;

    extern __shared__ unsigned char smem[];
    const uint32_t sb = smem_u32(smem);
    const int tid = threadIdx.x;
    const int half = tid >> 8, ltid = tid & 255;
    const int lane = ltid & 31, wid8 = ltid >> 5;
    const int mw2 = wid8 >> 2;                 // 0..1 -> 32-row group
    const int nw2 = wid8 & 3;                  // 0..3 -> 32-col (l1) / 16-col (l2) group
    const int lr = lane >> 2, lc = (lane & 3) * 2;

    const uint32_t AHo = HALF0 + half * HALF_SZ;
    const uint32_t ALo = AHo + ASZ;
    const uint32_t HHo = ALo + ASZ;
    int* sSend = (int*)(smem + half * 512);
    int* sRecv = (int*)(smem + half * 512 + 256);

    // one-time weight images
    for (int i = tid; i < 128 * AK; i += 512) {
        int k = i >> 7, n = i & 127;
        float v = W1g[(size_t)k * Hh + n];
        __half h = __float2half_rn(v);
        uint32_t o = ioff<ARB>(n, k * 2);
        *(__half*)(smem + B1H + o) = h;
        *(__half*)(smem + B1L + o) = __float2half_rn(v - __half2float(h));
    }
    for (int i = tid; i < 64 * 128; i += 512) {
        int k = i >> 6, n = i & 63;
        float v = W2g[(size_t)k * Dd + n];
        __half h = __float2half_rn(v);
        uint32_t o = ioff<256>(n, k * 2);
        *(__half*)(smem + B2H + o) = h;
        *(__half*)(smem + B2L + o) = __float2half_rn(v - __half2float(h));
    }
    // hoisted biases
    float b1r[8];
    #pragma unroll
    for (int ni = 0; ni < 4; ni++) {
        b1r[2*ni]   = __ldg(b1g + nw2 * 32 + ni * 8 + lc);
        b1r[2*ni+1] = __ldg(b1g + nw2 * 32 + ni * 8 + lc + 1);
    }
    float b2r[4];
    #pragma unroll
    for (int ni = 0; ni < 2; ni++) {
        b2r[2*ni]   = __ldg(b2g + nw2 * 16 + ni * 8 + lc);
        b2r[2*ni+1] = __ldg(b2g + nw2 * 16 + ni * 8 + lc + 1);
    }
    __syncthreads();

    #define HBAR() asm volatile("bar.sync %0, 256;" :: "r"(half + 1) : "memory")

    for (int tile = blockIdx.x * 2 + half; tile < num_tiles; tile += gridDim.x * 2) {
        const int row0 = tile * TM;
        HBAR();                                  // prev tile readers done (this half)
        if (EDGE && ltid < TM) {
            sSend[ltid] = senders[row0 + ltid];
            sRecv[ltid] = receivers[row0 + ltid];
        }
        // ---- build A image (64 rows) ----
        if (EDGE) {
            #pragma unroll
            for (int it = 0; it < 4; it++) {
                int idx = it * 256 + ltid, r = idx >> 4, c4 = idx & 15;
                float4 v = *(const float4*)(f0 + (size_t)(row0 + r) * Dd + c4 * 4);
                uint2 hv, lv;
                split2(v.x, v.y, hv.x, lv.x);
                split2(v.z, v.w, hv.y, lv.y);
                uint32_t o = ioff<ARB>(r, c4 * 8);
                *(uint2*)(smem + AHo + o) = hv;
                *(uint2*)(smem + ALo + o) = lv;
            }
        } else {
            #pragma unroll
            for (int it = 0; it < 8; it++) {
                int idx = it * 256 + ltid, r = idx >> 5, c8 = idx & 31;
                int col = c8 * 4, grow = row0 + r;
                float4 v = make_float4(0.f, 0.f, 0.f, 0.f);
                if (grow < M)
                    v = (col < Dd) ? *(const float4*)(g_agg + (size_t)grow * Dd + col)
                                   : *(const float4*)(node_feats + (size_t)grow * Dd + col - Dd);
                uint2 hv, lv;
                split2(v.x, v.y, hv.x, lv.x);
                split2(v.z, v.w, hv.y, lv.y);
                uint32_t o = ioff<ARB>(r, c8 * 8);
                *(uint2*)(smem + AHo + o) = hv;
                *(uint2*)(smem + ALo + o) = lv;
            }
        }
        HBAR();

        // ---- EARLY P prefetch (hidden behind layer-1 MMA) ----
        uint32_t ps[2][2][4], pr[2][2][4];
        if (EDGE) {
            #pragma unroll
            for (int mi = 0; mi < 2; mi++)
                #pragma unroll
                for (int rr = 0; rr < 2; rr++) {
                    int row = mw2 * 32 + mi * 16 + lr + rr * 8;
                    const __half* Pbs = g_P + (size_t)sSend[row] * 256;
                    const __half* Pbr = g_P + (size_t)sRecv[row] * 256 + 128;
                    #pragma unroll
                    for (int ni = 0; ni < 4; ni++) {
                        int c0 = nw2 * 32 + ni * 8 + lc;
                        ps[mi][rr][ni] = *(const uint32_t*)(Pbs + c0);
                        pr[mi][rr][ni] = *(const uint32_t*)(Pbr + c0);
                    }
                }
        }

        // ---- layer 1: warp computes 32r x 32c (3-term) ----
        float acc1[2][16];
        #pragma unroll
        for (int a = 0; a < 2; a++)
            #pragma unroll
            for (int b = 0; b < 16; b++) acc1[a][b] = 0.f;

        #pragma unroll
        for (int ks = 0; ks < AK; ks += 16) {
            uint32_t ah[2][4], al[2][4], bh[4][2], bl[4][2];
            #pragma unroll
            for (int mi = 0; mi < 2; mi++) {
                uint32_t ao = ioff<ARB>(mw2 * 32 + mi * 16 + (lane & 15), ks * 2 + (lane >> 4) * 16);
                ldsm4(ah[mi], sb + AHo + ao);
                ldsm4(al[mi], sb + ALo + ao);
            }
            #pragma unroll
            for (int p = 0; p < 2; p++) {
                uint32_t t[4], u[4];
                uint32_t bo = ioff<ARB>(nw2 * 32 + p * 16 + (lane & 15), ks * 2 + (lane >> 4) * 16);
                ldsm4(t, sb + B1H + bo);
                ldsm4(u, sb + B1L + bo);
                bh[2*p][0] = t[0]; bh[2*p+1][0] = t[1]; bh[2*p][1] = t[2]; bh[2*p+1][1] = t[3];
                bl[2*p][0] = u[0]; bl[2*p+1][0] = u[1]; bl[2*p][1] = u[2]; bl[2*p+1][1] = u[3];
            }
            #pragma unroll
            for (int mi = 0; mi < 2; mi++)
                #pragma unroll
                for (int ni = 0; ni < 4; ni++) {
                    mma16816(&acc1[mi][ni*4], ah[mi], bh[ni]);
                    mma16816(&acc1[mi][ni*4], al[mi], bh[ni]);
                    mma16816(&acc1[mi][ni*4], ah[mi], bl[ni]);
                }
        }

        // ---- epilogue 1: +P +bias1, relu, pack fp16-hi, write h ----
        #pragma unroll
        for (int mi = 0; mi < 2; mi++) {
            int r0 = mw2 * 32 + mi * 16 + lr;
            #pragma unroll
            for (int ni = 0; ni < 4; ni++) {
                int c0 = nw2 * 32 + ni * 8 + lc;
                float v0 = acc1[mi][ni*4+0] + b1r[2*ni],   v1 = acc1[mi][ni*4+1] + b1r[2*ni+1];
                float v2 = acc1[mi][ni*4+2] + b1r[2*ni],   v3 = acc1[mi][ni*4+3] + b1r[2*ni+1];
                if (EDGE) {
                    float2 fs = __half22float2(*(__half2*)&ps[mi][0][ni]);
                    float2 fr = __half22float2(*(__half2*)&pr[mi][0][ni]);
                    v0 += fs.x + fr.x; v1 += fs.y + fr.y;
                    float2 gs = __half22float2(*(__half2*)&ps[mi][1][ni]);
                    float2 gr = __half22float2(*(__half2*)&pr[mi][1][ni]);
                    v2 += gs.x + gr.x; v3 += gs.y + gr.y;
                }
                *(uint32_t*)(smem + HHo + ioff<256>(r0,     c0 * 2)) = pack_hi(fmaxf(v0,0.f), fmaxf(v1,0.f));
                *(uint32_t*)(smem + HHo + ioff<256>(r0 + 8, c0 * 2)) = pack_hi(fmaxf(v2,0.f), fmaxf(v3,0.f));
            }
        }
        HBAR();

        // ---- layer 2: warp computes 32r x 16c (2-term) ----
        float acc2[2][8];
        #pragma unroll
        for (int a = 0; a < 2; a++)
            #pragma unroll
            for (int b = 0; b < 8; b++) acc2[a][b] = 0.f;

        #pragma unroll
        for (int ks = 0; ks < 128; ks += 16) {
            uint32_t ah[2][4], bh[2][2], bl[2][2];
            #pragma unroll
            for (int mi = 0; mi < 2; mi++) {
                uint32_t ao = ioff<256>(mw2 * 32 + mi * 16 + (lane & 15), ks * 2 + (lane >> 4) * 16);
                ldsm4(ah[mi], sb + HHo + ao);
            }
            {
                uint32_t t[4], u[4];
                uint32_t bo = ioff<256>(nw2 * 16 + (lane & 15), ks * 2 + (lane >> 4) * 16);
                ldsm4(t, sb + B2H + bo);
                ldsm4(u, sb + B2L + bo);
                bh[0][0] = t[0]; bh[1][0] = t[1]; bh[0][1] = t[2]; bh[1][1] = t[3];
                bl[0][0] = u[0]; bl[1][0] = u[1]; bl[0][1] = u[2]; bl[1][1] = u[3];
            }
            #pragma unroll
            for (int mi = 0; mi < 2; mi++)
                #pragma unroll
                for (int ni = 0; ni < 2; ni++) {
                    mma16816(&acc2[mi][ni*4], ah[mi], bh[ni]);
                    mma16816(&acc2[mi][ni*4], ah[mi], bl[ni]);
                }
        }

        // ---- epilogue 2: bias2, store out, vector scatter-add ----
        #pragma unroll
        for (int mi = 0; mi < 2; mi++) {
            int r0 = mw2 * 32 + mi * 16 + lr;
            int rv0 = 0, rv1 = 0;
            if (EDGE) { rv0 = sRecv[r0]; rv1 = sRecv[r0 + 8]; }
            #pragma unroll
            for (int ni = 0; ni < 2; ni++) {
                int c = nw2 * 16 + ni * 8 + lc;
                float v0 = acc2[mi][ni*4+0] + b2r[2*ni], v1 = acc2[mi][ni*4+1] + b2r[2*ni+1];
                float v2 = acc2[mi][ni*4+2] + b2r[2*ni], v3 = acc2[mi][ni*4+3] + b2r[2*ni+1];
                if (EDGE || row0 + r0 < M)
                    *(float2*)(out + (size_t)(row0 + r0) * Dd + c) = make_float2(v0, v1);
                if (EDGE || row0 + r0 + 8 < M)
                    *(float2*)(out + (size_t)(row0 + r0 + 8) * Dd + c) = make_float2(v2, v3);
                if (EDGE) {
                    red_add_v2(g_agg + (size_t)rv0 * Dd + c, v0, v1);
                    red_add_v2(g_agg + (size_t)rv1 * Dd + c, v2, v3);
                }
            }
        }
    }
    #undef HBAR
}

// ---------------- launch ----------------
constexpr int SMEM_PRE  = 98304;
constexpr int SMEM_EDGE = 1024 + 2 * 16384 + 2 * 16384 + 2 * (2 * 8192  + 16384);
constexpr int SMEM_NODE = 1024 + 2 * 32768 + 2 * 16384 + 2 * (2 * 16384 + 16384);

extern "C" void kernel_launch(void* const* d_in, const int* in_sizes, int n_in,
                              void* d_out, int out_size)
{
    const float* node_feats = (const float*)d_in[0];
    const float* edge_feats = (const float*)d_in[1];
    const float* We1 = (const float*)d_in[2];
    const float* be1 = (const float*)d_in[3];
    const float* We2 = (const float*)d_in[4];
    const float* be2 = (const float*)d_in[5];
    const float* Wn1 = (const float*)d_in[6];
    const float* bn1 = (const float*)d_in[7];
    const float* Wn2 = (const float*)d_in[8];
    const float* bn2 = (const float*)d_in[9];
    const int* senders   = (const int*)d_in[10];
    const int* receivers = (const int*)d_in[11];

    float* e_out = (float*)d_out;
    float* n_out = e_out + (size_t)N_EDGES * Dd;

    cudaFuncSetAttribute(pre_kernel, cudaFuncAttributeMaxDynamicSharedMemorySize, SMEM_PRE);
    cudaFuncSetAttribute(gnn_mlp<true>,  cudaFuncAttributeMaxDynamicSharedMemorySize, SMEM_EDGE);
    cudaFuncSetAttribute(gnn_mlp<false>, cudaFuncAttributeMaxDynamicSharedMemorySize, SMEM_NODE);

    pre_kernel<<<148, 512, SMEM_PRE>>>(node_feats, We1);

    gnn_mlp<true><<<148, 512, SMEM_EDGE>>>(
        edge_feats, node_feats, We1, be1, We2, be2,
        senders, receivers, e_out, N_EDGES, N_EDGES / TM);

    gnn_mlp<false><<<148, 512, SMEM_NODE>>>(
        nullptr, node_feats, Wn1, bn1, Wn2, bn2,
        nullptr, nullptr, n_out, N_NODES, (N_NODES + TM - 1) / TM);
}

// round 10
// speedup vs baseline: 3.9567x; 1.0148x over previous
#include <cuda_runtime.h>
#include <cuda_fp16.h>
#include <cstdint>

// ---------------- problem constants ----------------
constexpr int Dd = 64, Hh = 128, N_NODES = 50000, N_EDGES = 800000;
constexpr int TM = 64;   // rows per half-tile

// ---------------- device scratch (no cudaMalloc allowed) ----------------
__device__ float  g_agg[(size_t)N_NODES * Dd];
__device__ __half g_P[(size_t)N_NODES * 256];  // fp16: [n,0:128)=nf@W1b (sender), [128:256)=nf@W1c (recv)

// ---------------- helpers ----------------
__device__ __forceinline__ uint32_t smem_u32(const void* p) {
    uint32_t a;
    asm("{ .reg .u64 t; cvta.to.shared.u64 t, %1; cvt.u32.u64 %0, t; }" : "=r"(a) : "l"(p));
    return a;
}
__device__ __forceinline__ void ldsm4(uint32_t* r, uint32_t addr) {
    asm volatile("ldmatrix.sync.aligned.m8n8.x4.shared.b16 {%0,%1,%2,%3}, [%4];"
                 : "=r"(r[0]), "=r"(r[1]), "=r"(r[2]), "=r"(r[3]) : "r"(addr));
}
__device__ __forceinline__ void mma16816(float* c, const uint32_t* a, const uint32_t* b) {
    asm volatile("mma.sync.aligned.m16n8k16.row.col.f32.f16.f16.f32 "
                 "{%0,%1,%2,%3}, {%4,%5,%6,%7}, {%8,%9}, {%0,%1,%2,%3};"
                 : "+f"(c[0]), "+f"(c[1]), "+f"(c[2]), "+f"(c[3])
                 : "r"(a[0]), "r"(a[1]), "r"(a[2]), "r"(a[3]), "r"(b[0]), "r"(b[1]));
}
__device__ __forceinline__ void split2(float x, float y, uint32_t& hi, uint32_t& lo) {
    __half2 hp = __float22half2_rn(make_float2(x, y));
    float2 hb = __half22float2(hp);
    __half2 lp = __float22half2_rn(make_float2(x - hb.x, y - hb.y));
    hi = *(uint32_t*)&hp; lo = *(uint32_t*)&lp;
}
__device__ __forceinline__ uint32_t pack_hi(float x, float y) {
    __half2 hp = __float22half2_rn(make_float2(x, y));
    return *(uint32_t*)&hp;
}
__device__ __forceinline__ void red_add_v2(float* p, float v0, float v1) {
    asm volatile("red.global.add.v2.f32 [%0], {%1,%2};" :: "l"(p), "f"(v0), "f"(v1) : "memory");
}
template<int RB>
__device__ __forceinline__ uint32_t ioff(int r, int cb) {
    return (uint32_t)(r * RB + ((((cb >> 4) ^ (r & 7)) << 4) | (cb & 15)));
}

// ---------------- precompute kernel: P = nf @ [W1b|W1c] (fp16 out), zero g_agg ----------------
__global__ void __launch_bounds__(512, 1)
pre_kernel(const float* __restrict__ nf, const float* __restrict__ We1)
{
    constexpr uint32_t BH = 0, BL = 32768, AH = 65536, AL = 81920; // total 98304
    constexpr int NT = (N_NODES + 127) / 128;
    extern __shared__ unsigned char smem[];
    const uint32_t sb = smem_u32(smem);
    const int tid = threadIdx.x, lane = tid & 31, wid = tid >> 5;
    const int mw = wid >> 3, nw = wid & 7;
    const int lr = lane >> 2, lc = (lane & 3) * 2;

    {   // zero g_agg
        float4* p = (float4*)g_agg;
        for (int i = blockIdx.x * 512 + tid; i < N_NODES * Dd / 4; i += gridDim.x * 512)
            p[i] = make_float4(0.f, 0.f, 0.f, 0.f);
    }
    // B image: 256 P-cols x 64 k (hi/lo)
    for (int i = tid; i < 64 * 256; i += 512) {
        int k = i >> 8, n = i & 255;
        int srow = (n < 128) ? (64 + k) : (128 + k);
        float v = We1[(size_t)srow * Hh + (n & 127)];
        __half h = __float2half_rn(v);
        uint32_t o = ioff<128>(n, k * 2);
        *(__half*)(smem + BH + o) = h;
        *(__half*)(smem + BL + o) = __float2half_rn(v - __half2float(h));
    }
    __syncthreads();

    for (int tile = blockIdx.x; tile < NT; tile += gridDim.x) {
        const int row0 = tile * 128;
        __syncthreads();
        #pragma unroll
        for (int it = 0; it < 4; it++) {
            int idx = it * 512 + tid, r = idx >> 4, c4 = idx & 15;
            int grow = row0 + r;
            float4 v = (grow < N_NODES) ? *(const float4*)(nf + (size_t)grow * Dd + c4 * 4)
                                        : make_float4(0.f, 0.f, 0.f, 0.f);
            uint2 hv, lv;
            split2(v.x, v.y, hv.x, lv.x);
            split2(v.z, v.w, hv.y, lv.y);
            uint32_t o = ioff<128>(r, c4 * 8);
            *(uint2*)(smem + AH + o) = hv;
            *(uint2*)(smem + AL + o) = lv;
        }
        __syncthreads();

        float acc[4][16];
        #pragma unroll
        for (int a = 0; a < 4; a++)
            #pragma unroll
            for (int b = 0; b < 16; b++) acc[a][b] = 0.f;

        #pragma unroll
        for (int ks = 0; ks < 64; ks += 16) {
            uint32_t ah[4][4], al[4][4], bh[4][2], bl[4][2];
            #pragma unroll
            for (int mi = 0; mi < 4; mi++) {
                uint32_t ao = ioff<128>(mw * 64 + mi * 16 + (lane & 15), ks * 2 + (lane >> 4) * 16);
                ldsm4(ah[mi], sb + AH + ao);
                ldsm4(al[mi], sb + AL + ao);
            }
            #pragma unroll
            for (int p = 0; p < 2; p++) {
                uint32_t t[4], u[4];
                uint32_t bo = ioff<128>(nw * 32 + p * 16 + (lane & 15), ks * 2 + (lane >> 4) * 16);
                ldsm4(t, sb + BH + bo);
                ldsm4(u, sb + BL + bo);
                bh[2*p][0] = t[0]; bh[2*p+1][0] = t[1]; bh[2*p][1] = t[2]; bh[2*p+1][1] = t[3];
                bl[2*p][0] = u[0]; bl[2*p+1][0] = u[1]; bl[2*p][1] = u[2]; bl[2*p+1][1] = u[3];
            }
            #pragma unroll
            for (int mi = 0; mi < 4; mi++)
                #pragma unroll
                for (int ni = 0; ni < 4; ni++) {
                    mma16816(&acc[mi][ni*4], ah[mi], bh[ni]);
                    mma16816(&acc[mi][ni*4], al[mi], bh[ni]);
                    mma16816(&acc[mi][ni*4], ah[mi], bl[ni]);
                }
        }

        #pragma unroll
        for (int mi = 0; mi < 4; mi++) {
            int r0 = row0 + mw * 64 + mi * 16 + lr;
            #pragma unroll
            for (int ni = 0; ni < 4; ni++) {
                int c = nw * 32 + ni * 8 + lc;
                if (r0 < N_NODES)
                    *(uint32_t*)(g_P + (size_t)r0 * 256 + c) = pack_hi(acc[mi][ni*4+0], acc[mi][ni*4+1]);
                if (r0 + 8 < N_NODES)
                    *(uint32_t*)(g_P + (size_t)(r0 + 8) * 256 + c) = pack_hi(acc[mi][ni*4+2], acc[mi][ni*4+3]);
            }
        }
    }
}

// ---------------- fused 2-layer MLP: dual-wavefront + cross-tile A prefetch (edge) ----------------
template<bool EDGE>
__global__ void __launch_bounds__(512, 1)
gnn_mlp(const float* __restrict__ f0, const float* __restrict__ node_feats,
        const float* __restrict__ W1g, const float* __restrict__ b1g,
        const float* __restrict__ W2g, const float* __restrict__ b2g,
        const int* __restrict__ senders, const int* __restrict__ receivers,
        float* __restrict__ out, int M, int num_tiles)
{
    constexpr int AK  = EDGE ? 64 : 128;       // layer-1 K
    constexpr int ARB = AK * 2;                // A / B1 image row bytes
    constexpr uint32_t B1H = 1024;
    constexpr uint32_t B1SZ = 128u * ARB;
    constexpr uint32_t B1L = B1H + B1SZ;
    constexpr uint32_t B2H = B1L + B1SZ;
    constexpr uint32_t B2L = B2H + 16384;
    constexpr uint32_t HALF0 = B2L + 16384;
    constexpr uint32_t ASZ   = (uint32_t)TM * ARB;
    constexpr uint32_t HALF_SZ = 2 * ASZ + (uint32_t)TM * 256;

    extern __shared__ unsigned char smem[];
    const uint32_t sb = smem_u32(smem);
    const int tid = threadIdx.x;
    const int half = tid >> 8, ltid = tid & 255;
    const int lane = ltid & 31, wid8 = ltid >> 5;
    const int mw2 = wid8 >> 2;                 // 0..1 -> 32-row group
    const int nw2 = wid8 & 3;                  // 0..3 -> 32-col (l1) / 16-col (l2) group
    const int lr = lane >> 2, lc = (lane & 3) * 2;

    const uint32_t AHo = HALF0 + half * HALF_SZ;
    const uint32_t ALo = AHo + ASZ;
    const uint32_t HHo = ALo + ASZ;
    int* sSend = (int*)(smem + half * 512);
    int* sRecv = (int*)(smem + half * 512 + 256);

    // one-time weight images
    for (int i = tid; i < 128 * AK; i += 512) {
        int k = i >> 7, n = i & 127;
        float v = W1g[(size_t)k * Hh + n];
        __half h = __float2half_rn(v);
        uint32_t o = ioff<ARB>(n, k * 2);
        *(__half*)(smem + B1H + o) = h;
        *(__half*)(smem + B1L + o) = __float2half_rn(v - __half2float(h));
    }
    for (int i = tid; i < 64 * 128; i += 512) {
        int k = i >> 6, n = i & 63;
        float v = W2g[(size_t)k * Dd + n];
        __half h = __float2half_rn(v);
        uint32_t o = ioff<256>(n, k * 2);
        *(__half*)(smem + B2H + o) = h;
        *(__half*)(smem + B2L + o) = __float2half_rn(v - __half2float(h));
    }
    // hoisted biases
    float b1r[8];
    #pragma unroll
    for (int ni = 0; ni < 4; ni++) {
        b1r[2*ni]   = __ldg(b1g + nw2 * 32 + ni * 8 + lc);
        b1r[2*ni+1] = __ldg(b1g + nw2 * 32 + ni * 8 + lc + 1);
    }
    float b2r[4];
    #pragma unroll
    for (int ni = 0; ni < 2; ni++) {
        b2r[2*ni]   = __ldg(b2g + nw2 * 16 + ni * 8 + lc);
        b2r[2*ni+1] = __ldg(b2g + nw2 * 16 + ni * 8 + lc + 1);
    }
    __syncthreads();

    #define HBAR() asm volatile("bar.sync %0, 256;" :: "r"(half + 1) : "memory")

    // ---- cross-tile prefetch state (EDGE path) ----
    float4 pA[4];
    int iS = 0, iR = 0;
    const int tstep = gridDim.x * 2;
    if (EDGE) {
        int t0 = blockIdx.x * 2 + half;
        if (t0 < num_tiles) {
            int r0 = t0 * TM;
            #pragma unroll
            for (int it = 0; it < 4; it++) {
                int idx = it * 256 + ltid, r = idx >> 4, c4 = idx & 15;
                pA[it] = *(const float4*)(f0 + (size_t)(r0 + r) * Dd + c4 * 4);
            }
            if (ltid < TM) { iS = senders[r0 + ltid]; iR = receivers[r0 + ltid]; }
        }
    }

    for (int tile = blockIdx.x * 2 + half; tile < num_tiles; tile += tstep) {
        const int row0 = tile * TM;
        HBAR();                                  // prev tile readers done (this half)
        // ---- stage indices + A image from prefetch regs (EDGE) / direct (node) ----
        if (EDGE) {
            if (ltid < TM) { sSend[ltid] = iS; sRecv[ltid] = iR; }
            #pragma unroll
            for (int it = 0; it < 4; it++) {
                int idx = it * 256 + ltid, r = idx >> 4, c4 = idx & 15;
                uint2 hv, lv;
                split2(pA[it].x, pA[it].y, hv.x, lv.x);
                split2(pA[it].z, pA[it].w, hv.y, lv.y);
                uint32_t o = ioff<ARB>(r, c4 * 8);
                *(uint2*)(smem + AHo + o) = hv;
                *(uint2*)(smem + ALo + o) = lv;
            }
        } else {
            #pragma unroll
            for (int it = 0; it < 8; it++) {
                int idx = it * 256 + ltid, r = idx >> 5, c8 = idx & 31;
                int col = c8 * 4, grow = row0 + r;
                float4 v = make_float4(0.f, 0.f, 0.f, 0.f);
                if (grow < M)
                    v = (col < Dd) ? *(const float4*)(g_agg + (size_t)grow * Dd + col)
                                   : *(const float4*)(node_feats + (size_t)grow * Dd + col - Dd);
                uint2 hv, lv;
                split2(v.x, v.y, hv.x, lv.x);
                split2(v.z, v.w, hv.y, lv.y);
                uint32_t o = ioff<ARB>(r, c8 * 8);
                *(uint2*)(smem + AHo + o) = hv;
                *(uint2*)(smem + ALo + o) = lv;
            }
        }
        HBAR();

        // ---- P prefetch (hidden behind layer-1 MMA) ----
        uint32_t ps[2][2][4], pr[2][2][4];
        if (EDGE) {
            #pragma unroll
            for (int mi = 0; mi < 2; mi++)
                #pragma unroll
                for (int rr = 0; rr < 2; rr++) {
                    int row = mw2 * 32 + mi * 16 + lr + rr * 8;
                    const __half* Pbs = g_P + (size_t)sSend[row] * 256;
                    const __half* Pbr = g_P + (size_t)sRecv[row] * 256 + 128;
                    #pragma unroll
                    for (int ni = 0; ni < 4; ni++) {
                        int c0 = nw2 * 32 + ni * 8 + lc;
                        ps[mi][rr][ni] = *(const uint32_t*)(Pbs + c0);
                        pr[mi][rr][ni] = *(const uint32_t*)(Pbr + c0);
                    }
                }
        }

        // ---- layer 1: warp computes 32r x 32c (3-term) ----
        float acc1[2][16];
        #pragma unroll
        for (int a = 0; a < 2; a++)
            #pragma unroll
            for (int b = 0; b < 16; b++) acc1[a][b] = 0.f;

        #pragma unroll
        for (int ks = 0; ks < AK; ks += 16) {
            uint32_t ah[2][4], al[2][4], bh[4][2], bl[4][2];
            #pragma unroll
            for (int mi = 0; mi < 2; mi++) {
                uint32_t ao = ioff<ARB>(mw2 * 32 + mi * 16 + (lane & 15), ks * 2 + (lane >> 4) * 16);
                ldsm4(ah[mi], sb + AHo + ao);
                ldsm4(al[mi], sb + ALo + ao);
            }
            #pragma unroll
            for (int p = 0; p < 2; p++) {
                uint32_t t[4], u[4];
                uint32_t bo = ioff<ARB>(nw2 * 32 + p * 16 + (lane & 15), ks * 2 + (lane >> 4) * 16);
                ldsm4(t, sb + B1H + bo);
                ldsm4(u, sb + B1L + bo);
                bh[2*p][0] = t[0]; bh[2*p+1][0] = t[1]; bh[2*p][1] = t[2]; bh[2*p+1][1] = t[3];
                bl[2*p][0] = u[0]; bl[2*p+1][0] = u[1]; bl[2*p][1] = u[2]; bl[2*p+1][1] = u[3];
            }
            #pragma unroll
            for (int mi = 0; mi < 2; mi++)
                #pragma unroll
                for (int ni = 0; ni < 4; ni++) {
                    mma16816(&acc1[mi][ni*4], ah[mi], bh[ni]);
                    mma16816(&acc1[mi][ni*4], al[mi], bh[ni]);
                    mma16816(&acc1[mi][ni*4], ah[mi], bl[ni]);
                }
        }

        // ---- epilogue 1: +P +bias1, relu, pack fp16-hi, write h ----
        #pragma unroll
        for (int mi = 0; mi < 2; mi++) {
            int r0 = mw2 * 32 + mi * 16 + lr;
            #pragma unroll
            for (int ni = 0; ni < 4; ni++) {
                int c0 = nw2 * 32 + ni * 8 + lc;
                float v0 = acc1[mi][ni*4+0] + b1r[2*ni],   v1 = acc1[mi][ni*4+1] + b1r[2*ni+1];
                float v2 = acc1[mi][ni*4+2] + b1r[2*ni],   v3 = acc1[mi][ni*4+3] + b1r[2*ni+1];
                if (EDGE) {
                    float2 fs = __half22float2(*(__half2*)&ps[mi][0][ni]);
                    float2 fr = __half22float2(*(__half2*)&pr[mi][0][ni]);
                    v0 += fs.x + fr.x; v1 += fs.y + fr.y;
                    float2 gs = __half22float2(*(__half2*)&ps[mi][1][ni]);
                    float2 gr = __half22float2(*(__half2*)&pr[mi][1][ni]);
                    v2 += gs.x + gr.x; v3 += gs.y + gr.y;
                }
                *(uint32_t*)(smem + HHo + ioff<256>(r0,     c0 * 2)) = pack_hi(fmaxf(v0,0.f), fmaxf(v1,0.f));
                *(uint32_t*)(smem + HHo + ioff<256>(r0 + 8, c0 * 2)) = pack_hi(fmaxf(v2,0.f), fmaxf(v3,0.f));
            }
        }
        HBAR();

        // ---- prefetch NEXT tile's A + indices (hidden behind layer-2 MMA) ----
        if (EDGE) {
            int tn = tile + tstep;
            if (tn < num_tiles) {
                int r0n = tn * TM;
                #pragma unroll
                for (int it = 0; it < 4; it++) {
                    int idx = it * 256 + ltid, r = idx >> 4, c4 = idx & 15;
                    pA[it] = *(const float4*)(f0 + (size_t)(r0n + r) * Dd + c4 * 4);
                }
                if (ltid < TM) { iS = senders[r0n + ltid]; iR = receivers[r0n + ltid]; }
            }
        }

        // ---- layer 2: warp computes 32r x 16c (2-term) ----
        float acc2[2][8];
        #pragma unroll
        for (int a = 0; a < 2; a++)
            #pragma unroll
            for (int b = 0; b < 8; b++) acc2[a][b] = 0.f;

        #pragma unroll
        for (int ks = 0; ks < 128; ks += 16) {
            uint32_t ah[2][4], bh[2][2], bl[2][2];
            #pragma unroll
            for (int mi = 0; mi < 2; mi++) {
                uint32_t ao = ioff<256>(mw2 * 32 + mi * 16 + (lane & 15), ks * 2 + (lane >> 4) * 16);
                ldsm4(ah[mi], sb + HHo + ao);
            }
            {
                uint32_t t[4], u[4];
                uint32_t bo = ioff<256>(nw2 * 16 + (lane & 15), ks * 2 + (lane >> 4) * 16);
                ldsm4(t, sb + B2H + bo);
                ldsm4(u, sb + B2L + bo);
                bh[0][0] = t[0]; bh[1][0] = t[1]; bh[0][1] = t[2]; bh[1][1] = t[3];
                bl[0][0] = u[0]; bl[1][0] = u[1]; bl[0][1] = u[2]; bl[1][1] = u[3];
            }
            #pragma unroll
            for (int mi = 0; mi < 2; mi++)
                #pragma unroll
                for (int ni = 0; ni < 2; ni++) {
                    mma16816(&acc2[mi][ni*4], ah[mi], bh[ni]);
                    mma16816(&acc2[mi][ni*4], ah[mi], bl[ni]);
                }
        }

        // ---- epilogue 2: bias2, store out, vector scatter-add ----
        #pragma unroll
        for (int mi = 0; mi < 2; mi++) {
            int r0 = mw2 * 32 + mi * 16 + lr;
            int rv0 = 0, rv1 = 0;
            if (EDGE) { rv0 = sRecv[r0]; rv1 = sRecv[r0 + 8]; }
            #pragma unroll
            for (int ni = 0; ni < 2; ni++) {
                int c = nw2 * 16 + ni * 8 + lc;
                float v0 = acc2[mi][ni*4+0] + b2r[2*ni], v1 = acc2[mi][ni*4+1] + b2r[2*ni+1];
                float v2 = acc2[mi][ni*4+2] + b2r[2*ni], v3 = acc2[mi][ni*4+3] + b2r[2*ni+1];
                if (EDGE || row0 + r0 < M)
                    *(float2*)(out + (size_t)(row0 + r0) * Dd + c) = make_float2(v0, v1);
                if (EDGE || row0 + r0 + 8 < M)
                    *(float2*)(out + (size_t)(row0 + r0 + 8) * Dd + c) = make_float2(v2, v3);
                if (EDGE) {
                    red_add_v2(g_agg + (size_t)rv0 * Dd + c, v0, v1);
                    red_add_v2(g_agg + (size_t)rv1 * Dd + c, v2, v3);
                }
            }
        }
    }
    #undef HBAR
}

// ---------------- launch ----------------
constexpr int SMEM_PRE  = 98304;
constexpr int SMEM_EDGE = 1024 + 2 * 16384 + 2 * 16384 + 2 * (2 * 8192  + 16384);
constexpr int SMEM_NODE = 1024 + 2 * 32768 + 2 * 16384 + 2 * (2 * 16384 + 16384);

extern "C" void kernel_launch(void* const* d_in, const int* in_sizes, int n_in,
                              void* d_out, int out_size)
{
    const float* node_feats = (const float*)d_in[0];
    const float* edge_feats = (const float*)d_in[1];
    const float* We1 = (const float*)d_in[2];
    const float* be1 = (const float*)d_in[3];
    const float* We2 = (const float*)d_in[4];
    const float* be2 = (const float*)d_in[5];
    const float* Wn1 = (const float*)d_in[6];
    const float* bn1 = (const float*)d_in[7];
    const float* Wn2 = (const float*)d_in[8];
    const float* bn2 = (const float*)d_in[9];
    const int* senders   = (const int*)d_in[10];
    const int* receivers = (const int*)d_in[11];

    float* e_out = (float*)d_out;
    float* n_out = e_out + (size_t)N_EDGES * Dd;

    cudaFuncSetAttribute(pre_kernel, cudaFuncAttributeMaxDynamicSharedMemorySize, SMEM_PRE);
    cudaFuncSetAttribute(gnn_mlp<true>,  cudaFuncAttributeMaxDynamicSharedMemorySize, SMEM_EDGE);
    cudaFuncSetAttribute(gnn_mlp<false>, cudaFuncAttributeMaxDynamicSharedMemorySize, SMEM_NODE);

    pre_kernel<<<148, 512, SMEM_PRE>>>(node_feats, We1);

    gnn_mlp<true><<<148, 512, SMEM_EDGE>>>(
        edge_feats, node_feats, We1, be1, We2, be2,
        senders, receivers, e_out, N_EDGES, N_EDGES / TM);

    gnn_mlp<false><<<148, 512, SMEM_NODE>>>(
        nullptr, node_feats, Wn1, bn1, Wn2, bn2,
        nullptr, nullptr, n_out, N_NODES, (N_NODES + TM - 1) / TM);
}

// round 11
// speedup vs baseline: 4.1350x; 1.0451x over previous
#include <cuda_runtime.h>
#include <cuda_fp16.h>
#include <cstdint>

// ---------------- problem constants ----------------
constexpr int Dd = 64, Hh = 128, N_NODES = 50000, N_EDGES = 800000;
constexpr int TM = 64;   // rows per half-tile

// ---------------- device scratch (no cudaMalloc allowed) ----------------
__device__ float  g_agg[(size_t)N_NODES * Dd];
__device__ __half g_P[(size_t)N_NODES * 256];  // fp16: [n,0:128)=nf@W1b (sender), [128:256)=nf@W1c (recv)

// ---------------- helpers ----------------
__device__ __forceinline__ uint32_t smem_u32(const void* p) {
    uint32_t a;
    asm("{ .reg .u64 t; cvta.to.shared.u64 t, %1; cvt.u32.u64 %0, t; }" : "=r"(a) : "l"(p));
    return a;
}
__device__ __forceinline__ void ldsm4(uint32_t* r, uint32_t addr) {
    asm volatile("ldmatrix.sync.aligned.m8n8.x4.shared.b16 {%0,%1,%2,%3}, [%4];"
                 : "=r"(r[0]), "=r"(r[1]), "=r"(r[2]), "=r"(r[3]) : "r"(addr));
}
__device__ __forceinline__ void mma16816(float* c, const uint32_t* a, const uint32_t* b) {
    asm volatile("mma.sync.aligned.m16n8k16.row.col.f32.f16.f16.f32 "
                 "{%0,%1,%2,%3}, {%4,%5,%6,%7}, {%8,%9}, {%0,%1,%2,%3};"
                 : "+f"(c[0]), "+f"(c[1]), "+f"(c[2]), "+f"(c[3])
                 : "r"(a[0]), "r"(a[1]), "r"(a[2]), "r"(a[3]), "r"(b[0]), "r"(b[1]));
}
__device__ __forceinline__ void split2(float x, float y, uint32_t& hi, uint32_t& lo) {
    __half2 hp = __float22half2_rn(make_float2(x, y));
    float2 hb = __half22float2(hp);
    __half2 lp = __float22half2_rn(make_float2(x - hb.x, y - hb.y));
    hi = *(uint32_t*)&hp; lo = *(uint32_t*)&lp;
}
__device__ __forceinline__ uint32_t pack_hi(float x, float y) {
    __half2 hp = __float22half2_rn(make_float2(x, y));
    return *(uint32_t*)&hp;
}
__device__ __forceinline__ void red_add_v2(float* p, float v0, float v1) {
    asm volatile("red.global.add.v2.f32 [%0], {%1,%2};" :: "l"(p), "f"(v0), "f"(v1) : "memory");
}
template<int RB>
__device__ __forceinline__ uint32_t ioff(int r, int cb) {
    return (uint32_t)(r * RB + ((((cb >> 4) ^ (r & 7)) << 4) | (cb & 15)));
}

// ---------------- precompute kernel: P = nf @ [W1b|W1c] (fp16 out), zero g_agg ----------------
__global__ void __launch_bounds__(512, 1)
pre_kernel(const float* __restrict__ nf, const float* __restrict__ We1)
{
    constexpr uint32_t BH = 0, BL = 32768, AH = 65536, AL = 81920; // total 98304
    constexpr int NT = (N_NODES + 127) / 128;
    extern __shared__ unsigned char smem[];
    const uint32_t sb = smem_u32(smem);
    const int tid = threadIdx.x, lane = tid & 31, wid = tid >> 5;
    const int mw = wid >> 3, nw = wid & 7;
    const int lr = lane >> 2, lc = (lane & 3) * 2;

    {   // zero g_agg
        float4* p = (float4*)g_agg;
        for (int i = blockIdx.x * 512 + tid; i < N_NODES * Dd / 4; i += gridDim.x * 512)
            p[i] = make_float4(0.f, 0.f, 0.f, 0.f);
    }
    // B image: 256 P-cols x 64 k (hi/lo)
    for (int i = tid; i < 64 * 256; i += 512) {
        int k = i >> 8, n = i & 255;
        int srow = (n < 128) ? (64 + k) : (128 + k);
        float v = We1[(size_t)srow * Hh + (n & 127)];
        __half h = __float2half_rn(v);
        uint32_t o = ioff<128>(n, k * 2);
        *(__half*)(smem + BH + o) = h;
        *(__half*)(smem + BL + o) = __float2half_rn(v - __half2float(h));
    }
    __syncthreads();

    for (int tile = blockIdx.x; tile < NT; tile += gridDim.x) {
        const int row0 = tile * 128;
        __syncthreads();
        #pragma unroll
        for (int it = 0; it < 4; it++) {
            int idx = it * 512 + tid, r = idx >> 4, c4 = idx & 15;
            int grow = row0 + r;
            float4 v = (grow < N_NODES) ? *(const float4*)(nf + (size_t)grow * Dd + c4 * 4)
                                        : make_float4(0.f, 0.f, 0.f, 0.f);
            uint2 hv, lv;
            split2(v.x, v.y, hv.x, lv.x);
            split2(v.z, v.w, hv.y, lv.y);
            uint32_t o = ioff<128>(r, c4 * 8);
            *(uint2*)(smem + AH + o) = hv;
            *(uint2*)(smem + AL + o) = lv;
        }
        __syncthreads();

        float acc[4][16];
        #pragma unroll
        for (int a = 0; a < 4; a++)
            #pragma unroll
            for (int b = 0; b < 16; b++) acc[a][b] = 0.f;

        #pragma unroll
        for (int ks = 0; ks < 64; ks += 16) {
            uint32_t ah[4][4], al[4][4], bh[4][2], bl[4][2];
            #pragma unroll
            for (int mi = 0; mi < 4; mi++) {
                uint32_t ao = ioff<128>(mw * 64 + mi * 16 + (lane & 15), ks * 2 + (lane >> 4) * 16);
                ldsm4(ah[mi], sb + AH + ao);
                ldsm4(al[mi], sb + AL + ao);
            }
            #pragma unroll
            for (int p = 0; p < 2; p++) {
                uint32_t t[4], u[4];
                uint32_t bo = ioff<128>(nw * 32 + p * 16 + (lane & 15), ks * 2 + (lane >> 4) * 16);
                ldsm4(t, sb + BH + bo);
                ldsm4(u, sb + BL + bo);
                bh[2*p][0] = t[0]; bh[2*p+1][0] = t[1]; bh[2*p][1] = t[2]; bh[2*p+1][1] = t[3];
                bl[2*p][0] = u[0]; bl[2*p+1][0] = u[1]; bl[2*p][1] = u[2]; bl[2*p+1][1] = u[3];
            }
            #pragma unroll
            for (int mi = 0; mi < 4; mi++)
                #pragma unroll
                for (int ni = 0; ni < 4; ni++) {
                    mma16816(&acc[mi][ni*4], ah[mi], bh[ni]);
                    mma16816(&acc[mi][ni*4], al[mi], bh[ni]);
                    mma16816(&acc[mi][ni*4], ah[mi], bl[ni]);
                }
        }

        #pragma unroll
        for (int mi = 0; mi < 4; mi++) {
            int r0 = row0 + mw * 64 + mi * 16 + lr;
            #pragma unroll
            for (int ni = 0; ni < 4; ni++) {
                int c = nw * 32 + ni * 8 + lc;
                if (r0 < N_NODES)
                    *(uint32_t*)(g_P + (size_t)r0 * 256 + c) = pack_hi(acc[mi][ni*4+0], acc[mi][ni*4+1]);
                if (r0 + 8 < N_NODES)
                    *(uint32_t*)(g_P + (size_t)(r0 + 8) * 256 + c) = pack_hi(acc[mi][ni*4+2], acc[mi][ni*4+3]);
            }
        }
    }
}

// ---------------- fused 2-layer MLP: dual-wavefront, EDGE uses 2-term layer-1 ----------------
template<bool EDGE>
__global__ void __launch_bounds__(512, 1)
gnn_mlp(const float* __restrict__ f0, const float* __restrict__ node_feats,
        const float* __restrict__ W1g, const float* __restrict__ b1g,
        const float* __restrict__ W2g, const float* __restrict__ b2g,
        const int* __restrict__ senders, const int* __restrict__ receivers,
        float* __restrict__ out, int M, int num_tiles)
{
    constexpr int AK  = EDGE ? 64 : 128;       // layer-1 K
    constexpr int ARB = AK * 2;                // A / B1 image row bytes
    constexpr uint32_t B1H = 1024;
    constexpr uint32_t B1SZ = 128u * ARB;
    constexpr uint32_t B1L = B1H + B1SZ;
    constexpr uint32_t B2H = B1L + B1SZ;
    constexpr uint32_t B2L = B2H + 16384;
    constexpr uint32_t HALF0 = B2L + 16384;
    constexpr uint32_t ASZ   = (uint32_t)TM * ARB;
    // EDGE: only A-hi image; NODE: A-hi + A-lo
    constexpr uint32_t NAIMG = EDGE ? 1u : 2u;
    constexpr uint32_t HALF_SZ = NAIMG * ASZ + (uint32_t)TM * 256;

    extern __shared__ unsigned char smem[];
    const uint32_t sb = smem_u32(smem);
    const int tid = threadIdx.x;
    const int half = tid >> 8, ltid = tid & 255;
    const int lane = ltid & 31, wid8 = ltid >> 5;
    const int mw2 = wid8 >> 2;                 // 0..1 -> 32-row group
    const int nw2 = wid8 & 3;                  // 0..3 -> 32-col (l1) / 16-col (l2) group
    const int lr = lane >> 2, lc = (lane & 3) * 2;

    const uint32_t AHo = HALF0 + half * HALF_SZ;
    const uint32_t ALo = AHo + ASZ;                    // node only
    const uint32_t HHo = AHo + NAIMG * ASZ;
    int* sSend = (int*)(smem + half * 512);
    int* sRecv = (int*)(smem + half * 512 + 256);

    // one-time weight images
    for (int i = tid; i < 128 * AK; i += 512) {
        int k = i >> 7, n = i & 127;
        float v = W1g[(size_t)k * Hh + n];
        __half h = __float2half_rn(v);
        uint32_t o = ioff<ARB>(n, k * 2);
        *(__half*)(smem + B1H + o) = h;
        *(__half*)(smem + B1L + o) = __float2half_rn(v - __half2float(h));
    }
    for (int i = tid; i < 64 * 128; i += 512) {
        int k = i >> 6, n = i & 63;
        float v = W2g[(size_t)k * Dd + n];
        __half h = __float2half_rn(v);
        uint32_t o = ioff<256>(n, k * 2);
        *(__half*)(smem + B2H + o) = h;
        *(__half*)(smem + B2L + o) = __float2half_rn(v - __half2float(h));
    }
    // hoisted biases
    float b1r[8];
    #pragma unroll
    for (int ni = 0; ni < 4; ni++) {
        b1r[2*ni]   = __ldg(b1g + nw2 * 32 + ni * 8 + lc);
        b1r[2*ni+1] = __ldg(b1g + nw2 * 32 + ni * 8 + lc + 1);
    }
    float b2r[4];
    #pragma unroll
    for (int ni = 0; ni < 2; ni++) {
        b2r[2*ni]   = __ldg(b2g + nw2 * 16 + ni * 8 + lc);
        b2r[2*ni+1] = __ldg(b2g + nw2 * 16 + ni * 8 + lc + 1);
    }
    __syncthreads();

    #define HBAR() asm volatile("bar.sync %0, 256;" :: "r"(half + 1) : "memory")

    // ---- cross-tile prefetch state (EDGE path) ----
    float4 pA[4];
    int iS = 0, iR = 0;
    const int tstep = gridDim.x * 2;
    if (EDGE) {
        int t0 = blockIdx.x * 2 + half;
        if (t0 < num_tiles) {
            int r0 = t0 * TM;
            #pragma unroll
            for (int it = 0; it < 4; it++) {
                int idx = it * 256 + ltid, r = idx >> 4, c4 = idx & 15;
                pA[it] = *(const float4*)(f0 + (size_t)(r0 + r) * Dd + c4 * 4);
            }
            if (ltid < TM) { iS = senders[r0 + ltid]; iR = receivers[r0 + ltid]; }
        }
    }

    for (int tile = blockIdx.x * 2 + half; tile < num_tiles; tile += tstep) {
        const int row0 = tile * TM;
        HBAR();                                  // prev tile readers done (this half)
        // ---- stage indices + A image ----
        if (EDGE) {
            if (ltid < TM) { sSend[ltid] = iS; sRecv[ltid] = iR; }
            #pragma unroll
            for (int it = 0; it < 4; it++) {
                int idx = it * 256 + ltid, r = idx >> 4, c4 = idx & 15;
                uint2 hv;
                hv.x = pack_hi(pA[it].x, pA[it].y);
                hv.y = pack_hi(pA[it].z, pA[it].w);
                *(uint2*)(smem + AHo + ioff<ARB>(r, c4 * 8)) = hv;
            }
        } else {
            #pragma unroll
            for (int it = 0; it < 8; it++) {
                int idx = it * 256 + ltid, r = idx >> 5, c8 = idx & 31;
                int col = c8 * 4, grow = row0 + r;
                float4 v = make_float4(0.f, 0.f, 0.f, 0.f);
                if (grow < M)
                    v = (col < Dd) ? *(const float4*)(g_agg + (size_t)grow * Dd + col)
                                   : *(const float4*)(node_feats + (size_t)grow * Dd + col - Dd);
                uint2 hv, lv;
                split2(v.x, v.y, hv.x, lv.x);
                split2(v.z, v.w, hv.y, lv.y);
                uint32_t o = ioff<ARB>(r, c8 * 8);
                *(uint2*)(smem + AHo + o) = hv;
                *(uint2*)(smem + ALo + o) = lv;
            }
        }
        HBAR();

        // ---- P prefetch (hidden behind layer-1 MMA) ----
        uint32_t ps[2][2][4], pr[2][2][4];
        if (EDGE) {
            #pragma unroll
            for (int mi = 0; mi < 2; mi++)
                #pragma unroll
                for (int rr = 0; rr < 2; rr++) {
                    int row = mw2 * 32 + mi * 16 + lr + rr * 8;
                    const __half* Pbs = g_P + (size_t)sSend[row] * 256;
                    const __half* Pbr = g_P + (size_t)sRecv[row] * 256 + 128;
                    #pragma unroll
                    for (int ni = 0; ni < 4; ni++) {
                        int c0 = nw2 * 32 + ni * 8 + lc;
                        ps[mi][rr][ni] = *(const uint32_t*)(Pbs + c0);
                        pr[mi][rr][ni] = *(const uint32_t*)(Pbr + c0);
                    }
                }
        }

        // ---- layer 1: warp computes 32r x 32c ----
        // EDGE: 2-term Ah*(B1h+B1l); NODE: 3-term (A hi/lo)
        float acc1[2][16];
        #pragma unroll
        for (int a = 0; a < 2; a++)
            #pragma unroll
            for (int b = 0; b < 16; b++) acc1[a][b] = 0.f;

        #pragma unroll
        for (int ks = 0; ks < AK; ks += 16) {
            uint32_t ah[2][4], al[2][4], bh[4][2], bl[4][2];
            #pragma unroll
            for (int mi = 0; mi < 2; mi++) {
                uint32_t ao = ioff<ARB>(mw2 * 32 + mi * 16 + (lane & 15), ks * 2 + (lane >> 4) * 16);
                ldsm4(ah[mi], sb + AHo + ao);
                if (!EDGE) ldsm4(al[mi], sb + ALo + ao);
            }
            #pragma unroll
            for (int p = 0; p < 2; p++) {
                uint32_t t[4], u[4];
                uint32_t bo = ioff<ARB>(nw2 * 32 + p * 16 + (lane & 15), ks * 2 + (lane >> 4) * 16);
                ldsm4(t, sb + B1H + bo);
                ldsm4(u, sb + B1L + bo);
                bh[2*p][0] = t[0]; bh[2*p+1][0] = t[1]; bh[2*p][1] = t[2]; bh[2*p+1][1] = t[3];
                bl[2*p][0] = u[0]; bl[2*p+1][0] = u[1]; bl[2*p][1] = u[2]; bl[2*p+1][1] = u[3];
            }
            #pragma unroll
            for (int mi = 0; mi < 2; mi++)
                #pragma unroll
                for (int ni = 0; ni < 4; ni++) {
                    mma16816(&acc1[mi][ni*4], ah[mi], bh[ni]);
                    mma16816(&acc1[mi][ni*4], ah[mi], bl[ni]);
                    if (!EDGE) mma16816(&acc1[mi][ni*4], al[mi], bh[ni]);
                }
        }

        // ---- epilogue 1: +P +bias1, relu, pack fp16-hi, write h ----
        #pragma unroll
        for (int mi = 0; mi < 2; mi++) {
            int r0 = mw2 * 32 + mi * 16 + lr;
            #pragma unroll
            for (int ni = 0; ni < 4; ni++) {
                int c0 = nw2 * 32 + ni * 8 + lc;
                float v0 = acc1[mi][ni*4+0] + b1r[2*ni],   v1 = acc1[mi][ni*4+1] + b1r[2*ni+1];
                float v2 = acc1[mi][ni*4+2] + b1r[2*ni],   v3 = acc1[mi][ni*4+3] + b1r[2*ni+1];
                if (EDGE) {
                    float2 fs = __half22float2(*(__half2*)&ps[mi][0][ni]);
                    float2 fr = __half22float2(*(__half2*)&pr[mi][0][ni]);
                    v0 += fs.x + fr.x; v1 += fs.y + fr.y;
                    float2 gs = __half22float2(*(__half2*)&ps[mi][1][ni]);
                    float2 gr = __half22float2(*(__half2*)&pr[mi][1][ni]);
                    v2 += gs.x + gr.x; v3 += gs.y + gr.y;
                }
                *(uint32_t*)(smem + HHo + ioff<256>(r0,     c0 * 2)) = pack_hi(fmaxf(v0,0.f), fmaxf(v1,0.f));
                *(uint32_t*)(smem + HHo + ioff<256>(r0 + 8, c0 * 2)) = pack_hi(fmaxf(v2,0.f), fmaxf(v3,0.f));
            }
        }
        HBAR();

        // ---- prefetch NEXT tile's A + indices (hidden behind layer-2 MMA) ----
        if (EDGE) {
            int tn = tile + tstep;
            if (tn < num_tiles) {
                int r0n = tn * TM;
                #pragma unroll
                for (int it = 0; it < 4; it++) {
                    int idx = it * 256 + ltid, r = idx >> 4, c4 = idx & 15;
                    pA[it] = *(const float4*)(f0 + (size_t)(r0n + r) * Dd + c4 * 4);
                }
                if (ltid < TM) { iS = senders[r0n + ltid]; iR = receivers[r0n + ltid]; }
            }
        }

        // ---- layer 2: warp computes 32r x 16c (2-term) ----
        float acc2[2][8];
        #pragma unroll
        for (int a = 0; a < 2; a++)
            #pragma unroll
            for (int b = 0; b < 8; b++) acc2[a][b] = 0.f;

        #pragma unroll
        for (int ks = 0; ks < 128; ks += 16) {
            uint32_t ah[2][4], bh[2][2], bl[2][2];
            #pragma unroll
            for (int mi = 0; mi < 2; mi++) {
                uint32_t ao = ioff<256>(mw2 * 32 + mi * 16 + (lane & 15), ks * 2 + (lane >> 4) * 16);
                ldsm4(ah[mi], sb + HHo + ao);
            }
            {
                uint32_t t[4], u[4];
                uint32_t bo = ioff<256>(nw2 * 16 + (lane & 15), ks * 2 + (lane >> 4) * 16);
                ldsm4(t, sb + B2H + bo);
                ldsm4(u, sb + B2L + bo);
                bh[0][0] = t[0]; bh[1][0] = t[1]; bh[0][1] = t[2]; bh[1][1] = t[3];
                bl[0][0] = u[0]; bl[1][0] = u[1]; bl[0][1] = u[2]; bl[1][1] = u[3];
            }
            #pragma unroll
            for (int mi = 0; mi < 2; mi++)
                #pragma unroll
                for (int ni = 0; ni < 2; ni++) {
                    mma16816(&acc2[mi][ni*4], ah[mi], bh[ni]);
                    mma16816(&acc2[mi][ni*4], ah[mi], bl[ni]);
                }
        }

        // ---- epilogue 2: bias2, store out, vector scatter-add ----
        #pragma unroll
        for (int mi = 0; mi < 2; mi++) {
            int r0 = mw2 * 32 + mi * 16 + lr;
            int rv0 = 0, rv1 = 0;
            if (EDGE) { rv0 = sRecv[r0]; rv1 = sRecv[r0 + 8]; }
            #pragma unroll
            for (int ni = 0; ni < 2; ni++) {
                int c = nw2 * 16 + ni * 8 + lc;
                float v0 = acc2[mi][ni*4+0] + b2r[2*ni], v1 = acc2[mi][ni*4+1] + b2r[2*ni+1];
                float v2 = acc2[mi][ni*4+2] + b2r[2*ni], v3 = acc2[mi][ni*4+3] + b2r[2*ni+1];
                if (EDGE || row0 + r0 < M)
                    *(float2*)(out + (size_t)(row0 + r0) * Dd + c) = make_float2(v0, v1);
                if (EDGE || row0 + r0 + 8 < M)
                    *(float2*)(out + (size_t)(row0 + r0 + 8) * Dd + c) = make_float2(v2, v3);
                if (EDGE) {
                    red_add_v2(g_agg + (size_t)rv0 * Dd + c, v0, v1);
                    red_add_v2(g_agg + (size_t)rv1 * Dd + c, v2, v3);
                }
            }
        }
    }
    #undef HBAR
}

// ---------------- launch ----------------
constexpr int SMEM_PRE  = 98304;
constexpr int SMEM_EDGE = 1024 + 2 * 16384 + 2 * 16384 + 2 * (8192 + 16384);       // 115712
constexpr int SMEM_NODE = 1024 + 2 * 32768 + 2 * 16384 + 2 * (2 * 16384 + 16384);  // 197632

extern "C" void kernel_launch(void* const* d_in, const int* in_sizes, int n_in,
                              void* d_out, int out_size)
{
    const float* node_feats = (const float*)d_in[0];
    const float* edge_feats = (const float*)d_in[1];
    const float* We1 = (const float*)d_in[2];
    const float* be1 = (const float*)d_in[3];
    const float* We2 = (const float*)d_in[4];
    const float* be2 = (const float*)d_in[5];
    const float* Wn1 = (const float*)d_in[6];
    const float* bn1 = (const float*)d_in[7];
    const float* Wn2 = (const float*)d_in[8];
    const float* bn2 = (const float*)d_in[9];
    const int* senders   = (const int*)d_in[10];
    const int* receivers = (const int*)d_in[11];

    float* e_out = (float*)d_out;
    float* n_out = e_out + (size_t)N_EDGES * Dd;

    cudaFuncSetAttribute(pre_kernel, cudaFuncAttributeMaxDynamicSharedMemorySize, SMEM_PRE);
    cudaFuncSetAttribute(gnn_mlp<true>,  cudaFuncAttributeMaxDynamicSharedMemorySize, SMEM_EDGE);
    cudaFuncSetAttribute(gnn_mlp<false>, cudaFuncAttributeMaxDynamicSharedMemorySize, SMEM_NODE);

    pre_kernel<<<148, 512, SMEM_PRE>>>(node_feats, We1);

    gnn_mlp<true><<<148, 512, SMEM_EDGE>>>(
        edge_feats, node_feats, We1, be1, We2, be2,
        senders, receivers, e_out, N_EDGES, N_EDGES / TM);

    gnn_mlp<false><<<148, 512, SMEM_NODE>>>(
        nullptr, node_feats, Wn1, bn1, Wn2, bn2,
        nullptr, nullptr, n_out, N_NODES, (N_NODES + TM - 1) / TM);
}

// round 12
// speedup vs baseline: 4.2722x; 1.0332x over previous
#include <cuda_runtime.h>
#include <cuda_fp16.h>
#include <cstdint>

// ---------------- problem constants ----------------
constexpr int Dd = 64, Hh = 128, N_NODES = 50000, N_EDGES = 800000;
constexpr int TM = 64;   // rows per half-tile

// ---------------- device scratch (no cudaMalloc allowed) ----------------
__device__ float  g_agg[(size_t)N_NODES * Dd];
__device__ __half g_P[(size_t)N_NODES * 256];  // fp16: [n,0:128)=nf@W1b (sender), [128:256)=nf@W1c (recv)

// ---------------- helpers ----------------
__device__ __forceinline__ uint32_t smem_u32(const void* p) {
    uint32_t a;
    asm("{ .reg .u64 t; cvta.to.shared.u64 t, %1; cvt.u32.u64 %0, t; }" : "=r"(a) : "l"(p));
    return a;
}
__device__ __forceinline__ void ldsm4(uint32_t* r, uint32_t addr) {
    asm volatile("ldmatrix.sync.aligned.m8n8.x4.shared.b16 {%0,%1,%2,%3}, [%4];"
                 : "=r"(r[0]), "=r"(r[1]), "=r"(r[2]), "=r"(r[3]) : "r"(addr));
}
__device__ __forceinline__ void mma16816(float* c, const uint32_t* a, const uint32_t* b) {
    asm volatile("mma.sync.aligned.m16n8k16.row.col.f32.f16.f16.f32 "
                 "{%0,%1,%2,%3}, {%4,%5,%6,%7}, {%8,%9}, {%0,%1,%2,%3};"
                 : "+f"(c[0]), "+f"(c[1]), "+f"(c[2]), "+f"(c[3])
                 : "r"(a[0]), "r"(a[1]), "r"(a[2]), "r"(a[3]), "r"(b[0]), "r"(b[1]));
}
__device__ __forceinline__ void split2(float x, float y, uint32_t& hi, uint32_t& lo) {
    __half2 hp = __float22half2_rn(make_float2(x, y));
    float2 hb = __half22float2(hp);
    __half2 lp = __float22half2_rn(make_float2(x - hb.x, y - hb.y));
    hi = *(uint32_t*)&hp; lo = *(uint32_t*)&lp;
}
__device__ __forceinline__ uint32_t pack_hi(float x, float y) {
    __half2 hp = __float22half2_rn(make_float2(x, y));
    return *(uint32_t*)&hp;
}
__device__ __forceinline__ void red_add_v2(float* p, float v0, float v1) {
    asm volatile("red.global.add.v2.f32 [%0], {%1,%2};" :: "l"(p), "f"(v0), "f"(v1) : "memory");
}
// streaming (evict-first) store of 8 bytes
__device__ __forceinline__ void stcs_v2(float* p, float v0, float v1) {
    asm volatile("st.global.cs.v2.f32 [%0], {%1,%2};" :: "l"(p), "f"(v0), "f"(v1) : "memory");
}
__device__ __forceinline__ float4 ldcs_v4(const float* p) {
    float4 v;
    asm volatile("ld.global.cs.v4.f32 {%0,%1,%2,%3}, [%4];"
                 : "=f"(v.x), "=f"(v.y), "=f"(v.z), "=f"(v.w) : "l"(p));
    return v;
}
template<int RB>
__device__ __forceinline__ uint32_t ioff(int r, int cb) {
    return (uint32_t)(r * RB + ((((cb >> 4) ^ (r & 7)) << 4) | (cb & 15)));
}

// ---------------- precompute kernel: P = nf @ [W1b|W1c] (fp16 out), zero g_agg ----------------
__global__ void __launch_bounds__(512, 1)
pre_kernel(const float* __restrict__ nf, const float* __restrict__ We1)
{
    constexpr uint32_t BH = 0, BL = 32768, AH = 65536, AL = 81920; // total 98304
    constexpr int NT = (N_NODES + 127) / 128;
    extern __shared__ unsigned char smem[];
    const uint32_t sb = smem_u32(smem);
    const int tid = threadIdx.x, lane = tid & 31, wid = tid >> 5;
    const int mw = wid >> 3, nw = wid & 7;
    const int lr = lane >> 2, lc = (lane & 3) * 2;

    {   // zero g_agg
        float4* p = (float4*)g_agg;
        for (int i = blockIdx.x * 512 + tid; i < N_NODES * Dd / 4; i += gridDim.x * 512)
            p[i] = make_float4(0.f, 0.f, 0.f, 0.f);
    }
    // B image: 256 P-cols x 64 k (hi/lo)
    for (int i = tid; i < 64 * 256; i += 512) {
        int k = i >> 8, n = i & 255;
        int srow = (n < 128) ? (64 + k) : (128 + k);
        float v = We1[(size_t)srow * Hh + (n & 127)];
        __half h = __float2half_rn(v);
        uint32_t o = ioff<128>(n, k * 2);
        *(__half*)(smem + BH + o) = h;
        *(__half*)(smem + BL + o) = __float2half_rn(v - __half2float(h));
    }
    __syncthreads();

    for (int tile = blockIdx.x; tile < NT; tile += gridDim.x) {
        const int row0 = tile * 128;
        __syncthreads();
        #pragma unroll
        for (int it = 0; it < 4; it++) {
            int idx = it * 512 + tid, r = idx >> 4, c4 = idx & 15;
            int grow = row0 + r;
            float4 v = (grow < N_NODES) ? *(const float4*)(nf + (size_t)grow * Dd + c4 * 4)
                                        : make_float4(0.f, 0.f, 0.f, 0.f);
            uint2 hv, lv;
            split2(v.x, v.y, hv.x, lv.x);
            split2(v.z, v.w, hv.y, lv.y);
            uint32_t o = ioff<128>(r, c4 * 8);
            *(uint2*)(smem + AH + o) = hv;
            *(uint2*)(smem + AL + o) = lv;
        }
        __syncthreads();

        float acc[4][16];
        #pragma unroll
        for (int a = 0; a < 4; a++)
            #pragma unroll
            for (int b = 0; b < 16; b++) acc[a][b] = 0.f;

        #pragma unroll
        for (int ks = 0; ks < 64; ks += 16) {
            uint32_t ah[4][4], al[4][4], bh[4][2], bl[4][2];
            #pragma unroll
            for (int mi = 0; mi < 4; mi++) {
                uint32_t ao = ioff<128>(mw * 64 + mi * 16 + (lane & 15), ks * 2 + (lane >> 4) * 16);
                ldsm4(ah[mi], sb + AH + ao);
                ldsm4(al[mi], sb + AL + ao);
            }
            #pragma unroll
            for (int p = 0; p < 2; p++) {
                uint32_t t[4], u[4];
                uint32_t bo = ioff<128>(nw * 32 + p * 16 + (lane & 15), ks * 2 + (lane >> 4) * 16);
                ldsm4(t, sb + BH + bo);
                ldsm4(u, sb + BL + bo);
                bh[2*p][0] = t[0]; bh[2*p+1][0] = t[1]; bh[2*p][1] = t[2]; bh[2*p+1][1] = t[3];
                bl[2*p][0] = u[0]; bl[2*p+1][0] = u[1]; bl[2*p][1] = u[2]; bl[2*p+1][1] = u[3];
            }
            #pragma unroll
            for (int mi = 0; mi < 4; mi++)
                #pragma unroll
                for (int ni = 0; ni < 4; ni++) {
                    mma16816(&acc[mi][ni*4], ah[mi], bh[ni]);
                    mma16816(&acc[mi][ni*4], al[mi], bh[ni]);
                    mma16816(&acc[mi][ni*4], ah[mi], bl[ni]);
                }
        }

        #pragma unroll
        for (int mi = 0; mi < 4; mi++) {
            int r0 = row0 + mw * 64 + mi * 16 + lr;
            #pragma unroll
            for (int ni = 0; ni < 4; ni++) {
                int c = nw * 32 + ni * 8 + lc;
                if (r0 < N_NODES)
                    *(uint32_t*)(g_P + (size_t)r0 * 256 + c) = pack_hi(acc[mi][ni*4+0], acc[mi][ni*4+1]);
                if (r0 + 8 < N_NODES)
                    *(uint32_t*)(g_P + (size_t)(r0 + 8) * 256 + c) = pack_hi(acc[mi][ni*4+2], acc[mi][ni*4+3]);
            }
        }
    }
}

// ---------------- fused 2-layer MLP: dual-wavefront, streaming cache hints ----------------
template<bool EDGE>
__global__ void __launch_bounds__(512, 1)
gnn_mlp(const float* __restrict__ f0, const float* __restrict__ node_feats,
        const float* __restrict__ W1g, const float* __restrict__ b1g,
        const float* __restrict__ W2g, const float* __restrict__ b2g,
        const int* __restrict__ senders, const int* __restrict__ receivers,
        float* __restrict__ out, int M, int num_tiles)
{
    constexpr int AK  = EDGE ? 64 : 128;       // layer-1 K
    constexpr int ARB = AK * 2;                // A / B1 image row bytes
    constexpr uint32_t B1H = 1024;
    constexpr uint32_t B1SZ = 128u * ARB;
    constexpr uint32_t B1L = B1H + B1SZ;
    constexpr uint32_t B2H = B1L + B1SZ;
    constexpr uint32_t B2L = B2H + 16384;
    constexpr uint32_t HALF0 = B2L + 16384;
    constexpr uint32_t ASZ   = (uint32_t)TM * ARB;
    constexpr uint32_t NAIMG = EDGE ? 1u : 2u;
    constexpr uint32_t HALF_SZ = NAIMG * ASZ + (uint32_t)TM * 256;

    extern __shared__ unsigned char smem[];
    const uint32_t sb = smem_u32(smem);
    const int tid = threadIdx.x;
    const int half = tid >> 8, ltid = tid & 255;
    const int lane = ltid & 31, wid8 = ltid >> 5;
    const int mw2 = wid8 >> 2;
    const int nw2 = wid8 & 3;
    const int lr = lane >> 2, lc = (lane & 3) * 2;

    const uint32_t AHo = HALF0 + half * HALF_SZ;
    const uint32_t ALo = AHo + ASZ;                    // node only
    const uint32_t HHo = AHo + NAIMG * ASZ;
    int* sSend = (int*)(smem + half * 512);
    int* sRecv = (int*)(smem + half * 512 + 256);

    // one-time weight images
    for (int i = tid; i < 128 * AK; i += 512) {
        int k = i >> 7, n = i & 127;
        float v = W1g[(size_t)k * Hh + n];
        __half h = __float2half_rn(v);
        uint32_t o = ioff<ARB>(n, k * 2);
        *(__half*)(smem + B1H + o) = h;
        *(__half*)(smem + B1L + o) = __float2half_rn(v - __half2float(h));
    }
    for (int i = tid; i < 64 * 128; i += 512) {
        int k = i >> 6, n = i & 63;
        float v = W2g[(size_t)k * Dd + n];
        __half h = __float2half_rn(v);
        uint32_t o = ioff<256>(n, k * 2);
        *(__half*)(smem + B2H + o) = h;
        *(__half*)(smem + B2L + o) = __float2half_rn(v - __half2float(h));
    }
    // hoisted biases
    float b1r[8];
    #pragma unroll
    for (int ni = 0; ni < 4; ni++) {
        b1r[2*ni]   = __ldg(b1g + nw2 * 32 + ni * 8 + lc);
        b1r[2*ni+1] = __ldg(b1g + nw2 * 32 + ni * 8 + lc + 1);
    }
    float b2r[4];
    #pragma unroll
    for (int ni = 0; ni < 2; ni++) {
        b2r[2*ni]   = __ldg(b2g + nw2 * 16 + ni * 8 + lc);
        b2r[2*ni+1] = __ldg(b2g + nw2 * 16 + ni * 8 + lc + 1);
    }
    __syncthreads();

    #define HBAR() asm volatile("bar.sync %0, 256;" :: "r"(half + 1) : "memory")

    // ---- cross-tile prefetch state (EDGE path) ----
    float4 pA[4];
    int iS = 0, iR = 0;
    const int tstep = gridDim.x * 2;
    if (EDGE) {
        int t0 = blockIdx.x * 2 + half;
        if (t0 < num_tiles) {
            int r0 = t0 * TM;
            #pragma unroll
            for (int it = 0; it < 4; it++) {
                int idx = it * 256 + ltid, r = idx >> 4, c4 = idx & 15;
                pA[it] = ldcs_v4(f0 + (size_t)(r0 + r) * Dd + c4 * 4);
            }
            if (ltid < TM) { iS = senders[r0 + ltid]; iR = receivers[r0 + ltid]; }
        }
    }

    for (int tile = blockIdx.x * 2 + half; tile < num_tiles; tile += tstep) {
        const int row0 = tile * TM;
        HBAR();
        // ---- stage indices + A image ----
        if (EDGE) {
            if (ltid < TM) { sSend[ltid] = iS; sRecv[ltid] = iR; }
            #pragma unroll
            for (int it = 0; it < 4; it++) {
                int idx = it * 256 + ltid, r = idx >> 4, c4 = idx & 15;
                uint2 hv;
                hv.x = pack_hi(pA[it].x, pA[it].y);
                hv.y = pack_hi(pA[it].z, pA[it].w);
                *(uint2*)(smem + AHo + ioff<ARB>(r, c4 * 8)) = hv;
            }
        } else {
            #pragma unroll
            for (int it = 0; it < 8; it++) {
                int idx = it * 256 + ltid, r = idx >> 5, c8 = idx & 31;
                int col = c8 * 4, grow = row0 + r;
                float4 v = make_float4(0.f, 0.f, 0.f, 0.f);
                if (grow < M)
                    v = (col < Dd) ? *(const float4*)(g_agg + (size_t)grow * Dd + col)
                                   : *(const float4*)(node_feats + (size_t)grow * Dd + col - Dd);
                uint2 hv, lv;
                split2(v.x, v.y, hv.x, lv.x);
                split2(v.z, v.w, hv.y, lv.y);
                uint32_t o = ioff<ARB>(r, c8 * 8);
                *(uint2*)(smem + AHo + o) = hv;
                *(uint2*)(smem + ALo + o) = lv;
            }
        }
        HBAR();

        // ---- P prefetch (hidden behind layer-1 MMA) ----
        uint32_t ps[2][2][4], pr[2][2][4];
        if (EDGE) {
            #pragma unroll
            for (int mi = 0; mi < 2; mi++)
                #pragma unroll
                for (int rr = 0; rr < 2; rr++) {
                    int row = mw2 * 32 + mi * 16 + lr + rr * 8;
                    const __half* Pbs = g_P + (size_t)sSend[row] * 256;
                    const __half* Pbr = g_P + (size_t)sRecv[row] * 256 + 128;
                    #pragma unroll
                    for (int ni = 0; ni < 4; ni++) {
                        int c0 = nw2 * 32 + ni * 8 + lc;
                        ps[mi][rr][ni] = *(const uint32_t*)(Pbs + c0);
                        pr[mi][rr][ni] = *(const uint32_t*)(Pbr + c0);
                    }
                }
        }

        // ---- layer 1: warp computes 32r x 32c (EDGE 2-term; NODE 3-term) ----
        float acc1[2][16];
        #pragma unroll
        for (int a = 0; a < 2; a++)
            #pragma unroll
            for (int b = 0; b < 16; b++) acc1[a][b] = 0.f;

        #pragma unroll
        for (int ks = 0; ks < AK; ks += 16) {
            uint32_t ah[2][4], al[2][4], bh[4][2], bl[4][2];
            #pragma unroll
            for (int mi = 0; mi < 2; mi++) {
                uint32_t ao = ioff<ARB>(mw2 * 32 + mi * 16 + (lane & 15), ks * 2 + (lane >> 4) * 16);
                ldsm4(ah[mi], sb + AHo + ao);
                if (!EDGE) ldsm4(al[mi], sb + ALo + ao);
            }
            #pragma unroll
            for (int p = 0; p < 2; p++) {
                uint32_t t[4], u[4];
                uint32_t bo = ioff<ARB>(nw2 * 32 + p * 16 + (lane & 15), ks * 2 + (lane >> 4) * 16);
                ldsm4(t, sb + B1H + bo);
                ldsm4(u, sb + B1L + bo);
                bh[2*p][0] = t[0]; bh[2*p+1][0] = t[1]; bh[2*p][1] = t[2]; bh[2*p+1][1] = t[3];
                bl[2*p][0] = u[0]; bl[2*p+1][0] = u[1]; bl[2*p][1] = u[2]; bl[2*p+1][1] = u[3];
            }
            #pragma unroll
            for (int mi = 0; mi < 2; mi++)
                #pragma unroll
                for (int ni = 0; ni < 4; ni++) {
                    mma16816(&acc1[mi][ni*4], ah[mi], bh[ni]);
                    mma16816(&acc1[mi][ni*4], ah[mi], bl[ni]);
                    if (!EDGE) mma16816(&acc1[mi][ni*4], al[mi], bh[ni]);
                }
        }

        // ---- epilogue 1: +P +bias1, relu, pack fp16-hi, write h ----
        #pragma unroll
        for (int mi = 0; mi < 2; mi++) {
            int r0 = mw2 * 32 + mi * 16 + lr;
            #pragma unroll
            for (int ni = 0; ni < 4; ni++) {
                int c0 = nw2 * 32 + ni * 8 + lc;
                float v0 = acc1[mi][ni*4+0] + b1r[2*ni],   v1 = acc1[mi][ni*4+1] + b1r[2*ni+1];
                float v2 = acc1[mi][ni*4+2] + b1r[2*ni],   v3 = acc1[mi][ni*4+3] + b1r[2*ni+1];
                if (EDGE) {
                    float2 fs = __half22float2(*(__half2*)&ps[mi][0][ni]);
                    float2 fr = __half22float2(*(__half2*)&pr[mi][0][ni]);
                    v0 += fs.x + fr.x; v1 += fs.y + fr.y;
                    float2 gs = __half22float2(*(__half2*)&ps[mi][1][ni]);
                    float2 gr = __half22float2(*(__half2*)&pr[mi][1][ni]);
                    v2 += gs.x + gr.x; v3 += gs.y + gr.y;
                }
                *(uint32_t*)(smem + HHo + ioff<256>(r0,     c0 * 2)) = pack_hi(fmaxf(v0,0.f), fmaxf(v1,0.f));
                *(uint32_t*)(smem + HHo + ioff<256>(r0 + 8, c0 * 2)) = pack_hi(fmaxf(v2,0.f), fmaxf(v3,0.f));
            }
        }
        HBAR();

        // ---- prefetch NEXT tile's A + indices (hidden behind layer-2 MMA) ----
        if (EDGE) {
            int tn = tile + tstep;
            if (tn < num_tiles) {
                int r0n = tn * TM;
                #pragma unroll
                for (int it = 0; it < 4; it++) {
                    int idx = it * 256 + ltid, r = idx >> 4, c4 = idx & 15;
                    pA[it] = ldcs_v4(f0 + (size_t)(r0n + r) * Dd + c4 * 4);
                }
                if (ltid < TM) { iS = senders[r0n + ltid]; iR = receivers[r0n + ltid]; }
            }
        }

        // ---- layer 2: warp computes 32r x 16c (2-term) ----
        float acc2[2][8];
        #pragma unroll
        for (int a = 0; a < 2; a++)
            #pragma unroll
            for (int b = 0; b < 8; b++) acc2[a][b] = 0.f;

        #pragma unroll
        for (int ks = 0; ks < 128; ks += 16) {
            uint32_t ah[2][4], bh[2][2], bl[2][2];
            #pragma unroll
            for (int mi = 0; mi < 2; mi++) {
                uint32_t ao = ioff<256>(mw2 * 32 + mi * 16 + (lane & 15), ks * 2 + (lane >> 4) * 16);
                ldsm4(ah[mi], sb + HHo + ao);
            }
            {
                uint32_t t[4], u[4];
                uint32_t bo = ioff<256>(nw2 * 16 + (lane & 15), ks * 2 + (lane >> 4) * 16);
                ldsm4(t, sb + B2H + bo);
                ldsm4(u, sb + B2L + bo);
                bh[0][0] = t[0]; bh[1][0] = t[1]; bh[0][1] = t[2]; bh[1][1] = t[3];
                bl[0][0] = u[0]; bl[1][0] = u[1]; bl[0][1] = u[2]; bl[1][1] = u[3];
            }
            #pragma unroll
            for (int mi = 0; mi < 2; mi++)
                #pragma unroll
                for (int ni = 0; ni < 2; ni++) {
                    mma16816(&acc2[mi][ni*4], ah[mi], bh[ni]);
                    mma16816(&acc2[mi][ni*4], ah[mi], bl[ni]);
                }
        }

        // ---- epilogue 2: bias2, streaming store out, vector scatter-add ----
        #pragma unroll
        for (int mi = 0; mi < 2; mi++) {
            int r0 = mw2 * 32 + mi * 16 + lr;
            int rv0 = 0, rv1 = 0;
            if (EDGE) { rv0 = sRecv[r0]; rv1 = sRecv[r0 + 8]; }
            #pragma unroll
            for (int ni = 0; ni < 2; ni++) {
                int c = nw2 * 16 + ni * 8 + lc;
                float v0 = acc2[mi][ni*4+0] + b2r[2*ni], v1 = acc2[mi][ni*4+1] + b2r[2*ni+1];
                float v2 = acc2[mi][ni*4+2] + b2r[2*ni], v3 = acc2[mi][ni*4+3] + b2r[2*ni+1];
                if (EDGE || row0 + r0 < M)
                    stcs_v2(out + (size_t)(row0 + r0) * Dd + c, v0, v1);
                if (EDGE || row0 + r0 + 8 < M)
                    stcs_v2(out + (size_t)(row0 + r0 + 8) * Dd + c, v2, v3);
                if (EDGE) {
                    red_add_v2(g_agg + (size_t)rv0 * Dd + c, v0, v1);
                    red_add_v2(g_agg + (size_t)rv1 * Dd + c, v2, v3);
                }
            }
        }
    }
    #undef HBAR
}

// ---------------- launch ----------------
constexpr int SMEM_PRE  = 98304;
constexpr int SMEM_EDGE = 1024 + 2 * 16384 + 2 * 16384 + 2 * (8192 + 16384);       // 115712
constexpr int SMEM_NODE = 1024 + 2 * 32768 + 2 * 16384 + 2 * (2 * 16384 + 16384);  // 197632

extern "C" void kernel_launch(void* const* d_in, const int* in_sizes, int n_in,
                              void* d_out, int out_size)
{
    const float* node_feats = (const float*)d_in[0];
    const float* edge_feats = (const float*)d_in[1];
    const float* We1 = (const float*)d_in[2];
    const float* be1 = (const float*)d_in[3];
    const float* We2 = (const float*)d_in[4];
    const float* be2 = (const float*)d_in[5];
    const float* Wn1 = (const float*)d_in[6];
    const float* bn1 = (const float*)d_in[7];
    const float* Wn2 = (const float*)d_in[8];
    const float* bn2 = (const float*)d_in[9];
    const int* senders   = (const int*)d_in[10];
    const int* receivers = (const int*)d_in[11];

    float* e_out = (float*)d_out;
    float* n_out = e_out + (size_t)N_EDGES * Dd;

    cudaFuncSetAttribute(pre_kernel, cudaFuncAttributeMaxDynamicSharedMemorySize, SMEM_PRE);
    cudaFuncSetAttribute(gnn_mlp<true>,  cudaFuncAttributeMaxDynamicSharedMemorySize, SMEM_EDGE);
    cudaFuncSetAttribute(gnn_mlp<false>, cudaFuncAttributeMaxDynamicSharedMemorySize, SMEM_NODE);

    pre_kernel<<<148, 512, SMEM_PRE>>>(node_feats, We1);

    gnn_mlp<true><<<148, 512, SMEM_EDGE>>>(
        edge_feats, node_feats, We1, be1, We2, be2,
        senders, receivers, e_out, N_EDGES, N_EDGES / TM);

    gnn_mlp<false><<<148, 512, SMEM_NODE>>>(
        nullptr, node_feats, Wn1, bn1, Wn2, bn2,
        nullptr, nullptr, n_out, N_NODES, (N_NODES + TM - 1) / TM);
}